// round 2
// baseline (speedup 1.0000x reference)
#include <cuda_runtime.h>
#include <math.h>

#define BB 8
#define CC 256
#define HH 128
#define WW 128
#define HWs (HH*WW)              // 16384
#define NBCHW (BB*CC*HWs)        // 33554432
#define PW 134
#define PHW (PW*PW)              // 17956

typedef unsigned long long ull;

// ---------------- static device scratch (allocation-free) ----------------
__device__ float g_buf0[NBCHW];
__device__ float g_buf1[NBCHW];
__device__ float g_buf2[NBCHW];
__device__ float g_buf3[NBCHW];
__device__ float g_buf4[NBCHW];
__device__ float g_buf5[NBCHW];
__device__ float g_M[(long)BB*HH*WW*WW];     // 16.7M attention probs (c_to_p)
__device__ float g_gate[BB*CC];
__device__ float g_amean[BB*CC];
__device__ float g_amax[BB*CC];
__device__ float g_b1g[BB*CC*CC];
__device__ float g_b2g[BB*CC*CC];
__device__ float g_mA[BB*HWs];
__device__ float g_mB[BB*HWs];
__device__ float g_pA[BB*PHW];
__device__ float g_pB[BB*PHW];
__device__ float g_vfinal[BB*HWs];

// ---------------- f32x2 helpers (full-rate fp32 FMA on sm_103a) ----------
__device__ __forceinline__ ull fma2(ull a, ull b, ull c){
    ull d; asm("fma.rn.f32x2 %0, %1, %2, %3;" : "=l"(d) : "l"(a), "l"(b), "l"(c)); return d;
}
__device__ __forceinline__ ull dup2(float a){
    ull d; asm("mov.b64 %0, {%1, %2};" : "=l"(d) : "f"(a), "f"(a)); return d;
}
__device__ __forceinline__ float2 unpk(ull v){
    float2 r; asm("mov.b64 {%0, %1}, %2;" : "=f"(r.x), "=f"(r.y) : "l"(v)); return r;
}
__device__ __forceinline__ float sigmoidf_(float x){ return 1.0f/(1.0f+expf(-x)); }

// ---------------- 3x3 avg + max pool (SAME; avg counts pad, max excludes) ----
__global__ void pool_k(const float* __restrict__ xp, float* __restrict__ y1, float* __restrict__ y2){
    long idx = (long)blockIdx.x*256 + threadIdx.x;
    if (idx >= (long)NBCHW) return;
    int w = (int)(idx & (WW-1));
    int h = (int)((idx >> 7) & (HH-1));
    long base = idx - (long)(h*WW + w);
    float s = 0.f, mx = -INFINITY;
    #pragma unroll
    for (int dy=-1; dy<=1; dy++){
        int hh = h+dy; if (hh<0||hh>=HH) continue;
        #pragma unroll
        for (int dx=-1; dx<=1; dx++){
            int ww = w+dx; if (ww<0||ww>=WW) continue;
            float v = xp[base + hh*WW + ww];
            s += v; mx = fmaxf(mx, v);
        }
    }
    y1[idx] = s * (1.f/9.f);
    y2[idx] = mx;
}

// ---------------- per-(b,c) mean & max over HW ----------------
__global__ void reduce_k(const float* __restrict__ x, float* __restrict__ mean, float* __restrict__ mxo){
    __shared__ float ss[256], sm[256];
    int bc = blockIdx.x, t = threadIdx.x;
    const float* p = x + (long)bc*HWs;
    float s = 0.f, m = -INFINITY;
    for (int i = t; i < HWs; i += 256){ float v = p[i]; s += v; m = fmaxf(m, v); }
    ss[t] = s; sm[t] = m; __syncthreads();
    for (int o = 128; o > 0; o >>= 1){
        if (t < o){ ss[t] += ss[t+o]; sm[t] = fmaxf(sm[t], sm[t+o]); }
        __syncthreads();
    }
    if (t == 0){ mean[bc] = ss[0]*(1.f/(float)HWs); mxo[bc] = sm[0]; }
}

// ---------------- CALayer gate (per batch) ----------------
__global__ void cagate_k(const float* __restrict__ amean, const float* __restrict__ amax,
                         const float* __restrict__ aw1, const float* __restrict__ ab1,
                         const float* __restrict__ aw2, const float* __restrict__ ab2,
                         const float* __restrict__ mw1, const float* __restrict__ mb1,
                         const float* __restrict__ mw2, const float* __restrict__ mb2,
                         float* __restrict__ gate){
    __shared__ float ha[16], hm[16];
    int b = blockIdx.x, t = threadIdx.x;
    if (t < 16){
        float s = ab1[t];
        for (int i = 0; i < CC; i++) s += aw1[t*CC+i]*amean[b*CC+i];
        ha[t] = fmaxf(s, 0.f);
    } else if (t < 32){
        int u = t-16; float s = mb1[u];
        for (int i = 0; i < CC; i++) s += mw1[u*CC+i]*amax[b*CC+i];
        hm[u] = fmaxf(s, 0.f);
    }
    __syncthreads();
    float g = ab2[t] + mb2[t];
    #pragma unroll
    for (int k = 0; k < 16; k++) g += aw2[t*16+k]*ha[k] + mw2[t*16+k]*hm[k];
    gate[b*CC + t] = sigmoidf_(g);
}

// ---------------- fold gate into per-batch weights (b1,b2 for buffer_c paths) ---
__global__ void scalew_k(const float* __restrict__ w1, const float* __restrict__ w2,
                         const float* __restrict__ gate, float* __restrict__ w1g, float* __restrict__ w2g){
    int idx = blockIdx.x*256 + threadIdx.x;      // 8*65536
    int b = idx >> 16, rem = idx & 65535, i = rem & 255;
    float g = gate[b*CC + i];
    w1g[idx] = w1[rem]*g;
    w2g[idx] = w2[rem]*g;
}

// ---------------- generic 1x1-conv GEMM: Y[b,m,n] = sum_k A[m,k] X[b,k,n] -----
#define EPI_NONE   0
#define EPI_RELU   1
#define EPI_ADDSRC 2
#define EPI_SIGMUL 3
#define EPI_FUSION 4

__global__ void gemm_k(const float* __restrict__ A, int aRS, long aBS,
                       const float* __restrict__ X0, const float* __restrict__ X1,
                       float* __restrict__ Y, const float* __restrict__ bias,
                       int K, int epi, const float* __restrict__ E0, const float* __restrict__ E1)
{
    __shared__ __align__(16) float As[8][128];
    __shared__ __align__(16) float Bs[8][128];
    int b  = blockIdx.z;
    int m0 = blockIdx.y*128, n0 = blockIdx.x*128;
    int tid = threadIdx.x;
    int ti4 = (tid>>4)*4, tj4 = (tid&15)*4;
    const float* Ab = A + (long)b*aBS;

    ull acc[8][4];
    #pragma unroll
    for (int i=0;i<8;i++){ acc[i][0]=0; acc[i][1]=0; acc[i][2]=0; acc[i][3]=0; }

    int la_m = tid>>1, la_k = (tid&1)*4;
    int lb_k = tid>>5, lb_n = (tid&31)*4;

    for (int k0 = 0; k0 < K; k0 += 8){
        const float* ar = Ab + (long)(m0+la_m)*aRS + k0 + la_k;
        float a0v = ar[0], a1v = ar[1], a2v = ar[2], a3v = ar[3];
        int kk = k0 + lb_k;
        const float* xr = (kk < CC) ? (X0 + ((long)b*CC + kk)*HWs)
                                    : (X1 + ((long)b*CC + (kk-CC))*HWs);
        float4 bv = *(const float4*)(xr + n0 + lb_n);
        __syncthreads();
        As[la_k+0][la_m]=a0v; As[la_k+1][la_m]=a1v; As[la_k+2][la_m]=a2v; As[la_k+3][la_m]=a3v;
        *(float4*)&Bs[lb_k][lb_n] = bv;
        __syncthreads();
        #pragma unroll
        for (int kq=0;kq<8;kq++){
            float4 av0 = *(const float4*)&As[kq][ti4];
            float4 av1 = *(const float4*)&As[kq][ti4+64];
            longlong2 q0 = *(const longlong2*)&Bs[kq][tj4];
            longlong2 q1 = *(const longlong2*)&Bs[kq][tj4+64];
            ull bp0=(ull)q0.x, bp1=(ull)q0.y, bp2=(ull)q1.x, bp3=(ull)q1.y;
            float am[8]={av0.x,av0.y,av0.z,av0.w,av1.x,av1.y,av1.z,av1.w};
            #pragma unroll
            for (int i=0;i<8;i++){
                ull ad = dup2(am[i]);
                acc[i][0]=fma2(ad,bp0,acc[i][0]);
                acc[i][1]=fma2(ad,bp1,acc[i][1]);
                acc[i][2]=fma2(ad,bp2,acc[i][2]);
                acc[i][3]=fma2(ad,bp3,acc[i][3]);
            }
        }
    }
    // epilogue
    #pragma unroll
    for (int ri=0;ri<8;ri++){
        int r = ti4 + ((ri<4) ? ri : 60+ri);
        int o = m0 + r;
        float bi = bias[o];
        long ybase = ((long)b*CC + o)*HWs + n0;
        float f[8];
        #pragma unroll
        for (int jp=0;jp<4;jp++){ float2 u = unpk(acc[ri][jp]); f[jp*2]=u.x; f[jp*2+1]=u.y; }
        #pragma unroll
        for (int cg=0; cg<2; cg++){
            int coff = tj4 + cg*64;
            float v[4];
            #pragma unroll
            for (int q=0;q<4;q++){
                float x = f[cg*4+q] + bi;
                if (epi == EPI_RELU)        x = fmaxf(x, 0.f);
                else if (epi == EPI_ADDSRC) x += E0[ybase + coff + q];
                else if (epi == EPI_SIGMUL) x = sigmoidf_(x) * E0[ybase + coff + q];
                else if (epi == EPI_FUSION) x += E1[(long)o*513 + 512] * E0[(long)b*HWs + n0 + coff + q];
                v[q] = x;
            }
            float4 st = {v[0],v[1],v[2],v[3]};
            *(float4*)(Y + ybase + coff) = st;
        }
    }
}

// ---------------- scores + softmax (+ optional colsum->mask) ----------------
// scores[i,j] = sum_c Q[b,c,h,i]*S[b,c,h,j]; softmax over j.
template<int WRITE_M>
__global__ void score_k(const float* __restrict__ Q, const float* __restrict__ S,
                        float* __restrict__ Mout, float* __restrict__ mOut)
{
    __shared__ __align__(16) float As[8][128];
    __shared__ __align__(16) float Ss[8][128];
    __shared__ float CS[16][128];
    int h = blockIdx.x, b = blockIdx.y;
    int tid = threadIdx.x;
    int ti4 = (tid>>4)*4, tj4 = (tid&15)*4;
    int lr = tid>>5, lc = (tid&31)*4;

    ull acc[8][4];
    #pragma unroll
    for (int i=0;i<8;i++){ acc[i][0]=0; acc[i][1]=0; acc[i][2]=0; acc[i][3]=0; }

    for (int k0=0;k0<CC;k0+=8){
        long qa = ((long)b*CC + k0 + lr)*HWs + h*WW + lc;
        float4 qv = *(const float4*)(Q + qa);
        float4 sv = *(const float4*)(S + qa);
        __syncthreads();
        *(float4*)&As[lr][lc] = qv;
        *(float4*)&Ss[lr][lc] = sv;
        __syncthreads();
        #pragma unroll
        for (int kq=0;kq<8;kq++){
            float4 av0 = *(const float4*)&As[kq][ti4];
            float4 av1 = *(const float4*)&As[kq][ti4+64];
            longlong2 q0 = *(const longlong2*)&Ss[kq][tj4];
            longlong2 q1 = *(const longlong2*)&Ss[kq][tj4+64];
            ull bp0=(ull)q0.x, bp1=(ull)q0.y, bp2=(ull)q1.x, bp3=(ull)q1.y;
            float am[8]={av0.x,av0.y,av0.z,av0.w,av1.x,av1.y,av1.z,av1.w};
            #pragma unroll
            for (int i=0;i<8;i++){
                ull ad = dup2(am[i]);
                acc[i][0]=fma2(ad,bp0,acc[i][0]);
                acc[i][1]=fma2(ad,bp1,acc[i][1]);
                acc[i][2]=fma2(ad,bp2,acc[i][2]);
                acc[i][3]=fma2(ad,bp3,acc[i][3]);
            }
        }
    }
    // unpack + row softmax (rows reduced across 16 lanes, width-16 shfl)
    float s[8][8];
    #pragma unroll
    for (int ri=0;ri<8;ri++){
        #pragma unroll
        for (int jp=0;jp<4;jp++){ float2 u = unpk(acc[ri][jp]); s[ri][jp*2]=u.x; s[ri][jp*2+1]=u.y; }
    }
    float csum[8];
    #pragma unroll
    for (int q=0;q<8;q++) csum[q]=0.f;

    #pragma unroll
    for (int ri=0;ri<8;ri++){
        float mx = s[ri][0];
        #pragma unroll
        for (int q=1;q<8;q++) mx = fmaxf(mx, s[ri][q]);
        #pragma unroll
        for (int msk=1; msk<16; msk<<=1) mx = fmaxf(mx, __shfl_xor_sync(0xffffffffu, mx, msk, 16));
        float sum = 0.f;
        #pragma unroll
        for (int q=0;q<8;q++){ s[ri][q] = expf(s[ri][q]-mx); sum += s[ri][q]; }
        #pragma unroll
        for (int msk=1; msk<16; msk<<=1) sum += __shfl_xor_sync(0xffffffffu, sum, msk, 16);
        float inv = 1.f/sum;
        #pragma unroll
        for (int q=0;q<8;q++){ s[ri][q] *= inv; if (!WRITE_M) csum[q] += s[ri][q]; }
        if (WRITE_M){
            int r = ti4 + ((ri<4) ? ri : 60+ri);
            long base = ((long)(b*HH + h)*128 + r)*128;
            float4 v0 = {s[ri][0],s[ri][1],s[ri][2],s[ri][3]};
            float4 v1 = {s[ri][4],s[ri][5],s[ri][6],s[ri][7]};
            *(float4*)(Mout + base + tj4)      = v0;
            *(float4*)(Mout + base + tj4 + 64) = v1;
        }
    }
    if (!WRITE_M){
        int ty = tid>>4;
        __syncthreads();
        *(float4*)&CS[ty][tj4]      = *(float4*)&csum[0];
        *(float4*)&CS[ty][tj4+64]   = *(float4*)&csum[4];
        __syncthreads();
        if (tid < 128){
            float t = 0.f;
            #pragma unroll
            for (int y=0;y<16;y++) t += CS[y][tid];
            // m = 1 - V, V = (colsum > 0.1)
            mOut[(long)b*HWs + h*WW + tid] = (t > 0.1f) ? 0.f : 1.f;
        }
    }
}

// ---------------- attend: out[b,c,h,i] = sum_j M[b,h,i,j] * v3[b,c,h,j] ------
__global__ void attend_k(const float* __restrict__ M, const float* __restrict__ V3,
                         float* __restrict__ out)
{
    __shared__ __align__(16) float As[8][128];
    __shared__ __align__(16) float Bs[8][128];
    int m0 = blockIdx.x*128;           // c half
    int bh = blockIdx.y; int b = bh>>7, h = bh&127;
    int tid = threadIdx.x;
    int ti4 = (tid>>4)*4, tj4 = (tid&15)*4;
    int la_m = tid>>1, la_k = (tid&1)*4;

    ull acc[8][4];
    #pragma unroll
    for (int i=0;i<8;i++){ acc[i][0]=0; acc[i][1]=0; acc[i][2]=0; acc[i][3]=0; }

    for (int k0=0;k0<128;k0+=8){
        float4 av = *(const float4*)(V3 + ((long)(b*CC + m0 + la_m))*HWs + h*WW + k0 + la_k);
        float4 mv = *(const float4*)(M + ((long)bh*128 + la_m)*128 + k0 + la_k);
        __syncthreads();
        As[la_k+0][la_m]=av.x; As[la_k+1][la_m]=av.y; As[la_k+2][la_m]=av.z; As[la_k+3][la_m]=av.w;
        Bs[la_k+0][la_m]=mv.x; Bs[la_k+1][la_m]=mv.y; Bs[la_k+2][la_m]=mv.z; Bs[la_k+3][la_m]=mv.w;
        __syncthreads();
        #pragma unroll
        for (int kq=0;kq<8;kq++){
            float4 av0 = *(const float4*)&As[kq][ti4];
            float4 av1 = *(const float4*)&As[kq][ti4+64];
            longlong2 q0 = *(const longlong2*)&Bs[kq][tj4];
            longlong2 q1 = *(const longlong2*)&Bs[kq][tj4+64];
            ull bp0=(ull)q0.x, bp1=(ull)q0.y, bp2=(ull)q1.x, bp3=(ull)q1.y;
            float am[8]={av0.x,av0.y,av0.z,av0.w,av1.x,av1.y,av1.z,av1.w};
            #pragma unroll
            for (int i=0;i<8;i++){
                ull ad = dup2(am[i]);
                acc[i][0]=fma2(ad,bp0,acc[i][0]);
                acc[i][1]=fma2(ad,bp1,acc[i][1]);
                acc[i][2]=fma2(ad,bp2,acc[i][2]);
                acc[i][3]=fma2(ad,bp3,acc[i][3]);
            }
        }
    }
    #pragma unroll
    for (int ri=0;ri<8;ri++){
        int r = ti4 + ((ri<4) ? ri : 60+ri);
        long ybase = ((long)(b*CC + m0 + r))*HWs + h*WW;
        float f[8];
        #pragma unroll
        for (int jp=0;jp<4;jp++){ float2 u = unpk(acc[ri][jp]); f[jp*2]=u.x; f[jp*2+1]=u.y; }
        float4 v0 = {f[0],f[1],f[2],f[3]};
        float4 v1 = {f[4],f[5],f[6],f[7]};
        *(float4*)(out + ybase + tj4)      = v0;
        *(float4*)(out + ybase + tj4 + 64) = v1;
    }
}

// ---------------- morphology ----------------
__global__ void morph_k(const float* __restrict__ src, float* __restrict__ dst,
                        int Wd, int Hd, int r, int erode, int total){
    int idx = blockIdx.x*256 + threadIdx.x;
    if (idx >= total) return;
    int plane = Wd*Hd;
    int b = idx / plane, rem = idx - b*plane;
    int h = rem / Wd, w = rem - h*Wd;
    const float* p = src + (long)b*plane;
    float res = erode ? 1.f : 0.f;
    int r2 = r*r;
    for (int dy=-r; dy<=r; dy++){
        for (int dx=-r; dx<=r; dx++){
            if (dy*dy + dx*dx > r2) continue;
            int hh = h+dy, ww = w+dx;
            float v = (hh>=0 && hh<Hd && ww>=0 && ww<Wd) ? p[hh*Wd+ww] : 0.f;
            if (erode){ if (v < 0.5f) res = 0.f; }
            else      { if (v > 0.5f) res = 1.f; }
        }
    }
    dst[(long)b*plane + rem] = res;
}

__global__ void pad_k(const float* __restrict__ src, float* __restrict__ dst, int total){
    int idx = blockIdx.x*256 + threadIdx.x;
    if (idx >= total) return;
    int b = idx / PHW, rem = idx - b*PHW;
    int h = rem / PW, w = rem - h*PW;
    float v = 0.f;
    if (h >= 3 && h < 3+HH && w >= 3 && w < 3+WW)
        v = src[(long)b*HWs + (h-3)*WW + (w-3)];
    dst[idx] = v;
}

__global__ void final_k(const float* __restrict__ src, float* __restrict__ dst){
    int idx = blockIdx.x*256 + threadIdx.x;   // B*HW
    int b = idx >> 14, rem = idx & (HWs-1);
    int h = rem >> 7, w = rem & 127;
    dst[idx] = 1.f - src[(long)b*PHW + (h+3)*PW + (w+3)];
}

// ---------------- launch ----------------
extern "C" void kernel_launch(void* const* d_in, const int* in_sizes, int n_in,
                              void* d_out, int out_size) {
    const float* x_p   = (const float*)d_in[0];
    const float* x_c   = (const float*)d_in[1];
    const float* pa_w1 = (const float*)d_in[2];
    const float* pa_b1 = (const float*)d_in[3];
    const float* pa_w2 = (const float*)d_in[4];
    const float* pa_b2 = (const float*)d_in[5];
    const float* pa_wc = (const float*)d_in[6];
    const float* pa_bc = (const float*)d_in[7];
    const float* ca_aw1= (const float*)d_in[8];
    const float* ca_ab1= (const float*)d_in[9];
    const float* ca_aw2= (const float*)d_in[10];
    const float* ca_ab2= (const float*)d_in[11];
    const float* ca_mw1= (const float*)d_in[12];
    const float* ca_mb1= (const float*)d_in[13];
    const float* ca_mw2= (const float*)d_in[14];
    const float* ca_mb2= (const float*)d_in[15];
    const float* b1_w  = (const float*)d_in[16];
    const float* b1_b  = (const float*)d_in[17];
    const float* b2_w  = (const float*)d_in[18];
    const float* b2_b  = (const float*)d_in[19];
    const float* b3_w  = (const float*)d_in[20];
    const float* b3_b  = (const float*)d_in[21];
    const float* fus_w = (const float*)d_in[22];
    const float* fus_b = (const float*)d_in[23];
    float* out = (float*)d_out;

    float *buf0,*buf1,*buf2,*buf3,*buf4,*buf5,*gM,*gate,*amean,*amax,*b1g,*b2g;
    float *mA,*mB,*pA,*pB,*vfin;
    cudaGetSymbolAddress((void**)&buf0, g_buf0);
    cudaGetSymbolAddress((void**)&buf1, g_buf1);
    cudaGetSymbolAddress((void**)&buf2, g_buf2);
    cudaGetSymbolAddress((void**)&buf3, g_buf3);
    cudaGetSymbolAddress((void**)&buf4, g_buf4);
    cudaGetSymbolAddress((void**)&buf5, g_buf5);
    cudaGetSymbolAddress((void**)&gM,   g_M);
    cudaGetSymbolAddress((void**)&gate, g_gate);
    cudaGetSymbolAddress((void**)&amean,g_amean);
    cudaGetSymbolAddress((void**)&amax, g_amax);
    cudaGetSymbolAddress((void**)&b1g,  g_b1g);
    cudaGetSymbolAddress((void**)&b2g,  g_b2g);
    cudaGetSymbolAddress((void**)&mA,   g_mA);
    cudaGetSymbolAddress((void**)&mB,   g_mB);
    cudaGetSymbolAddress((void**)&pA,   g_pA);
    cudaGetSymbolAddress((void**)&pB,   g_pB);
    cudaGetSymbolAddress((void**)&vfin, g_vfinal);

    // pooling + CA gate + folded weights
    pool_k<<<NBCHW/256, 256>>>(x_p, buf0, buf1);
    reduce_k<<<BB*CC, 256>>>(x_c, amean, amax);
    cagate_k<<<BB, 256>>>(amean, amax, ca_aw1, ca_ab1, ca_aw2, ca_ab2,
                          ca_mw1, ca_mb1, ca_mw2, ca_mb2, gate);
    scalew_k<<<(BB*CC*CC)/256, 256>>>(b1_w, b2_w, gate, b1g, b2g);

    dim3 gg(HWs/128, CC/128, BB);
    // PALayer MLPs
    gemm_k<<<gg,256>>>(pa_w1,256,0, buf0,0, buf2, pa_b1, 256, EPI_RELU,   0, 0);
    gemm_k<<<gg,256>>>(pa_w2,256,0, buf2,0, buf3, pa_b2, 256, EPI_ADDSRC, buf0, 0); // z1=y1+y3
    gemm_k<<<gg,256>>>(pa_w1,256,0, buf1,0, buf2, pa_b1, 256, EPI_RELU,   0, 0);
    gemm_k<<<gg,256>>>(pa_w2,256,0, buf2,0, buf4, pa_b2, 256, EPI_ADDSRC, buf1, 0); // z2=y2+y4
    gemm_k<<<gg,256>>>(pa_wc,512,0, buf3,buf4, buf5, pa_bc, 512, EPI_SIGMUL, x_p, 0); // buffer_p
    // Q/S/v3
    gemm_k<<<gg,256>>>(b1_w,256,0,     buf5,0, buf0, b1_b, 256, EPI_NONE, 0, 0); // Q1
    gemm_k<<<gg,256>>>(b2g,256,65536,  x_c, 0, buf1, b2_b, 256, EPI_NONE, 0, 0); // S1
    gemm_k<<<gg,256>>>(b1g,256,65536,  x_c, 0, buf2, b1_b, 256, EPI_NONE, 0, 0); // Q2
    gemm_k<<<gg,256>>>(b2_w,256,0,     buf5,0, buf3, b2_b, 256, EPI_NONE, 0, 0); // S2
    gemm_k<<<gg,256>>>(b3_w,256,0,     x_c, 0, buf4, b3_b, 256, EPI_NONE, 0, 0); // v3
    // attention
    dim3 gs(HH, BB);
    score_k<1><<<gs,256>>>(buf0, buf1, gM, 0);   // M_c_to_p
    score_k<0><<<gs,256>>>(buf2, buf3, 0, mA);   // mask m = 1 - V(p_to_c)
    // morphology
    int n128 = BB*HWs;
    morph_k<<<n128/256,256>>>(mA, mB, 128,128, 2, 1, n128);
    morph_k<<<n128/256,256>>>(mB, mA, 128,128, 2, 0, n128);
    morph_k<<<n128/256,256>>>(mA, mB, 128,128, 1, 0, n128);
    morph_k<<<n128/256,256>>>(mB, mA, 128,128, 1, 1, n128);
    int np = BB*PHW, gp = (np+255)/256;
    pad_k<<<gp,256>>>(mA, pA, np);
    morph_k<<<gp,256>>>(pA, pB, PW,PW, 3, 0, np);
    morph_k<<<gp,256>>>(pB, pA, PW,PW, 3, 1, np);
    final_k<<<n128/256,256>>>(pA, vfin);
    // attend + fusion
    dim3 ga(2, BB*HH);
    attend_k<<<ga,256>>>(gM, buf4, buf0);
    gemm_k<<<gg,256>>>(fus_w,513,0, buf0, x_p, out, fus_b, 512, EPI_FUSION, vfin, fus_w);
}

// round 3
// speedup vs baseline: 1.0046x; 1.0046x over previous
#include <cuda_runtime.h>
#include <math.h>

#define BB 8
#define CC 256
#define HH 128
#define WW 128
#define HWs (HH*WW)              // 16384
#define NBCHW (BB*CC*HWs)        // 33554432
#define PW 134
#define PHW (PW*PW)              // 17956

typedef unsigned long long ull;

// ---------------- static device scratch (allocation-free) ----------------
__device__ float g_buf0[NBCHW];
__device__ float g_buf1[NBCHW];
__device__ float g_buf2[NBCHW];
__device__ float g_buf3[NBCHW];
__device__ float g_buf4[NBCHW];
__device__ float g_buf5[NBCHW];
__device__ float g_M[(long)BB*HH*WW*WW];     // 16.7M attention probs (c_to_p)
__device__ float g_gate[BB*CC];
__device__ float g_amean[BB*CC];
__device__ float g_amax[BB*CC];
__device__ float g_b1g[BB*CC*CC];
__device__ float g_b2g[BB*CC*CC];
__device__ float g_mA[BB*HWs];
__device__ float g_mB[BB*HWs];
__device__ float g_pA[BB*PHW];
__device__ float g_pB[BB*PHW];
__device__ float g_vfinal[BB*HWs];

// ---------------- f32x2 helpers (full-rate fp32 FMA on sm_103a) ----------
__device__ __forceinline__ ull fma2(ull a, ull b, ull c){
    ull d; asm("fma.rn.f32x2 %0, %1, %2, %3;" : "=l"(d) : "l"(a), "l"(b), "l"(c)); return d;
}
__device__ __forceinline__ ull dup2(float a){
    ull d; asm("mov.b64 %0, {%1, %2};" : "=l"(d) : "f"(a), "f"(a)); return d;
}
__device__ __forceinline__ float2 unpk(ull v){
    float2 r; asm("mov.b64 {%0, %1}, %2;" : "=f"(r.x), "=f"(r.y) : "l"(v)); return r;
}
__device__ __forceinline__ float sigmoidf_(float x){ return 1.0f/(1.0f+expf(-x)); }

// ---------------- 3x3 avg + max pool (SAME; avg counts pad, max excludes) ----
__global__ void pool_k(const float* __restrict__ xp, float* __restrict__ y1, float* __restrict__ y2){
    long idx = (long)blockIdx.x*256 + threadIdx.x;
    if (idx >= (long)NBCHW) return;
    int w = (int)(idx & (WW-1));
    int h = (int)((idx >> 7) & (HH-1));
    long base = idx - (long)(h*WW + w);
    float s = 0.f, mx = -INFINITY;
    #pragma unroll
    for (int dy=-1; dy<=1; dy++){
        int hh = h+dy; if (hh<0||hh>=HH) continue;
        #pragma unroll
        for (int dx=-1; dx<=1; dx++){
            int ww = w+dx; if (ww<0||ww>=WW) continue;
            float v = xp[base + hh*WW + ww];
            s += v; mx = fmaxf(mx, v);
        }
    }
    y1[idx] = s * (1.f/9.f);
    y2[idx] = mx;
}

// ---------------- per-(b,c) mean & max over HW ----------------
__global__ void reduce_k(const float* __restrict__ x, float* __restrict__ mean, float* __restrict__ mxo){
    __shared__ float ss[256], sm[256];
    int bc = blockIdx.x, t = threadIdx.x;
    const float* p = x + (long)bc*HWs;
    float s = 0.f, m = -INFINITY;
    for (int i = t; i < HWs; i += 256){ float v = p[i]; s += v; m = fmaxf(m, v); }
    ss[t] = s; sm[t] = m; __syncthreads();
    for (int o = 128; o > 0; o >>= 1){
        if (t < o){ ss[t] += ss[t+o]; sm[t] = fmaxf(sm[t], sm[t+o]); }
        __syncthreads();
    }
    if (t == 0){ mean[bc] = ss[0]*(1.f/(float)HWs); mxo[bc] = sm[0]; }
}

// ---------------- CALayer gate (per batch) ----------------
__global__ void cagate_k(const float* __restrict__ amean, const float* __restrict__ amax,
                         const float* __restrict__ aw1, const float* __restrict__ ab1,
                         const float* __restrict__ aw2, const float* __restrict__ ab2,
                         const float* __restrict__ mw1, const float* __restrict__ mb1,
                         const float* __restrict__ mw2, const float* __restrict__ mb2,
                         float* __restrict__ gate){
    __shared__ float ha[16], hm[16];
    int b = blockIdx.x, t = threadIdx.x;
    if (t < 16){
        float s = ab1[t];
        for (int i = 0; i < CC; i++) s += aw1[t*CC+i]*amean[b*CC+i];
        ha[t] = fmaxf(s, 0.f);
    } else if (t < 32){
        int u = t-16; float s = mb1[u];
        for (int i = 0; i < CC; i++) s += mw1[u*CC+i]*amax[b*CC+i];
        hm[u] = fmaxf(s, 0.f);
    }
    __syncthreads();
    float g = ab2[t] + mb2[t];
    #pragma unroll
    for (int k = 0; k < 16; k++) g += aw2[t*16+k]*ha[k] + mw2[t*16+k]*hm[k];
    gate[b*CC + t] = sigmoidf_(g);
}

// ---------------- fold gate into per-batch weights (b1,b2 for buffer_c paths) ---
__global__ void scalew_k(const float* __restrict__ w1, const float* __restrict__ w2,
                         const float* __restrict__ gate, float* __restrict__ w1g, float* __restrict__ w2g){
    int idx = blockIdx.x*256 + threadIdx.x;      // 8*65536
    int b = idx >> 16, rem = idx & 65535, i = rem & 255;
    float g = gate[b*CC + i];
    w1g[idx] = w1[rem]*g;
    w2g[idx] = w2[rem]*g;
}

// ---------------- generic 1x1-conv GEMM: Y[b,m,n] = sum_k A[m,k] X[b,k,n] -----
#define EPI_NONE   0
#define EPI_RELU   1
#define EPI_ADDSRC 2
#define EPI_SIGMUL 3
#define EPI_FUSION 4

__global__ void gemm_k(const float* __restrict__ A, int aRS, long aBS,
                       const float* __restrict__ X0, const float* __restrict__ X1,
                       float* __restrict__ Y, const float* __restrict__ bias,
                       int K, int epi, const float* __restrict__ E0, const float* __restrict__ E1)
{
    __shared__ __align__(16) float As[8][128];
    __shared__ __align__(16) float Bs[8][128];
    int b  = blockIdx.z;
    int m0 = blockIdx.y*128, n0 = blockIdx.x*128;
    int tid = threadIdx.x;
    int ti4 = (tid>>4)*4, tj4 = (tid&15)*4;
    const float* Ab = A + (long)b*aBS;

    ull acc[8][4];
    #pragma unroll
    for (int i=0;i<8;i++){ acc[i][0]=0; acc[i][1]=0; acc[i][2]=0; acc[i][3]=0; }

    int la_m = tid>>1, la_k = (tid&1)*4;
    int lb_k = tid>>5, lb_n = (tid&31)*4;

    for (int k0 = 0; k0 < K; k0 += 8){
        const float* ar = Ab + (long)(m0+la_m)*aRS + k0 + la_k;
        float a0v = ar[0], a1v = ar[1], a2v = ar[2], a3v = ar[3];
        int kk = k0 + lb_k;
        const float* xr = (kk < CC) ? (X0 + ((long)b*CC + kk)*HWs)
                                    : (X1 + ((long)b*CC + (kk-CC))*HWs);
        float4 bv = *(const float4*)(xr + n0 + lb_n);
        __syncthreads();
        As[la_k+0][la_m]=a0v; As[la_k+1][la_m]=a1v; As[la_k+2][la_m]=a2v; As[la_k+3][la_m]=a3v;
        *(float4*)&Bs[lb_k][lb_n] = bv;
        __syncthreads();
        #pragma unroll
        for (int kq=0;kq<8;kq++){
            float4 av0 = *(const float4*)&As[kq][ti4];
            float4 av1 = *(const float4*)&As[kq][ti4+64];
            longlong2 q0 = *(const longlong2*)&Bs[kq][tj4];
            longlong2 q1 = *(const longlong2*)&Bs[kq][tj4+64];
            ull bp0=(ull)q0.x, bp1=(ull)q0.y, bp2=(ull)q1.x, bp3=(ull)q1.y;
            float am[8]={av0.x,av0.y,av0.z,av0.w,av1.x,av1.y,av1.z,av1.w};
            #pragma unroll
            for (int i=0;i<8;i++){
                ull ad = dup2(am[i]);
                acc[i][0]=fma2(ad,bp0,acc[i][0]);
                acc[i][1]=fma2(ad,bp1,acc[i][1]);
                acc[i][2]=fma2(ad,bp2,acc[i][2]);
                acc[i][3]=fma2(ad,bp3,acc[i][3]);
            }
        }
    }
    // epilogue
    #pragma unroll
    for (int ri=0;ri<8;ri++){
        int r = ti4 + ((ri<4) ? ri : 60+ri);
        int o = m0 + r;
        float bi = bias[o];
        long ybase = ((long)b*CC + o)*HWs + n0;
        float f[8];
        #pragma unroll
        for (int jp=0;jp<4;jp++){ float2 u = unpk(acc[ri][jp]); f[jp*2]=u.x; f[jp*2+1]=u.y; }
        #pragma unroll
        for (int cg=0; cg<2; cg++){
            int coff = tj4 + cg*64;
            float v[4];
            #pragma unroll
            for (int q=0;q<4;q++){
                float x = f[cg*4+q] + bi;
                if (epi == EPI_RELU)        x = fmaxf(x, 0.f);
                else if (epi == EPI_ADDSRC) x += E0[ybase + coff + q];
                else if (epi == EPI_SIGMUL) x = sigmoidf_(x) * E0[ybase + coff + q];
                else if (epi == EPI_FUSION) x += E1[(long)o*513 + 512] * E0[(long)b*HWs + n0 + coff + q];
                v[q] = x;
            }
            float4 st = {v[0],v[1],v[2],v[3]};
            *(float4*)(Y + ybase + coff) = st;
        }
    }
}

// ---------------- scores + softmax (+ optional colsum->mask) ----------------
// scores[i,j] = sum_c Q[b,c,h,i]*S[b,c,h,j]; softmax over j.
template<int WRITE_M>
__global__ void score_k(const float* __restrict__ Q, const float* __restrict__ S,
                        float* __restrict__ Mout, float* __restrict__ mOut)
{
    __shared__ __align__(16) float As[8][128];
    __shared__ __align__(16) float Ss[8][128];
    __shared__ float CS[16][128];
    int h = blockIdx.x, b = blockIdx.y;
    int tid = threadIdx.x;
    int ti4 = (tid>>4)*4, tj4 = (tid&15)*4;
    int lr = tid>>5, lc = (tid&31)*4;

    ull acc[8][4];
    #pragma unroll
    for (int i=0;i<8;i++){ acc[i][0]=0; acc[i][1]=0; acc[i][2]=0; acc[i][3]=0; }

    for (int k0=0;k0<CC;k0+=8){
        long qa = ((long)b*CC + k0 + lr)*HWs + h*WW + lc;
        float4 qv = *(const float4*)(Q + qa);
        float4 sv = *(const float4*)(S + qa);
        __syncthreads();
        *(float4*)&As[lr][lc] = qv;
        *(float4*)&Ss[lr][lc] = sv;
        __syncthreads();
        #pragma unroll
        for (int kq=0;kq<8;kq++){
            float4 av0 = *(const float4*)&As[kq][ti4];
            float4 av1 = *(const float4*)&As[kq][ti4+64];
            longlong2 q0 = *(const longlong2*)&Ss[kq][tj4];
            longlong2 q1 = *(const longlong2*)&Ss[kq][tj4+64];
            ull bp0=(ull)q0.x, bp1=(ull)q0.y, bp2=(ull)q1.x, bp3=(ull)q1.y;
            float am[8]={av0.x,av0.y,av0.z,av0.w,av1.x,av1.y,av1.z,av1.w};
            #pragma unroll
            for (int i=0;i<8;i++){
                ull ad = dup2(am[i]);
                acc[i][0]=fma2(ad,bp0,acc[i][0]);
                acc[i][1]=fma2(ad,bp1,acc[i][1]);
                acc[i][2]=fma2(ad,bp2,acc[i][2]);
                acc[i][3]=fma2(ad,bp3,acc[i][3]);
            }
        }
    }
    // unpack + row softmax (rows reduced across 16 lanes, width-16 shfl)
    float s[8][8];
    #pragma unroll
    for (int ri=0;ri<8;ri++){
        #pragma unroll
        for (int jp=0;jp<4;jp++){ float2 u = unpk(acc[ri][jp]); s[ri][jp*2]=u.x; s[ri][jp*2+1]=u.y; }
    }
    float csum[8];
    #pragma unroll
    for (int q=0;q<8;q++) csum[q]=0.f;

    #pragma unroll
    for (int ri=0;ri<8;ri++){
        float mx = s[ri][0];
        #pragma unroll
        for (int q=1;q<8;q++) mx = fmaxf(mx, s[ri][q]);
        #pragma unroll
        for (int msk=1; msk<16; msk<<=1) mx = fmaxf(mx, __shfl_xor_sync(0xffffffffu, mx, msk, 16));
        float sum = 0.f;
        #pragma unroll
        for (int q=0;q<8;q++){ s[ri][q] = expf(s[ri][q]-mx); sum += s[ri][q]; }
        #pragma unroll
        for (int msk=1; msk<16; msk<<=1) sum += __shfl_xor_sync(0xffffffffu, sum, msk, 16);
        float inv = 1.f/sum;
        #pragma unroll
        for (int q=0;q<8;q++){ s[ri][q] *= inv; if (!WRITE_M) csum[q] += s[ri][q]; }
        if (WRITE_M){
            int r = ti4 + ((ri<4) ? ri : 60+ri);
            long base = ((long)(b*HH + h)*128 + r)*128;
            float4 v0 = {s[ri][0],s[ri][1],s[ri][2],s[ri][3]};
            float4 v1 = {s[ri][4],s[ri][5],s[ri][6],s[ri][7]};
            *(float4*)(Mout + base + tj4)      = v0;
            *(float4*)(Mout + base + tj4 + 64) = v1;
        }
    }
    if (!WRITE_M){
        int ty = tid>>4;
        __syncthreads();
        *(float4*)&CS[ty][tj4]      = *(float4*)&csum[0];
        *(float4*)&CS[ty][tj4+64]   = *(float4*)&csum[4];
        __syncthreads();
        if (tid < 128){
            float t = 0.f;
            #pragma unroll
            for (int y=0;y<16;y++) t += CS[y][tid];
            // m = 1 - V, V = (colsum > 0.1)
            mOut[(long)b*HWs + h*WW + tid] = (t > 0.1f) ? 0.f : 1.f;
        }
    }
}

// ---------------- attend: out[b,c,h,i] = sum_j M[b,h,i,j] * v3[b,c,h,j] ------
__global__ void attend_k(const float* __restrict__ M, const float* __restrict__ V3,
                         float* __restrict__ out)
{
    __shared__ __align__(16) float As[8][128];
    __shared__ __align__(16) float Bs[8][128];
    int m0 = blockIdx.x*128;           // c half
    int bh = blockIdx.y; int b = bh>>7, h = bh&127;
    int tid = threadIdx.x;
    int ti4 = (tid>>4)*4, tj4 = (tid&15)*4;
    int la_m = tid>>1, la_k = (tid&1)*4;

    ull acc[8][4];
    #pragma unroll
    for (int i=0;i<8;i++){ acc[i][0]=0; acc[i][1]=0; acc[i][2]=0; acc[i][3]=0; }

    for (int k0=0;k0<128;k0+=8){
        float4 av = *(const float4*)(V3 + ((long)(b*CC + m0 + la_m))*HWs + h*WW + k0 + la_k);
        float4 mv = *(const float4*)(M + ((long)bh*128 + la_m)*128 + k0 + la_k);
        __syncthreads();
        As[la_k+0][la_m]=av.x; As[la_k+1][la_m]=av.y; As[la_k+2][la_m]=av.z; As[la_k+3][la_m]=av.w;
        Bs[la_k+0][la_m]=mv.x; Bs[la_k+1][la_m]=mv.y; Bs[la_k+2][la_m]=mv.z; Bs[la_k+3][la_m]=mv.w;
        __syncthreads();
        #pragma unroll
        for (int kq=0;kq<8;kq++){
            float4 av0 = *(const float4*)&As[kq][ti4];
            float4 av1 = *(const float4*)&As[kq][ti4+64];
            longlong2 q0 = *(const longlong2*)&Bs[kq][tj4];
            longlong2 q1 = *(const longlong2*)&Bs[kq][tj4+64];
            ull bp0=(ull)q0.x, bp1=(ull)q0.y, bp2=(ull)q1.x, bp3=(ull)q1.y;
            float am[8]={av0.x,av0.y,av0.z,av0.w,av1.x,av1.y,av1.z,av1.w};
            #pragma unroll
            for (int i=0;i<8;i++){
                ull ad = dup2(am[i]);
                acc[i][0]=fma2(ad,bp0,acc[i][0]);
                acc[i][1]=fma2(ad,bp1,acc[i][1]);
                acc[i][2]=fma2(ad,bp2,acc[i][2]);
                acc[i][3]=fma2(ad,bp3,acc[i][3]);
            }
        }
    }
    #pragma unroll
    for (int ri=0;ri<8;ri++){
        int r = ti4 + ((ri<4) ? ri : 60+ri);
        long ybase = ((long)(b*CC + m0 + r))*HWs + h*WW;
        float f[8];
        #pragma unroll
        for (int jp=0;jp<4;jp++){ float2 u = unpk(acc[ri][jp]); f[jp*2]=u.x; f[jp*2+1]=u.y; }
        float4 v0 = {f[0],f[1],f[2],f[3]};
        float4 v1 = {f[4],f[5],f[6],f[7]};
        *(float4*)(out + ybase + tj4)      = v0;
        *(float4*)(out + ybase + tj4 + 64) = v1;
    }
}

// ---------------- morphology ----------------
__global__ void morph_k(const float* __restrict__ src, float* __restrict__ dst,
                        int Wd, int Hd, int r, int erode, int total){
    int idx = blockIdx.x*256 + threadIdx.x;
    if (idx >= total) return;
    int plane = Wd*Hd;
    int b = idx / plane, rem = idx - b*plane;
    int h = rem / Wd, w = rem - h*Wd;
    const float* p = src + (long)b*plane;
    float res = erode ? 1.f : 0.f;
    int r2 = r*r;
    for (int dy=-r; dy<=r; dy++){
        for (int dx=-r; dx<=r; dx++){
            if (dy*dy + dx*dx > r2) continue;
            int hh = h+dy, ww = w+dx;
            float v = (hh>=0 && hh<Hd && ww>=0 && ww<Wd) ? p[hh*Wd+ww] : 0.f;
            if (erode){ if (v < 0.5f) res = 0.f; }
            else      { if (v > 0.5f) res = 1.f; }
        }
    }
    dst[(long)b*plane + rem] = res;
}

__global__ void pad_k(const float* __restrict__ src, float* __restrict__ dst, int total){
    int idx = blockIdx.x*256 + threadIdx.x;
    if (idx >= total) return;
    int b = idx / PHW, rem = idx - b*PHW;
    int h = rem / PW, w = rem - h*PW;
    float v = 0.f;
    if (h >= 3 && h < 3+HH && w >= 3 && w < 3+WW)
        v = src[(long)b*HWs + (h-3)*WW + (w-3)];
    dst[idx] = v;
}

__global__ void final_k(const float* __restrict__ src, float* __restrict__ dst){
    int idx = blockIdx.x*256 + threadIdx.x;   // B*HW
    int b = idx >> 14, rem = idx & (HWs-1);
    int h = rem >> 7, w = rem & 127;
    dst[idx] = 1.f - src[(long)b*PHW + (h+3)*PW + (w+3)];
}

// ---------------- launch ----------------
extern "C" void kernel_launch(void* const* d_in, const int* in_sizes, int n_in,
                              void* d_out, int out_size) {
    const float* x_p   = (const float*)d_in[0];
    const float* x_c   = (const float*)d_in[1];
    const float* pa_w1 = (const float*)d_in[2];
    const float* pa_b1 = (const float*)d_in[3];
    const float* pa_w2 = (const float*)d_in[4];
    const float* pa_b2 = (const float*)d_in[5];
    const float* pa_wc = (const float*)d_in[6];
    const float* pa_bc = (const float*)d_in[7];
    const float* ca_aw1= (const float*)d_in[8];
    const float* ca_ab1= (const float*)d_in[9];
    const float* ca_aw2= (const float*)d_in[10];
    const float* ca_ab2= (const float*)d_in[11];
    const float* ca_mw1= (const float*)d_in[12];
    const float* ca_mb1= (const float*)d_in[13];
    const float* ca_mw2= (const float*)d_in[14];
    const float* ca_mb2= (const float*)d_in[15];
    const float* b1_w  = (const float*)d_in[16];
    const float* b1_b  = (const float*)d_in[17];
    const float* b2_w  = (const float*)d_in[18];
    const float* b2_b  = (const float*)d_in[19];
    const float* b3_w  = (const float*)d_in[20];
    const float* b3_b  = (const float*)d_in[21];
    const float* fus_w = (const float*)d_in[22];
    const float* fus_b = (const float*)d_in[23];
    float* out = (float*)d_out;

    float *buf0,*buf1,*buf2,*buf3,*buf4,*buf5,*gM,*gate,*amean,*amax,*b1g,*b2g;
    float *mA,*mB,*pA,*pB,*vfin;
    cudaGetSymbolAddress((void**)&buf0, g_buf0);
    cudaGetSymbolAddress((void**)&buf1, g_buf1);
    cudaGetSymbolAddress((void**)&buf2, g_buf2);
    cudaGetSymbolAddress((void**)&buf3, g_buf3);
    cudaGetSymbolAddress((void**)&buf4, g_buf4);
    cudaGetSymbolAddress((void**)&buf5, g_buf5);
    cudaGetSymbolAddress((void**)&gM,   g_M);
    cudaGetSymbolAddress((void**)&gate, g_gate);
    cudaGetSymbolAddress((void**)&amean,g_amean);
    cudaGetSymbolAddress((void**)&amax, g_amax);
    cudaGetSymbolAddress((void**)&b1g,  g_b1g);
    cudaGetSymbolAddress((void**)&b2g,  g_b2g);
    cudaGetSymbolAddress((void**)&mA,   g_mA);
    cudaGetSymbolAddress((void**)&mB,   g_mB);
    cudaGetSymbolAddress((void**)&pA,   g_pA);
    cudaGetSymbolAddress((void**)&pB,   g_pB);
    cudaGetSymbolAddress((void**)&vfin, g_vfinal);

    // pooling + CA gate + folded weights
    pool_k<<<NBCHW/256, 256>>>(x_p, buf0, buf1);
    reduce_k<<<BB*CC, 256>>>(x_c, amean, amax);
    cagate_k<<<BB, 256>>>(amean, amax, ca_aw1, ca_ab1, ca_aw2, ca_ab2,
                          ca_mw1, ca_mb1, ca_mw2, ca_mb2, gate);
    scalew_k<<<(BB*CC*CC)/256, 256>>>(b1_w, b2_w, gate, b1g, b2g);

    dim3 gg(HWs/128, CC/128, BB);
    // PALayer MLPs
    gemm_k<<<gg,256>>>(pa_w1,256,0, buf0,0, buf2, pa_b1, 256, EPI_RELU,   0, 0);
    gemm_k<<<gg,256>>>(pa_w2,256,0, buf2,0, buf3, pa_b2, 256, EPI_ADDSRC, buf0, 0); // z1=y1+y3
    gemm_k<<<gg,256>>>(pa_w1,256,0, buf1,0, buf2, pa_b1, 256, EPI_RELU,   0, 0);
    gemm_k<<<gg,256>>>(pa_w2,256,0, buf2,0, buf4, pa_b2, 256, EPI_ADDSRC, buf1, 0); // z2=y2+y4
    gemm_k<<<gg,256>>>(pa_wc,512,0, buf3,buf4, buf5, pa_bc, 512, EPI_SIGMUL, x_p, 0); // buffer_p
    // Q/S/v3
    gemm_k<<<gg,256>>>(b1_w,256,0,     buf5,0, buf0, b1_b, 256, EPI_NONE, 0, 0); // Q1
    gemm_k<<<gg,256>>>(b2g,256,65536,  x_c, 0, buf1, b2_b, 256, EPI_NONE, 0, 0); // S1
    gemm_k<<<gg,256>>>(b1g,256,65536,  x_c, 0, buf2, b1_b, 256, EPI_NONE, 0, 0); // Q2
    gemm_k<<<gg,256>>>(b2_w,256,0,     buf5,0, buf3, b2_b, 256, EPI_NONE, 0, 0); // S2
    gemm_k<<<gg,256>>>(b3_w,256,0,     x_c, 0, buf4, b3_b, 256, EPI_NONE, 0, 0); // v3
    // attention
    dim3 gs(HH, BB);
    score_k<1><<<gs,256>>>(buf0, buf1, gM, 0);   // M_c_to_p
    score_k<0><<<gs,256>>>(buf2, buf3, 0, mA);   // mask m = 1 - V(p_to_c)
    // morphology
    int n128 = BB*HWs;
    morph_k<<<n128/256,256>>>(mA, mB, 128,128, 2, 1, n128);
    morph_k<<<n128/256,256>>>(mB, mA, 128,128, 2, 0, n128);
    morph_k<<<n128/256,256>>>(mA, mB, 128,128, 1, 0, n128);
    morph_k<<<n128/256,256>>>(mB, mA, 128,128, 1, 1, n128);
    int np = BB*PHW, gp = (np+255)/256;
    pad_k<<<gp,256>>>(mA, pA, np);
    morph_k<<<gp,256>>>(pA, pB, PW,PW, 3, 0, np);
    morph_k<<<gp,256>>>(pB, pA, PW,PW, 3, 1, np);
    final_k<<<n128/256,256>>>(pA, vfin);
    // attend + fusion
    dim3 ga(2, BB*HH);
    attend_k<<<ga,256>>>(gM, buf4, buf0);
    gemm_k<<<gg,256>>>(fus_w,513,0, buf0, x_p, out, fus_b, 512, EPI_FUSION, vfin, fus_w);
}

// round 5
// speedup vs baseline: 1.3860x; 1.3796x over previous
#include <cuda_runtime.h>
#include <cuda_bf16.h>
#include <math.h>

#define BB 8
#define CC 256
#define HH 128
#define WW 128
#define HWs 16384
#define NBCHW (BB*CC*HWs)
#define PW 134
#define PHW (PW*PW)
typedef unsigned long long ull;
typedef unsigned int u32;

__device__ float g_buf0[NBCHW];
__device__ float g_buf1[NBCHW];
__device__ float g_buf2[NBCHW];
__device__ float g_buf3[NBCHW];
__device__ float g_buf4[NBCHW];
__device__ float g_buf5[NBCHW];
__device__ float g_M[(long)BB*HH*WW*WW];
__device__ float g_gate[BB*CC];
__device__ float g_amean[BB*CC];
__device__ float g_amax[BB*CC];
__device__ float g_b1g[BB*CC*CC];
__device__ float g_b2g[BB*CC*CC];
__device__ float g_mA[BB*HWs];
__device__ float g_mB[BB*HWs];
__device__ float g_pA[BB*PHW];
__device__ float g_pB[BB*PHW];
__device__ float g_vfinal[BB*HWs];

__device__ __forceinline__ ull fma2(ull a, ull b, ull c){
    ull d; asm("fma.rn.f32x2 %0, %1, %2, %3;" : "=l"(d) : "l"(a), "l"(b), "l"(c)); return d; }
__device__ __forceinline__ ull dup2(float a){
    ull d; asm("mov.b64 %0, {%1, %2};" : "=l"(d) : "f"(a), "f"(a)); return d; }
__device__ __forceinline__ float2 unpk(ull v){
    float2 r; asm("mov.b64 {%0, %1}, %2;" : "=f"(r.x), "=f"(r.y) : "l"(v)); return r; }
__device__ __forceinline__ float sigmoidf_(float x){ return 1.0f/(1.0f+expf(-x)); }
__device__ __forceinline__ u32 smem_u32(const void* p){
    u32 a; asm("{ .reg .u64 t; cvta.to.shared.u64 t, %1; cvt.u32.u64 %0, t; }" : "=r"(a) : "l"(p)); return a; }
__device__ __forceinline__ u32 pack2(float a, float b){
    __nv_bfloat162 t = __floats2bfloat162_rn(a, b); return *(u32*)&t; }
__device__ __forceinline__ void ldsm4(u32& r0,u32& r1,u32& r2,u32& r3,u32 a){
    asm volatile("ldmatrix.sync.aligned.m8n8.x4.shared.b16 {%0,%1,%2,%3}, [%4];"
        :"=r"(r0),"=r"(r1),"=r"(r2),"=r"(r3):"r"(a)); }
__device__ __forceinline__ void ldsm4t(u32& r0,u32& r1,u32& r2,u32& r3,u32 a){
    asm volatile("ldmatrix.sync.aligned.m8n8.x4.trans.shared.b16 {%0,%1,%2,%3}, [%4];"
        :"=r"(r0),"=r"(r1),"=r"(r2),"=r"(r3):"r"(a)); }
__device__ __forceinline__ void mmabf(float* c, const u32* a, const u32* b){
    asm volatile("mma.sync.aligned.m16n8k16.row.col.f32.bf16.bf16.f32 "
        "{%0,%1,%2,%3},{%4,%5,%6,%7},{%8,%9},{%0,%1,%2,%3};"
        :"+f"(c[0]),"+f"(c[1]),"+f"(c[2]),"+f"(c[3])
        :"r"(a[0]),"r"(a[1]),"r"(a[2]),"r"(a[3]),"r"(b[0]),"r"(b[1])); }

// ---- pool / reduce / gate / scaled weights (same as proven R2) ----
__global__ void pool_k(const float* __restrict__ xp, float* __restrict__ y1, float* __restrict__ y2){
    long idx = (long)blockIdx.x*256 + threadIdx.x;
    if (idx >= (long)NBCHW) return;
    int w = (int)(idx & 127), h = (int)((idx>>7)&127);
    long base = idx - (long)(h*WW+w);
    float s=0.f, mx=-INFINITY;
    #pragma unroll
    for (int dy=-1;dy<=1;dy++){ int hh=h+dy; if(hh<0||hh>=HH) continue;
        #pragma unroll
        for (int dx=-1;dx<=1;dx++){ int ww=w+dx; if(ww<0||ww>=WW) continue;
            float v = xp[base+hh*WW+ww]; s+=v; mx=fmaxf(mx,v); } }
    y1[idx]=s*(1.f/9.f); y2[idx]=mx;
}
__global__ void reduce_k(const float* __restrict__ x, float* __restrict__ mean, float* __restrict__ mxo){
    __shared__ float ss[256], sm[256];
    int bc=blockIdx.x, t=threadIdx.x;
    const float* p = x + (long)bc*HWs;
    float s=0.f, m=-INFINITY;
    for (int i=t;i<HWs;i+=256){ float v=p[i]; s+=v; m=fmaxf(m,v); }
    ss[t]=s; sm[t]=m; __syncthreads();
    for (int o=128;o>0;o>>=1){ if (t<o){ ss[t]+=ss[t+o]; sm[t]=fmaxf(sm[t],sm[t+o]); } __syncthreads(); }
    if (t==0){ mean[bc]=ss[0]*(1.f/(float)HWs); mxo[bc]=sm[0]; }
}
__global__ void cagate_k(const float* __restrict__ amean, const float* __restrict__ amax,
    const float* __restrict__ aw1, const float* __restrict__ ab1,
    const float* __restrict__ aw2, const float* __restrict__ ab2,
    const float* __restrict__ mw1, const float* __restrict__ mb1,
    const float* __restrict__ mw2, const float* __restrict__ mb2, float* __restrict__ gate){
    __shared__ float ha[16], hm[16];
    int b=blockIdx.x, t=threadIdx.x;
    if (t<16){ float s=ab1[t]; for (int i=0;i<CC;i++) s+=aw1[t*CC+i]*amean[b*CC+i]; ha[t]=fmaxf(s,0.f); }
    else if (t<32){ int u=t-16; float s=mb1[u]; for (int i=0;i<CC;i++) s+=mw1[u*CC+i]*amax[b*CC+i]; hm[u]=fmaxf(s,0.f); }
    __syncthreads();
    float g = ab2[t]+mb2[t];
    #pragma unroll
    for (int k=0;k<16;k++) g += aw2[t*16+k]*ha[k] + mw2[t*16+k]*hm[k];
    gate[b*CC+t] = sigmoidf_(g);
}
__global__ void scalew_k(const float* __restrict__ w1, const float* __restrict__ w2,
                         const float* __restrict__ gate, float* __restrict__ w1g, float* __restrict__ w2g){
    int idx = blockIdx.x*256 + threadIdx.x;
    int b = idx >> 16, rem = idx & 65535, i = rem & 255;
    float g = gate[b*CC + i];
    w1g[idx] = w1[rem]*g;
    w2g[idx] = w2[rem]*g;
}

// ---- HMMA bf16 split GEMM: Y[b,m,n] = sum_k A[m,k] X[b,k,n] + bias, epi ----
// block: 128m x 128n, 8 warps (2m x 4n), warp 64m x 32n, k-chunk 32.
__global__ void __launch_bounds__(256,2) gemm_mma(
    const float* __restrict__ A, int aRS, long aBS,
    const float* __restrict__ X0, const float* __restrict__ X1,
    float* __restrict__ Y, const float* __restrict__ bias,
    int K, int epi, const float* __restrict__ E0, const float* __restrict__ E1)
{
    __shared__ __nv_bfloat16 Ah[128][40], Al[128][40], Bh[32][136], Bl[32][136];
    int b = blockIdx.z, m0 = blockIdx.y*128, n0 = blockIdx.x*128;
    int tid = threadIdx.x, lane = tid&31, wid = tid>>5;
    int wm = (wid&1)*64, wn = (wid>>1)*32;
    const float* Ab = A + (long)b*aBS;

    float acc[16][4];
    #pragma unroll
    for (int i=0;i<16;i++){ acc[i][0]=0;acc[i][1]=0;acc[i][2]=0;acc[i][3]=0; }

    // ldmatrix lane addressing
    int lr = lane&15, lc8 = (lane>>4)*8;
    u32 aBase = smem_u32(&Ah[0][0]), alBase = smem_u32(&Al[0][0]);
    u32 bBase = smem_u32(&Bh[0][0]), blBase = smem_u32(&Bl[0][0]);

    int ar = tid>>1, ac = (tid&1)*16;          // A tile: 128 x 32
    int bkr = tid>>3, bnc = (tid&7)*16;        // B tile: 32 x 128

    for (int k0=0; k0<K; k0+=32){
        // convert A chunk
        {
            const float* arow = Ab + (long)(m0+ar)*aRS + k0 + ac;
            float f[16];
            #pragma unroll
            for (int j=0;j<16;j++) f[j] = arow[j];
            u32* dh = (u32*)&Ah[ar][ac]; u32* dl = (u32*)&Al[ar][ac];
            #pragma unroll
            for (int j=0;j<8;j++){
                float x0=f[2*j], x1=f[2*j+1];
                u32 h = pack2(x0,x1);
                __nv_bfloat162 hv = *(__nv_bfloat162*)&h;
                dh[j] = h;
                dl[j] = pack2(x0-__bfloat162float(hv.x), x1-__bfloat162float(hv.y));
            }
        }
        // convert B chunk
        {
            int kg = k0 + bkr;
            const float* xr = ((kg<CC) ? (X0 + ((long)b*CC+kg)*HWs)
                                       : (X1 + ((long)b*CC+kg-CC)*HWs)) + n0 + bnc;
            float f[16];
            #pragma unroll
            for (int j=0;j<4;j++){ float4 v = *(const float4*)(xr + j*4);
                f[4*j]=v.x; f[4*j+1]=v.y; f[4*j+2]=v.z; f[4*j+3]=v.w; }
            u32* dh = (u32*)&Bh[bkr][bnc]; u32* dl = (u32*)&Bl[bkr][bnc];
            #pragma unroll
            for (int j=0;j<8;j++){
                float x0=f[2*j], x1=f[2*j+1];
                u32 h = pack2(x0,x1);
                __nv_bfloat162 hv = *(__nv_bfloat162*)&h;
                dh[j] = h;
                dl[j] = pack2(x0-__bfloat162float(hv.x), x1-__bfloat162float(hv.y));
            }
        }
        __syncthreads();
        #pragma unroll
        for (int ks=0; ks<32; ks+=16){
            u32 bh[4][2], bl[4][2];
            #pragma unroll
            for (int pr=0; pr<2; pr++){
                u32 off = (u32)(((ks+lr)*136 + wn + pr*16 + lc8)*2);
                ldsm4t(bh[pr*2][0], bh[pr*2][1], bh[pr*2+1][0], bh[pr*2+1][1], bBase + off);
                ldsm4t(bl[pr*2][0], bl[pr*2][1], bl[pr*2+1][0], bl[pr*2+1][1], blBase + off);
            }
            #pragma unroll
            for (int mt=0; mt<4; mt++){
                u32 ah[4], al[4];
                u32 off = (u32)(((wm+mt*16+lr)*40 + ks + lc8)*2);
                ldsm4(ah[0],ah[1],ah[2],ah[3], aBase + off);
                ldsm4(al[0],al[1],al[2],al[3], alBase + off);
                #pragma unroll
                for (int nt=0; nt<4; nt++){
                    mmabf(acc[mt*4+nt], ah, bh[nt]);
                    mmabf(acc[mt*4+nt], ah, bl[nt]);
                    mmabf(acc[mt*4+nt], al, bh[nt]);
                }
            }
        }
        __syncthreads();
    }
    // epilogue
    #pragma unroll
    for (int mt=0; mt<4; mt++){
        #pragma unroll
        for (int nt=0; nt<4; nt++){
            float* c = acc[mt*4+nt];
            int n = n0 + wn + nt*8 + (lane&3)*2;
            #pragma unroll
            for (int hlf=0; hlf<2; hlf++){
                int m = m0 + wm + mt*16 + (lane>>2) + hlf*8;
                float v0 = c[hlf*2] + bias[m], v1 = c[hlf*2+1] + bias[m];
                long yb = ((long)b*CC + m)*HWs + n;
                if (epi==1){ v0=fmaxf(v0,0.f); v1=fmaxf(v1,0.f); }
                else if (epi==2){ v0+=E0[yb]; v1+=E0[yb+1]; }
                else if (epi==3){ v0=sigmoidf_(v0)*E0[yb]; v1=sigmoidf_(v1)*E0[yb+1]; }
                else if (epi==4){
                    float wl = E1[(long)m*513 + 512];
                    long eb = (long)b*HWs + n;
                    v0 += wl*E0[eb]; v1 += wl*E0[eb+1];
                }
                float2 st = {v0, v1};
                *(float2*)(Y + yb) = st;
            }
        }
    }
}

// ---- scores + softmax (fp32 f32x2), optional colsum->mask ----
template<int WRITE_M>
__global__ void score_k(const float* __restrict__ Q, const float* __restrict__ S,
                        float* __restrict__ Mout, float* __restrict__ mOut)
{
    __shared__ __align__(16) float As[8][128];
    __shared__ __align__(16) float Ss[8][128];
    __shared__ float CS[16][128];
    int h=blockIdx.x, b=blockIdx.y;
    int tid=threadIdx.x, ti4=(tid>>4)*4, tj4=(tid&15)*4, lr=tid>>5, lc=(tid&31)*4;
    ull acc[8][4];
    #pragma unroll
    for (int i=0;i<8;i++){ acc[i][0]=0; acc[i][1]=0; acc[i][2]=0; acc[i][3]=0; }
    for (int k0=0;k0<CC;k0+=8){
        long qa = ((long)b*CC + k0 + lr)*HWs + h*WW + lc;
        float4 qv = *(const float4*)(Q+qa);
        float4 sv = *(const float4*)(S+qa);
        __syncthreads();
        *(float4*)&As[lr][lc]=qv; *(float4*)&Ss[lr][lc]=sv;
        __syncthreads();
        #pragma unroll
        for (int kq=0;kq<8;kq++){
            float4 a0=*(const float4*)&As[kq][ti4];
            float4 a1=*(const float4*)&As[kq][ti4+64];
            longlong2 q0=*(const longlong2*)&Ss[kq][tj4];
            longlong2 q1=*(const longlong2*)&Ss[kq][tj4+64];
            ull b0=(ull)q0.x,b1=(ull)q0.y,b2=(ull)q1.x,b3=(ull)q1.y;
            float am[8]={a0.x,a0.y,a0.z,a0.w,a1.x,a1.y,a1.z,a1.w};
            #pragma unroll
            for (int i=0;i<8;i++){
                ull ad=dup2(am[i]);
                acc[i][0]=fma2(ad,b0,acc[i][0]); acc[i][1]=fma2(ad,b1,acc[i][1]);
                acc[i][2]=fma2(ad,b2,acc[i][2]); acc[i][3]=fma2(ad,b3,acc[i][3]);
            }
        }
    }
    float s[8][8]; float csum[8];
    #pragma unroll
    for (int q=0;q<8;q++) csum[q]=0.f;
    #pragma unroll
    for (int ri=0;ri<8;ri++){
        #pragma unroll
        for (int jp=0;jp<4;jp++){ float2 u=unpk(acc[ri][jp]); s[ri][jp*2]=u.x; s[ri][jp*2+1]=u.y; }
    }
    #pragma unroll
    for (int ri=0;ri<8;ri++){
        float mx=s[ri][0];
        #pragma unroll
        for (int q=1;q<8;q++) mx=fmaxf(mx,s[ri][q]);
        #pragma unroll
        for (int k=1;k<16;k<<=1) mx=fmaxf(mx,__shfl_xor_sync(0xffffffffu,mx,k,16));
        float sum=0.f;
        #pragma unroll
        for (int q=0;q<8;q++){ s[ri][q]=expf(s[ri][q]-mx); sum+=s[ri][q]; }
        #pragma unroll
        for (int k=1;k<16;k<<=1) sum+=__shfl_xor_sync(0xffffffffu,sum,k,16);
        float inv=1.f/sum;
        #pragma unroll
        for (int q=0;q<8;q++){ s[ri][q]*=inv; if(!WRITE_M) csum[q]+=s[ri][q]; }
        if (WRITE_M){
            int r = ti4 + ((ri<4)?ri:60+ri);
            long base = ((long)(b*HH+h)*128 + r)*128;
            float4 v0={s[ri][0],s[ri][1],s[ri][2],s[ri][3]};
            float4 v1={s[ri][4],s[ri][5],s[ri][6],s[ri][7]};
            *(float4*)(Mout+base+tj4)=v0; *(float4*)(Mout+base+tj4+64)=v1;
        }
    }
    if (!WRITE_M){
        int ty=tid>>4;
        __syncthreads();
        *(float4*)&CS[ty][tj4]=*(float4*)&csum[0];
        *(float4*)&CS[ty][tj4+64]=*(float4*)&csum[4];
        __syncthreads();
        if (tid<128){
            float t=0.f;
            #pragma unroll
            for (int y=0;y<16;y++) t+=CS[y][tid];
            mOut[(long)b*HWs + h*WW + tid] = (t>0.1f)?0.f:1.f;
        }
    }
}

// ---- attend ----
__global__ void attend_k(const float* __restrict__ M, const float* __restrict__ V3, float* __restrict__ out){
    __shared__ __align__(16) float As[8][128];
    __shared__ __align__(16) float Bs[8][128];
    int m0=blockIdx.x*128, bh=blockIdx.y, b=bh>>7, h=bh&127;
    int tid=threadIdx.x, ti4=(tid>>4)*4, tj4=(tid&15)*4, la_m=tid>>1, la_k=(tid&1)*4;
    ull acc[8][4];
    #pragma unroll
    for (int i=0;i<8;i++){ acc[i][0]=0; acc[i][1]=0; acc[i][2]=0; acc[i][3]=0; }
    for (int k0=0;k0<128;k0+=8){
        float4 av = *(const float4*)(V3 + ((long)(b*CC+m0+la_m))*HWs + h*WW + k0 + la_k);
        float4 mv = *(const float4*)(M + ((long)bh*128 + la_m)*128 + k0 + la_k);
        __syncthreads();
        As[la_k+0][la_m]=av.x; As[la_k+1][la_m]=av.y; As[la_k+2][la_m]=av.z; As[la_k+3][la_m]=av.w;
        Bs[la_k+0][la_m]=mv.x; Bs[la_k+1][la_m]=mv.y; Bs[la_k+2][la_m]=mv.z; Bs[la_k+3][la_m]=mv.w;
        __syncthreads();
        #pragma unroll
        for (int kq=0;kq<8;kq++){
            float4 a0=*(const float4*)&As[kq][ti4];
            float4 a1=*(const float4*)&As[kq][ti4+64];
            longlong2 q0=*(const longlong2*)&Bs[kq][tj4];
            longlong2 q1=*(const longlong2*)&Bs[kq][tj4+64];
            ull b0=(ull)q0.x,b1=(ull)q0.y,b2=(ull)q1.x,b3=(ull)q1.y;
            float am[8]={a0.x,a0.y,a0.z,a0.w,a1.x,a1.y,a1.z,a1.w};
            #pragma unroll
            for (int i=0;i<8;i++){
                ull ad=dup2(am[i]);
                acc[i][0]=fma2(ad,b0,acc[i][0]); acc[i][1]=fma2(ad,b1,acc[i][1]);
                acc[i][2]=fma2(ad,b2,acc[i][2]); acc[i][3]=fma2(ad,b3,acc[i][3]);
            }
        }
    }
    #pragma unroll
    for (int ri=0;ri<8;ri++){
        int r = ti4 + ((ri<4)?ri:60+ri);
        long yb = ((long)(b*CC+m0+r))*HWs + h*WW;
        float f[8];
        #pragma unroll
        for (int jp=0;jp<4;jp++){ float2 u=unpk(acc[ri][jp]); f[jp*2]=u.x; f[jp*2+1]=u.y; }
        float4 v0={f[0],f[1],f[2],f[3]}, v1={f[4],f[5],f[6],f[7]};
        *(float4*)(out+yb+tj4)=v0; *(float4*)(out+yb+tj4+64)=v1;
    }
}

// ---- morphology ----
__global__ void morph_k(const float* __restrict__ src, float* __restrict__ dst,
                        int Wd, int Hd, int r, int erode, int total){
    int idx = blockIdx.x*256 + threadIdx.x;
    if (idx >= total) return;
    int plane=Wd*Hd, b=idx/plane, rem=idx-b*plane, h=rem/Wd, w=rem-h*Wd;
    const float* p = src + (long)b*plane;
    float res = erode ? 1.f : 0.f;
    int r2=r*r;
    for (int dy=-r;dy<=r;dy++) for (int dx=-r;dx<=r;dx++){
        if (dy*dy+dx*dx > r2) continue;
        int hh=h+dy, ww=w+dx;
        float v = (hh>=0&&hh<Hd&&ww>=0&&ww<Wd) ? p[hh*Wd+ww] : 0.f;
        if (erode){ if (v<0.5f) res=0.f; } else { if (v>0.5f) res=1.f; }
    }
    dst[(long)b*plane+rem]=res;
}
__global__ void pad_k(const float* __restrict__ src, float* __restrict__ dst, int total){
    int idx = blockIdx.x*256 + threadIdx.x;
    if (idx >= total) return;
    int b=idx/PHW, rem=idx-b*PHW, h=rem/PW, w=rem-h*PW;
    float v=0.f;
    if (h>=3 && h<3+HH && w>=3 && w<3+WW) v = src[(long)b*HWs + (h-3)*WW + (w-3)];
    dst[idx]=v;
}
__global__ void final_k(const float* __restrict__ src, float* __restrict__ dst){
    int idx = blockIdx.x*256 + threadIdx.x;
    int b=idx>>14, rem=idx&(HWs-1), h=rem>>7, w=rem&127;
    dst[idx] = 1.f - src[(long)b*PHW + (h+3)*PW + (w+3)];
}

extern "C" void kernel_launch(void* const* d_in, const int* in_sizes, int n_in,
                              void* d_out, int out_size) {
    const float* x_p=(const float*)d_in[0];  const float* x_c=(const float*)d_in[1];
    const float* pa_w1=(const float*)d_in[2];const float* pa_b1=(const float*)d_in[3];
    const float* pa_w2=(const float*)d_in[4];const float* pa_b2=(const float*)d_in[5];
    const float* pa_wc=(const float*)d_in[6];const float* pa_bc=(const float*)d_in[7];
    const float* ca_aw1=(const float*)d_in[8];const float* ca_ab1=(const float*)d_in[9];
    const float* ca_aw2=(const float*)d_in[10];const float* ca_ab2=(const float*)d_in[11];
    const float* ca_mw1=(const float*)d_in[12];const float* ca_mb1=(const float*)d_in[13];
    const float* ca_mw2=(const float*)d_in[14];const float* ca_mb2=(const float*)d_in[15];
    const float* b1_w=(const float*)d_in[16];const float* b1_b=(const float*)d_in[17];
    const float* b2_w=(const float*)d_in[18];const float* b2_b=(const float*)d_in[19];
    const float* b3_w=(const float*)d_in[20];const float* b3_b=(const float*)d_in[21];
    const float* fus_w=(const float*)d_in[22];const float* fus_b=(const float*)d_in[23];
    float* out=(float*)d_out;

    float *buf0,*buf1,*buf2,*buf3,*buf4,*buf5,*gM,*gate,*amean,*amax,*b1g,*b2g,*mA,*mB,*pA,*pB,*vfin;
    cudaGetSymbolAddress((void**)&buf0,g_buf0); cudaGetSymbolAddress((void**)&buf1,g_buf1);
    cudaGetSymbolAddress((void**)&buf2,g_buf2); cudaGetSymbolAddress((void**)&buf3,g_buf3);
    cudaGetSymbolAddress((void**)&buf4,g_buf4); cudaGetSymbolAddress((void**)&buf5,g_buf5);
    cudaGetSymbolAddress((void**)&gM,g_M);      cudaGetSymbolAddress((void**)&gate,g_gate);
    cudaGetSymbolAddress((void**)&amean,g_amean); cudaGetSymbolAddress((void**)&amax,g_amax);
    cudaGetSymbolAddress((void**)&b1g,g_b1g);   cudaGetSymbolAddress((void**)&b2g,g_b2g);
    cudaGetSymbolAddress((void**)&mA,g_mA); cudaGetSymbolAddress((void**)&mB,g_mB);
    cudaGetSymbolAddress((void**)&pA,g_pA); cudaGetSymbolAddress((void**)&pB,g_pB);
    cudaGetSymbolAddress((void**)&vfin,g_vfinal);

    pool_k<<<NBCHW/256,256>>>(x_p, buf0, buf1);
    reduce_k<<<BB*CC,256>>>(x_c, amean, amax);
    cagate_k<<<BB,256>>>(amean,amax,ca_aw1,ca_ab1,ca_aw2,ca_ab2,ca_mw1,ca_mb1,ca_mw2,ca_mb2,gate);
    scalew_k<<<(BB*CC*CC)/256,256>>>(b1_w,b2_w,gate,b1g,b2g);

    dim3 gg(HWs/128, CC/128, BB);
    // PALayer MLPs
    gemm_mma<<<gg,256>>>(pa_w1,256,0, buf0,0, buf2, pa_b1, 256, 1, 0, 0);
    gemm_mma<<<gg,256>>>(pa_w2,256,0, buf2,0, buf3, pa_b2, 256, 2, buf0, 0);
    gemm_mma<<<gg,256>>>(pa_w1,256,0, buf1,0, buf2, pa_b1, 256, 1, 0, 0);
    gemm_mma<<<gg,256>>>(pa_w2,256,0, buf2,0, buf4, pa_b2, 256, 2, buf1, 0);
    gemm_mma<<<gg,256>>>(pa_wc,512,0, buf3,buf4, buf5, pa_bc, 512, 3, x_p, 0);
    // Q/S/v3
    gemm_mma<<<gg,256>>>(b1_w,256,0,    buf5,0, buf0, b1_b, 256, 0, 0, 0);
    gemm_mma<<<gg,256>>>(b2g,256,65536, x_c, 0, buf1, b2_b, 256, 0, 0, 0);
    gemm_mma<<<gg,256>>>(b1g,256,65536, x_c, 0, buf2, b1_b, 256, 0, 0, 0);
    gemm_mma<<<gg,256>>>(b2_w,256,0,    buf5,0, buf3, b2_b, 256, 0, 0, 0);
    gemm_mma<<<gg,256>>>(b3_w,256,0,    x_c, 0, buf4, b3_b, 256, 0, 0, 0);
    // attention
    dim3 gs(HH,BB);
    score_k<1><<<gs,256>>>(buf0, buf1, gM, 0);
    score_k<0><<<gs,256>>>(buf2, buf3, 0, mA);
    // morphology
    int n128 = BB*HWs;
    morph_k<<<n128/256,256>>>(mA,mB,128,128,2,1,n128);
    morph_k<<<n128/256,256>>>(mB,mA,128,128,2,0,n128);
    morph_k<<<n128/256,256>>>(mA,mB,128,128,1,0,n128);
    morph_k<<<n128/256,256>>>(mB,mA,128,128,1,1,n128);
    int np=BB*PHW, gp=(np+255)/256;
    pad_k<<<gp,256>>>(mA,pA,np);
    morph_k<<<gp,256>>>(pA,pB,PW,PW,3,0,np);
    morph_k<<<gp,256>>>(pB,pA,PW,PW,3,1,np);
    final_k<<<n128/256,256>>>(pA,vfin);
    // attend + fusion
    dim3 ga(2,BB*HH);
    attend_k<<<ga,256>>>(gM, buf4, buf0);
    gemm_mma<<<gg,256>>>(fus_w,513,0, buf0, x_p, out, fus_b, 512, 4, vfin, fus_w);
}

// round 6
// speedup vs baseline: 1.8555x; 1.3387x over previous
#include <cuda_runtime.h>
#include <cuda_bf16.h>
#include <math.h>

#define BB 8
#define CC 256
#define HH 128
#define WW 128
#define HWs 16384
#define NBCHW (BB*CC*HWs)
#define PW 134
#define PHW (PW*PW)
typedef unsigned long long ull;
typedef unsigned int u32;

__device__ float g_buf0[NBCHW];
__device__ float g_buf1[NBCHW];
__device__ float g_buf2[NBCHW];
__device__ float g_buf3[NBCHW];
__device__ float g_buf4[NBCHW];
__device__ float g_buf5[NBCHW];
__device__ float g_M[(long)BB*HH*WW*WW];
__device__ float g_gate[BB*CC];
__device__ float g_amean[BB*CC];
__device__ float g_amax[BB*CC];
__device__ float g_mA[BB*HWs];
__device__ float g_mB[BB*HWs];
__device__ float g_pA[BB*PHW];
__device__ float g_pB[BB*PHW];
__device__ float g_vfinal[BB*HWs];
__device__ __align__(16) __nv_bfloat16 g_imgh[134217728];
__device__ __align__(16) __nv_bfloat16 g_imgl[134217728];
__device__ __align__(16) __nv_bfloat16 g_wih[1638400];
__device__ __align__(16) __nv_bfloat16 g_wil[1638400];
#define I0o 0L
#define I1o 33554432L
#define I2o 67108864L
#define I3o 100663296L

__device__ __forceinline__ ull fma2(ull a, ull b, ull c){
    ull d; asm("fma.rn.f32x2 %0, %1, %2, %3;" : "=l"(d) : "l"(a), "l"(b), "l"(c)); return d; }
__device__ __forceinline__ ull dup2(float a){
    ull d; asm("mov.b64 %0, {%1, %2};" : "=l"(d) : "f"(a), "f"(a)); return d; }
__device__ __forceinline__ float2 unpk(ull v){
    float2 r; asm("mov.b64 {%0, %1}, %2;" : "=f"(r.x), "=f"(r.y) : "l"(v)); return r; }
__device__ __forceinline__ float sigmoidf_(float x){ return 1.0f/(1.0f+expf(-x)); }
__device__ __forceinline__ u32 smem_u32(const void* p){
    u32 a; asm("{ .reg .u64 t; cvta.to.shared.u64 t, %1; cvt.u32.u64 %0, t; }" : "=r"(a) : "l"(p)); return a; }
__device__ __forceinline__ u32 pack2(float a, float b){
    __nv_bfloat162 t = __floats2bfloat162_rn(a, b); return *(u32*)&t; }
// write hi/lo bf16 pair at element index idx (even)
__device__ __forceinline__ void w2(__nv_bfloat16* oh, __nv_bfloat16* ol, long idx, float a, float b){
    u32 h = pack2(a,b); __nv_bfloat162 hv = *(__nv_bfloat162*)&h;
    ((u32*)oh)[idx>>1] = h;
    ((u32*)ol)[idx>>1] = pack2(a-__bfloat162float(hv.x), b-__bfloat162float(hv.y));
}
__device__ __forceinline__ void ldsm4(u32& r0,u32& r1,u32& r2,u32& r3,u32 a){
    asm volatile("ldmatrix.sync.aligned.m8n8.x4.shared.b16 {%0,%1,%2,%3}, [%4];"
        :"=r"(r0),"=r"(r1),"=r"(r2),"=r"(r3):"r"(a)); }
__device__ __forceinline__ void ldsm4t(u32& r0,u32& r1,u32& r2,u32& r3,u32 a){
    asm volatile("ldmatrix.sync.aligned.m8n8.x4.trans.shared.b16 {%0,%1,%2,%3}, [%4];"
        :"=r"(r0),"=r"(r1),"=r"(r2),"=r"(r3):"r"(a)); }
__device__ __forceinline__ void mmabf(float* c, const u32* a, const u32* b){
    asm volatile("mma.sync.aligned.m16n8k16.row.col.f32.bf16.bf16.f32 "
        "{%0,%1,%2,%3},{%4,%5,%6,%7},{%8,%9},{%0,%1,%2,%3};"
        :"+f"(c[0]),"+f"(c[1]),"+f"(c[2]),"+f"(c[3])
        :"r"(a[0]),"r"(a[1]),"r"(a[2]),"r"(a[3]),"r"(b[0]),"r"(b[1])); }
__device__ __forceinline__ void cpa(u32 d, const void* s){
    asm volatile("cp.async.cg.shared.global [%0], [%1], 16;"::"r"(d),"l"(s)); }
__device__ __forceinline__ void cpcommit(){ asm volatile("cp.async.commit_group;":::"memory"); }
__device__ __forceinline__ void cpwait1(){ asm volatile("cp.async.wait_group 1;":::"memory"); }
__device__ __forceinline__ void cpwait0(){ asm volatile("cp.async.wait_group 0;":::"memory"); }

// ---- pool / reduce / gate ----
__global__ void pool_k(const float* __restrict__ xp, float* __restrict__ y1, float* __restrict__ y2){
    long idx = (long)blockIdx.x*256 + threadIdx.x;
    if (idx >= (long)NBCHW) return;
    int w = (int)(idx & 127), h = (int)((idx>>7)&127);
    long base = idx - (long)(h*WW+w);
    float s=0.f, mx=-INFINITY;
    #pragma unroll
    for (int dy=-1;dy<=1;dy++){ int hh=h+dy; if(hh<0||hh>=HH) continue;
        #pragma unroll
        for (int dx=-1;dx<=1;dx++){ int ww=w+dx; if(ww<0||ww>=WW) continue;
            float v = xp[base+hh*WW+ww]; s+=v; mx=fmaxf(mx,v); } }
    y1[idx]=s*(1.f/9.f); y2[idx]=mx;
}
__global__ void reduce_k(const float* __restrict__ x, float* __restrict__ mean, float* __restrict__ mxo){
    __shared__ float ss[256], sm[256];
    int bc=blockIdx.x, t=threadIdx.x;
    const float* p = x + (long)bc*HWs;
    float s=0.f, m=-INFINITY;
    for (int i=t;i<HWs;i+=256){ float v=p[i]; s+=v; m=fmaxf(m,v); }
    ss[t]=s; sm[t]=m; __syncthreads();
    for (int o=128;o>0;o>>=1){ if (t<o){ ss[t]+=ss[t+o]; sm[t]=fmaxf(sm[t],sm[t+o]); } __syncthreads(); }
    if (t==0){ mean[bc]=ss[0]*(1.f/(float)HWs); mxo[bc]=sm[0]; }
}
__global__ void cagate_k(const float* __restrict__ amean, const float* __restrict__ amax,
    const float* __restrict__ aw1, const float* __restrict__ ab1,
    const float* __restrict__ aw2, const float* __restrict__ ab2,
    const float* __restrict__ mw1, const float* __restrict__ mb1,
    const float* __restrict__ mw2, const float* __restrict__ mb2, float* __restrict__ gate){
    __shared__ float ha[16], hm[16];
    int b=blockIdx.x, t=threadIdx.x;
    if (t<16){ float s=ab1[t]; for (int i=0;i<CC;i++) s+=aw1[t*CC+i]*amean[b*CC+i]; ha[t]=fmaxf(s,0.f); }
    else if (t<32){ int u=t-16; float s=mb1[u]; for (int i=0;i<CC;i++) s+=mw1[u*CC+i]*amax[b*CC+i]; hm[u]=fmaxf(s,0.f); }
    __syncthreads();
    float g = ab2[t]+mb2[t];
    #pragma unroll
    for (int k=0;k<16;k++) g += aw2[t*16+k]*ha[k] + mw2[t*16+k]*hm[k];
    gate[b*CC+t] = sigmoidf_(g);
}

// ---- fp32 activation -> bf16 hi/lo image (same layout) ----
__global__ void cvt_k(const float* __restrict__ src, __nv_bfloat16* __restrict__ oh, __nv_bfloat16* __restrict__ ol){
    long i4 = ((long)blockIdx.x*256 + threadIdx.x)*4;
    float4 v = *(const float4*)(src + i4);
    w2(oh, ol, i4,   v.x, v.y);
    w2(oh, ol, i4+2, v.z, v.w);
}
// ---- weights [256,K] (src row stride RS, optional per-(b,k) gate) -> row-major bf16 hi/lo ----
__global__ void cvtw_k(const float* __restrict__ W, int RS, int K, const float* __restrict__ gate,
                       __nv_bfloat16* __restrict__ oh, __nv_bfloat16* __restrict__ ol){
    int idx = blockIdx.x*256 + threadIdx.x;
    int b = idx/(256*K); int rem = idx - b*256*K; int m = rem/K, k = rem - m*K;
    float v = W[(long)m*RS + k];
    if (gate) v *= gate[b*256 + k];
    __nv_bfloat16 h = __float2bfloat16_rn(v);
    oh[idx] = h; ol[idx] = __float2bfloat16_rn(v - __bfloat162float(h));
}

// ---- HMMA GEMM: CTA = 256m x 128n, cp.async double-buffered bf16 operands ----
// smem stage (bytes): Ah 0 (256x40), Al 20480, Bh 40960 (32x136), Bl 49664; stage=58368
#define STG 58368u
#define GSM (2*58368)
__global__ void __launch_bounds__(256,1) gemm_mma(
    const __nv_bfloat16* __restrict__ Wh, const __nv_bfloat16* __restrict__ Wl, long wBS, int K,
    const __nv_bfloat16* __restrict__ X0h, const __nv_bfloat16* __restrict__ X0l,
    const __nv_bfloat16* __restrict__ X1h, const __nv_bfloat16* __restrict__ X1l,
    float* __restrict__ Yf, __nv_bfloat16* __restrict__ Yh, __nv_bfloat16* __restrict__ Yl,
    const float* __restrict__ bias, int epi, const float* __restrict__ E0, const float* __restrict__ E1)
{
    extern __shared__ __align__(16) char smem[];
    u32 sm = smem_u32(smem);
    int tid=threadIdx.x, lane=tid&31, wid=tid>>5;
    int n0 = blockIdx.x*128, b = blockIdx.y;
    int wm = (wid&1)*128, wn = (wid>>1)*32;
    int lr = lane&15, lc8 = (lane>>4)*8;
    const __nv_bfloat16* WhB = Wh + wBS*b;
    const __nv_bfloat16* WlB = Wl + wBS*b;
    int NC = K>>5;

    float acc[32][4];
    #pragma unroll
    for (int i=0;i<32;i++){ acc[i][0]=0;acc[i][1]=0;acc[i][2]=0;acc[i][3]=0; }

    for (int c=0; c<=NC; c++){
        if (c<NC){
            u32 st = sm + (u32)(c&1)*STG;
            int kb = c*32;
            #pragma unroll
            for (int j=0;j<4;j++){
                int o=tid+256*j, r=o>>2, cb=o&3;
                u32 d = st + (u32)(r*80+cb*16);
                cpa(d,          WhB + (size_t)r*K + kb + cb*8);
                cpa(d + 20480u, WlB + (size_t)r*K + kb + cb*8);
            }
            const __nv_bfloat16 *xh=X0h,*xl=X0l; int kk=kb;
            if (kk>=256){ xh=X1h; xl=X1l; kk-=256; }
            #pragma unroll
            for (int j=0;j<2;j++){
                int o=tid+256*j, r=o>>4, cb=o&15;
                size_t s = ((size_t)b*256 + kk + r)*HWs + n0 + cb*8;
                u32 d = st + 40960u + (u32)(r*272+cb*16);
                cpa(d,         xh + s);
                cpa(d + 8704u, xl + s);
            }
            cpcommit();
        }
        if (c==0) continue;
        if (c<NC) cpwait1(); else cpwait0();
        __syncthreads();
        u32 sA = sm + (u32)((c-1)&1)*STG;
        #pragma unroll
        for (int ks=0; ks<32; ks+=16){
            u32 bh[4][2], bl[4][2];
            #pragma unroll
            for (int pr=0; pr<2; pr++){
                u32 off = (u32)((ks+lr)*272 + (wn+pr*16+lc8)*2);
                ldsm4t(bh[pr*2][0],bh[pr*2][1],bh[pr*2+1][0],bh[pr*2+1][1], sA+40960u+off);
                ldsm4t(bl[pr*2][0],bl[pr*2][1],bl[pr*2+1][0],bl[pr*2+1][1], sA+49664u+off);
            }
            #pragma unroll
            for (int mt=0; mt<8; mt++){
                u32 ah[4], al[4];
                u32 off = (u32)((wm+mt*16+lr)*80 + (ks+lc8)*2);
                ldsm4(ah[0],ah[1],ah[2],ah[3], sA+off);
                ldsm4(al[0],al[1],al[2],al[3], sA+20480u+off);
                #pragma unroll
                for (int nt=0; nt<4; nt++){
                    float* cc = acc[mt*4+nt];
                    mmabf(cc, ah, bh[nt]); mmabf(cc, ah, bl[nt]); mmabf(cc, al, bh[nt]);
                }
            }
        }
        __syncthreads();
    }
    #pragma unroll
    for (int mt=0; mt<8; mt++){
        #pragma unroll
        for (int nt=0; nt<4; nt++){
            float* cc = acc[mt*4+nt];
            int n = n0 + wn + nt*8 + (lane&3)*2;
            #pragma unroll
            for (int hlf=0; hlf<2; hlf++){
                int m = wm + mt*16 + (lane>>2) + hlf*8;
                float v0 = cc[hlf*2] + bias[m], v1 = cc[hlf*2+1] + bias[m];
                long yb = ((long)b*CC + m)*HWs + n;
                if (epi==1){ v0=fmaxf(v0,0.f); v1=fmaxf(v1,0.f); }
                else if (epi==2){ v0+=E0[yb]; v1+=E0[yb+1]; }
                else if (epi==3){ v0=sigmoidf_(v0)*E0[yb]; v1=sigmoidf_(v1)*E0[yb+1]; }
                else if (epi==4){ float wl=E1[(long)m*513+512]; long eb=(long)b*HWs+n;
                    v0+=wl*E0[eb]; v1+=wl*E0[eb+1]; }
                if (Yf){ float2 st={v0,v1}; *(float2*)(Yf+yb)=st; }
                else   w2(Yh, Yl, yb, v0, v1);
            }
        }
    }
}

// ---- scores + softmax (fp32 f32x2), optional colsum->mask ----
template<int WRITE_M>
__global__ void score_k(const float* __restrict__ Q, const float* __restrict__ S,
                        float* __restrict__ Mout, float* __restrict__ mOut)
{
    __shared__ __align__(16) float As[8][128];
    __shared__ __align__(16) float Ss[8][128];
    __shared__ float CS[16][128];
    int h=blockIdx.x, b=blockIdx.y;
    int tid=threadIdx.x, ti4=(tid>>4)*4, tj4=(tid&15)*4, lr=tid>>5, lc=(tid&31)*4;
    ull acc[8][4];
    #pragma unroll
    for (int i=0;i<8;i++){ acc[i][0]=0; acc[i][1]=0; acc[i][2]=0; acc[i][3]=0; }
    for (int k0=0;k0<CC;k0+=8){
        long qa = ((long)b*CC + k0 + lr)*HWs + h*WW + lc;
        float4 qv = *(const float4*)(Q+qa);
        float4 sv = *(const float4*)(S+qa);
        __syncthreads();
        *(float4*)&As[lr][lc]=qv; *(float4*)&Ss[lr][lc]=sv;
        __syncthreads();
        #pragma unroll
        for (int kq=0;kq<8;kq++){
            float4 a0=*(const float4*)&As[kq][ti4];
            float4 a1=*(const float4*)&As[kq][ti4+64];
            longlong2 q0=*(const longlong2*)&Ss[kq][tj4];
            longlong2 q1=*(const longlong2*)&Ss[kq][tj4+64];
            ull b0=(ull)q0.x,b1=(ull)q0.y,b2=(ull)q1.x,b3=(ull)q1.y;
            float am[8]={a0.x,a0.y,a0.z,a0.w,a1.x,a1.y,a1.z,a1.w};
            #pragma unroll
            for (int i=0;i<8;i++){
                ull ad=dup2(am[i]);
                acc[i][0]=fma2(ad,b0,acc[i][0]); acc[i][1]=fma2(ad,b1,acc[i][1]);
                acc[i][2]=fma2(ad,b2,acc[i][2]); acc[i][3]=fma2(ad,b3,acc[i][3]);
            }
        }
    }
    float s[8][8]; float csum[8];
    #pragma unroll
    for (int q=0;q<8;q++) csum[q]=0.f;
    #pragma unroll
    for (int ri=0;ri<8;ri++){
        #pragma unroll
        for (int jp=0;jp<4;jp++){ float2 u=unpk(acc[ri][jp]); s[ri][jp*2]=u.x; s[ri][jp*2+1]=u.y; }
    }
    #pragma unroll
    for (int ri=0;ri<8;ri++){
        float mx=s[ri][0];
        #pragma unroll
        for (int q=1;q<8;q++) mx=fmaxf(mx,s[ri][q]);
        #pragma unroll
        for (int k=1;k<16;k<<=1) mx=fmaxf(mx,__shfl_xor_sync(0xffffffffu,mx,k,16));
        float sum=0.f;
        #pragma unroll
        for (int q=0;q<8;q++){ s[ri][q]=expf(s[ri][q]-mx); sum+=s[ri][q]; }
        #pragma unroll
        for (int k=1;k<16;k<<=1) sum+=__shfl_xor_sync(0xffffffffu,sum,k,16);
        float inv=1.f/sum;
        #pragma unroll
        for (int q=0;q<8;q++){ s[ri][q]*=inv; if(!WRITE_M) csum[q]+=s[ri][q]; }
        if (WRITE_M){
            int r = ti4 + ((ri<4)?ri:60+ri);
            long base = ((long)(b*HH+h)*128 + r)*128;
            float4 v0={s[ri][0],s[ri][1],s[ri][2],s[ri][3]};
            float4 v1={s[ri][4],s[ri][5],s[ri][6],s[ri][7]};
            *(float4*)(Mout+base+tj4)=v0; *(float4*)(Mout+base+tj4+64)=v1;
        }
    }
    if (!WRITE_M){
        int ty=tid>>4;
        __syncthreads();
        *(float4*)&CS[ty][tj4]=*(float4*)&csum[0];
        *(float4*)&CS[ty][tj4+64]=*(float4*)&csum[4];
        __syncthreads();
        if (tid<128){
            float t=0.f;
            #pragma unroll
            for (int y=0;y<16;y++) t+=CS[y][tid];
            mOut[(long)b*HWs + h*WW + tid] = (t>0.1f)?0.f:1.f;
        }
    }
}

// ---- attend: emits bf16 hi/lo image for the fusion GEMM ----
__global__ void attend_k(const float* __restrict__ M, const float* __restrict__ V3,
                         __nv_bfloat16* __restrict__ oh, __nv_bfloat16* __restrict__ ol){
    __shared__ __align__(16) float As[8][128];
    __shared__ __align__(16) float Bs[8][128];
    int m0=blockIdx.x*128, bh=blockIdx.y, b=bh>>7, h=bh&127;
    int tid=threadIdx.x, ti4=(tid>>4)*4, tj4=(tid&15)*4, la_m=tid>>1, la_k=(tid&1)*4;
    ull acc[8][4];
    #pragma unroll
    for (int i=0;i<8;i++){ acc[i][0]=0; acc[i][1]=0; acc[i][2]=0; acc[i][3]=0; }
    for (int k0=0;k0<128;k0+=8){
        float4 av = *(const float4*)(V3 + ((long)(b*CC+m0+la_m))*HWs + h*WW + k0 + la_k);
        float4 mv = *(const float4*)(M + ((long)bh*128 + la_m)*128 + k0 + la_k);
        __syncthreads();
        As[la_k+0][la_m]=av.x; As[la_k+1][la_m]=av.y; As[la_k+2][la_m]=av.z; As[la_k+3][la_m]=av.w;
        Bs[la_k+0][la_m]=mv.x; Bs[la_k+1][la_m]=mv.y; Bs[la_k+2][la_m]=mv.z; Bs[la_k+3][la_m]=mv.w;
        __syncthreads();
        #pragma unroll
        for (int kq=0;kq<8;kq++){
            float4 a0=*(const float4*)&As[kq][ti4];
            float4 a1=*(const float4*)&As[kq][ti4+64];
            longlong2 q0=*(const longlong2*)&Bs[kq][tj4];
            longlong2 q1=*(const longlong2*)&Bs[kq][tj4+64];
            ull b0=(ull)q0.x,b1=(ull)q0.y,b2=(ull)q1.x,b3=(ull)q1.y;
            float am[8]={a0.x,a0.y,a0.z,a0.w,a1.x,a1.y,a1.z,a1.w};
            #pragma unroll
            for (int i=0;i<8;i++){
                ull ad=dup2(am[i]);
                acc[i][0]=fma2(ad,b0,acc[i][0]); acc[i][1]=fma2(ad,b1,acc[i][1]);
                acc[i][2]=fma2(ad,b2,acc[i][2]); acc[i][3]=fma2(ad,b3,acc[i][3]);
            }
        }
    }
    #pragma unroll
    for (int ri=0;ri<8;ri++){
        int r = ti4 + ((ri<4)?ri:60+ri);
        long yb = ((long)(b*CC+m0+r))*HWs + h*WW;
        float f[8];
        #pragma unroll
        for (int jp=0;jp<4;jp++){ float2 u=unpk(acc[ri][jp]); f[jp*2]=u.x; f[jp*2+1]=u.y; }
        w2(oh,ol, yb+tj4,    f[0],f[1]); w2(oh,ol, yb+tj4+2,  f[2],f[3]);
        w2(oh,ol, yb+tj4+64, f[4],f[5]); w2(oh,ol, yb+tj4+66, f[6],f[7]);
    }
}

// ---- morphology ----
__global__ void morph_k(const float* __restrict__ src, float* __restrict__ dst,
                        int Wd, int Hd, int r, int erode, int total){
    int idx = blockIdx.x*256 + threadIdx.x;
    if (idx >= total) return;
    int plane=Wd*Hd, b=idx/plane, rem=idx-b*plane, h=rem/Wd, w=rem-h*Wd;
    const float* p = src + (long)b*plane;
    float res = erode ? 1.f : 0.f;
    int r2=r*r;
    for (int dy=-r;dy<=r;dy++) for (int dx=-r;dx<=r;dx++){
        if (dy*dy+dx*dx > r2) continue;
        int hh=h+dy, ww=w+dx;
        float v = (hh>=0&&hh<Hd&&ww>=0&&ww<Wd) ? p[hh*Wd+ww] : 0.f;
        if (erode){ if (v<0.5f) res=0.f; } else { if (v>0.5f) res=1.f; }
    }
    dst[(long)b*plane+rem]=res;
}
__global__ void pad_k(const float* __restrict__ src, float* __restrict__ dst, int total){
    int idx = blockIdx.x*256 + threadIdx.x;
    if (idx >= total) return;
    int b=idx/PHW, rem=idx-b*PHW, h=rem/PW, w=rem-h*PW;
    float v=0.f;
    if (h>=3 && h<3+HH && w>=3 && w<3+WW) v = src[(long)b*HWs + (h-3)*WW + (w-3)];
    dst[idx]=v;
}
__global__ void final_k(const float* __restrict__ src, float* __restrict__ dst){
    int idx = blockIdx.x*256 + threadIdx.x;
    int b=idx>>14, rem=idx&(HWs-1), h=rem>>7, w=rem&127;
    dst[idx] = 1.f - src[(long)b*PHW + (h+3)*PW + (w+3)];
}

extern "C" void kernel_launch(void* const* d_in, const int* in_sizes, int n_in,
                              void* d_out, int out_size) {
    const float* x_p=(const float*)d_in[0];  const float* x_c=(const float*)d_in[1];
    const float* pa_w1=(const float*)d_in[2];const float* pa_b1=(const float*)d_in[3];
    const float* pa_w2=(const float*)d_in[4];const float* pa_b2=(const float*)d_in[5];
    const float* pa_wc=(const float*)d_in[6];const float* pa_bc=(const float*)d_in[7];
    const float* ca_aw1=(const float*)d_in[8];const float* ca_ab1=(const float*)d_in[9];
    const float* ca_aw2=(const float*)d_in[10];const float* ca_ab2=(const float*)d_in[11];
    const float* ca_mw1=(const float*)d_in[12];const float* ca_mb1=(const float*)d_in[13];
    const float* ca_mw2=(const float*)d_in[14];const float* ca_mb2=(const float*)d_in[15];
    const float* b1_w=(const float*)d_in[16];const float* b1_b=(const float*)d_in[17];
    const float* b2_w=(const float*)d_in[18];const float* b2_b=(const float*)d_in[19];
    const float* b3_w=(const float*)d_in[20];const float* b3_b=(const float*)d_in[21];
    const float* fus_w=(const float*)d_in[22];const float* fus_b=(const float*)d_in[23];
    float* out=(float*)d_out;

    float *buf0,*buf1,*buf2,*buf3,*buf4,*buf5,*gM,*gate,*amean,*amax,*mA,*mB,*pA,*pB,*vfin;
    __nv_bfloat16 *ih,*il,*wh,*wl;
    cudaGetSymbolAddress((void**)&buf0,g_buf0); cudaGetSymbolAddress((void**)&buf1,g_buf1);
    cudaGetSymbolAddress((void**)&buf2,g_buf2); cudaGetSymbolAddress((void**)&buf3,g_buf3);
    cudaGetSymbolAddress((void**)&buf4,g_buf4); cudaGetSymbolAddress((void**)&buf5,g_buf5);
    cudaGetSymbolAddress((void**)&gM,g_M);      cudaGetSymbolAddress((void**)&gate,g_gate);
    cudaGetSymbolAddress((void**)&amean,g_amean); cudaGetSymbolAddress((void**)&amax,g_amax);
    cudaGetSymbolAddress((void**)&mA,g_mA); cudaGetSymbolAddress((void**)&mB,g_mB);
    cudaGetSymbolAddress((void**)&pA,g_pA); cudaGetSymbolAddress((void**)&pB,g_pB);
    cudaGetSymbolAddress((void**)&vfin,g_vfinal);
    cudaGetSymbolAddress((void**)&ih,g_imgh); cudaGetSymbolAddress((void**)&il,g_imgl);
    cudaGetSymbolAddress((void**)&wh,g_wih);  cudaGetSymbolAddress((void**)&wl,g_wil);
    cudaFuncSetAttribute(gemm_mma, cudaFuncAttributeMaxDynamicSharedMemorySize, GSM);

    // weight image element offsets
    const long W1=0,W2=65536,WC=131072,B1=262144,B2=327680,B3=393216,FU=458752,B1G=589824,B2G=1114112;

    pool_k<<<NBCHW/256,256>>>(x_p, buf0, buf1);
    reduce_k<<<BB*CC,256>>>(x_c, amean, amax);
    cagate_k<<<BB,256>>>(amean,amax,ca_aw1,ca_ab1,ca_aw2,ca_ab2,ca_mw1,ca_mb1,ca_mw2,ca_mb2,gate);

    cvtw_k<<<256,256>>>(pa_w1,256,256,0, wh+W1, wl+W1);
    cvtw_k<<<256,256>>>(pa_w2,256,256,0, wh+W2, wl+W2);
    cvtw_k<<<512,256>>>(pa_wc,512,512,0, wh+WC, wl+WC);
    cvtw_k<<<256,256>>>(b1_w,256,256,0, wh+B1, wl+B1);
    cvtw_k<<<256,256>>>(b2_w,256,256,0, wh+B2, wl+B2);
    cvtw_k<<<256,256>>>(b3_w,256,256,0, wh+B3, wl+B3);
    cvtw_k<<<512,256>>>(fus_w,513,512,0, wh+FU, wl+FU);
    cvtw_k<<<2048,256>>>(b1_w,256,256,gate, wh+B1G, wl+B1G);
    cvtw_k<<<2048,256>>>(b2_w,256,256,gate, wh+B2G, wl+B2G);

    dim3 gg(128, BB);
    // PALayer avg path
    cvt_k<<<NBCHW/1024,256>>>(buf0, ih+I0o, il+I0o);
    gemm_mma<<<gg,256,GSM>>>(wh+W1,wl+W1,0,256, ih+I0o,il+I0o,0,0, 0, ih+I1o,il+I1o, pa_b1,1, 0,0);
    gemm_mma<<<gg,256,GSM>>>(wh+W2,wl+W2,0,256, ih+I1o,il+I1o,0,0, 0, ih+I2o,il+I2o, pa_b2,2, buf0,0);
    // max path
    cvt_k<<<NBCHW/1024,256>>>(buf1, ih+I0o, il+I0o);
    gemm_mma<<<gg,256,GSM>>>(wh+W1,wl+W1,0,256, ih+I0o,il+I0o,0,0, 0, ih+I1o,il+I1o, pa_b1,1, 0,0);
    gemm_mma<<<gg,256,GSM>>>(wh+W2,wl+W2,0,256, ih+I1o,il+I1o,0,0, 0, ih+I3o,il+I3o, pa_b2,2, buf1,0);
    // buffer_p
    gemm_mma<<<gg,256,GSM>>>(wh+WC,wl+WC,0,512, ih+I2o,il+I2o, ih+I3o,il+I3o, 0, ih+I0o,il+I0o, pa_bc,3, x_p,0);
    // x_c image
    cvt_k<<<NBCHW/1024,256>>>(x_c, ih+I1o, il+I1o);
    // Q1,S1,Q2,S2,v3
    gemm_mma<<<gg,256,GSM>>>(wh+B1,wl+B1,0,256,      ih+I0o,il+I0o,0,0, buf2,0,0, b1_b,0, 0,0);
    gemm_mma<<<gg,256,GSM>>>(wh+B2G,wl+B2G,65536,256, ih+I1o,il+I1o,0,0, buf3,0,0, b2_b,0, 0,0);
    gemm_mma<<<gg,256,GSM>>>(wh+B1G,wl+B1G,65536,256, ih+I1o,il+I1o,0,0, buf4,0,0, b1_b,0, 0,0);
    gemm_mma<<<gg,256,GSM>>>(wh+B2,wl+B2,0,256,      ih+I0o,il+I0o,0,0, buf5,0,0, b2_b,0, 0,0);
    gemm_mma<<<gg,256,GSM>>>(wh+B3,wl+B3,0,256,      ih+I1o,il+I1o,0,0, buf0,0,0, b3_b,0, 0,0);
    cvt_k<<<NBCHW/1024,256>>>(x_p, ih+I2o, il+I2o);
    // attention
    dim3 gs(HH,BB);
    score_k<1><<<gs,256>>>(buf2, buf3, gM, 0);
    score_k<0><<<gs,256>>>(buf4, buf5, 0, mA);
    // morphology
    int n128 = BB*HWs;
    morph_k<<<n128/256,256>>>(mA,mB,128,128,2,1,n128);
    morph_k<<<n128/256,256>>>(mB,mA,128,128,2,0,n128);
    morph_k<<<n128/256,256>>>(mA,mB,128,128,1,0,n128);
    morph_k<<<n128/256,256>>>(mB,mA,128,128,1,1,n128);
    int np=BB*PHW, gp=(np+255)/256;
    pad_k<<<gp,256>>>(mA,pA,np);
    morph_k<<<gp,256>>>(pA,pB,PW,PW,3,0,np);
    morph_k<<<gp,256>>>(pB,pA,PW,PW,3,1,np);
    final_k<<<n128/256,256>>>(pA,vfin);
    // attend (bf16 image out) + fusion
    dim3 ga(2,BB*HH);
    attend_k<<<ga,256>>>(gM, buf0, ih+I3o, il+I3o);
    gemm_mma<<<gg,256,GSM>>>(wh+FU,wl+FU,0,512, ih+I3o,il+I3o, ih+I2o,il+I2o, out,0,0, fus_b,4, vfin,fus_w);
}

// round 7
// speedup vs baseline: 1.8939x; 1.0207x over previous
#include <cuda_runtime.h>
#include <cuda_bf16.h>
#include <math.h>

#define BB 8
#define CC 256
#define HH 128
#define WW 128
#define HWs 16384
#define NBCHW (BB*CC*HWs)
#define PW 134
#define PHW (PW*PW)
typedef unsigned long long ull;
typedef unsigned int u32;

__device__ float g_buf0[NBCHW];
__device__ float g_buf1[NBCHW];
__device__ float g_gate[BB*CC];
__device__ float g_amean[BB*CC];
__device__ float g_amax[BB*CC];
__device__ float g_mA[BB*HWs];
__device__ float g_mB[BB*HWs];
__device__ float g_pA[BB*PHW];
__device__ float g_pB[BB*PHW];
__device__ float g_vfinal[BB*HWs];
__device__ __align__(16) __nv_bfloat16 g_imgh[335544320];
__device__ __align__(16) __nv_bfloat16 g_imgl[335544320];
__device__ __align__(16) __nv_bfloat16 g_Mh[16777216];
__device__ __align__(16) __nv_bfloat16 g_Ml[16777216];
__device__ __align__(16) __nv_bfloat16 g_wih[1638400];
__device__ __align__(16) __nv_bfloat16 g_wil[1638400];
#define IK(k) ((long)(k)*33554432L)

__device__ __forceinline__ float sigmoidf_(float x){ return 1.0f/(1.0f+expf(-x)); }
__device__ __forceinline__ u32 smem_u32(const void* p){
    u32 a; asm("{ .reg .u64 t; cvta.to.shared.u64 t, %1; cvt.u32.u64 %0, t; }" : "=r"(a) : "l"(p)); return a; }
__device__ __forceinline__ u32 pack2(float a, float b){
    __nv_bfloat162 t = __floats2bfloat162_rn(a, b); return *(u32*)&t; }
__device__ __forceinline__ void w2(__nv_bfloat16* oh, __nv_bfloat16* ol, long idx, float a, float b){
    u32 h = pack2(a,b); __nv_bfloat162 hv = *(__nv_bfloat162*)&h;
    ((u32*)oh)[idx>>1] = h;
    ((u32*)ol)[idx>>1] = pack2(a-__bfloat162float(hv.x), b-__bfloat162float(hv.y));
}
__device__ __forceinline__ void ldsm4(u32& r0,u32& r1,u32& r2,u32& r3,u32 a){
    asm volatile("ldmatrix.sync.aligned.m8n8.x4.shared.b16 {%0,%1,%2,%3}, [%4];"
        :"=r"(r0),"=r"(r1),"=r"(r2),"=r"(r3):"r"(a)); }
__device__ __forceinline__ void ldsm4t(u32& r0,u32& r1,u32& r2,u32& r3,u32 a){
    asm volatile("ldmatrix.sync.aligned.m8n8.x4.trans.shared.b16 {%0,%1,%2,%3}, [%4];"
        :"=r"(r0),"=r"(r1),"=r"(r2),"=r"(r3):"r"(a)); }
__device__ __forceinline__ void mmabf(float* c, const u32* a, const u32* b){
    asm volatile("mma.sync.aligned.m16n8k16.row.col.f32.bf16.bf16.f32 "
        "{%0,%1,%2,%3},{%4,%5,%6,%7},{%8,%9},{%0,%1,%2,%3};"
        :"+f"(c[0]),"+f"(c[1]),"+f"(c[2]),"+f"(c[3])
        :"r"(a[0]),"r"(a[1]),"r"(a[2]),"r"(a[3]),"r"(b[0]),"r"(b[1])); }
__device__ __forceinline__ void cpa(u32 d, const void* s){
    asm volatile("cp.async.cg.shared.global [%0], [%1], 16;"::"r"(d),"l"(s)); }
__device__ __forceinline__ void cpcommit(){ asm volatile("cp.async.commit_group;":::"memory"); }
__device__ __forceinline__ void cpwait1(){ asm volatile("cp.async.wait_group 1;":::"memory"); }
__device__ __forceinline__ void cpwait0(){ asm volatile("cp.async.wait_group 0;":::"memory"); }

// ---- pool / reduce / gate ----
__global__ void pool_k(const float* __restrict__ xp, float* __restrict__ y1, float* __restrict__ y2){
    long idx = (long)blockIdx.x*256 + threadIdx.x;
    if (idx >= (long)NBCHW) return;
    int w = (int)(idx & 127), h = (int)((idx>>7)&127);
    long base = idx - (long)(h*WW+w);
    float s=0.f, mx=-INFINITY;
    #pragma unroll
    for (int dy=-1;dy<=1;dy++){ int hh=h+dy; if(hh<0||hh>=HH) continue;
        #pragma unroll
        for (int dx=-1;dx<=1;dx++){ int ww=w+dx; if(ww<0||ww>=WW) continue;
            float v = xp[base+hh*WW+ww]; s+=v; mx=fmaxf(mx,v); } }
    y1[idx]=s*(1.f/9.f); y2[idx]=mx;
}
__global__ void reduce_k(const float* __restrict__ x, float* __restrict__ mean, float* __restrict__ mxo){
    __shared__ float ss[256], sm[256];
    int bc=blockIdx.x, t=threadIdx.x;
    const float* p = x + (long)bc*HWs;
    float s=0.f, m=-INFINITY;
    for (int i=t;i<HWs;i+=256){ float v=p[i]; s+=v; m=fmaxf(m,v); }
    ss[t]=s; sm[t]=m; __syncthreads();
    for (int o=128;o>0;o>>=1){ if (t<o){ ss[t]+=ss[t+o]; sm[t]=fmaxf(sm[t],sm[t+o]); } __syncthreads(); }
    if (t==0){ mean[bc]=ss[0]*(1.f/(float)HWs); mxo[bc]=sm[0]; }
}
__global__ void cagate_k(const float* __restrict__ amean, const float* __restrict__ amax,
    const float* __restrict__ aw1, const float* __restrict__ ab1,
    const float* __restrict__ aw2, const float* __restrict__ ab2,
    const float* __restrict__ mw1, const float* __restrict__ mb1,
    const float* __restrict__ mw2, const float* __restrict__ mb2, float* __restrict__ gate){
    __shared__ float ha[16], hm[16];
    int b=blockIdx.x, t=threadIdx.x;
    if (t<16){ float s=ab1[t]; for (int i=0;i<CC;i++) s+=aw1[t*CC+i]*amean[b*CC+i]; ha[t]=fmaxf(s,0.f); }
    else if (t<32){ int u=t-16; float s=mb1[u]; for (int i=0;i<CC;i++) s+=mw1[u*CC+i]*amax[b*CC+i]; hm[u]=fmaxf(s,0.f); }
    __syncthreads();
    float g = ab2[t]+mb2[t];
    #pragma unroll
    for (int k=0;k<16;k++) g += aw2[t*16+k]*ha[k] + mw2[t*16+k]*hm[k];
    gate[b*CC+t] = sigmoidf_(g);
}
__global__ void cvt_k(const float* __restrict__ src, __nv_bfloat16* __restrict__ oh, __nv_bfloat16* __restrict__ ol){
    long i4 = ((long)blockIdx.x*256 + threadIdx.x)*4;
    float4 v = *(const float4*)(src + i4);
    w2(oh, ol, i4,   v.x, v.y);
    w2(oh, ol, i4+2, v.z, v.w);
}
__global__ void cvtw_k(const float* __restrict__ W, int RS, int K, const float* __restrict__ gate,
                       __nv_bfloat16* __restrict__ oh, __nv_bfloat16* __restrict__ ol){
    int idx = blockIdx.x*256 + threadIdx.x;
    int b = idx/(256*K); int rem = idx - b*256*K; int m = rem/K, k = rem - m*K;
    float v = W[(long)m*RS + k];
    if (gate) v *= gate[b*256 + k];
    __nv_bfloat16 h = __float2bfloat16_rn(v);
    oh[idx] = h; ol[idx] = __float2bfloat16_rn(v - __bfloat162float(h));
}

// ---- HMMA GEMM: CTA = 256m x 128n ----
#define STG 58368u
#define GSM (2*58368)
__global__ void __launch_bounds__(256,1) gemm_mma(
    const __nv_bfloat16* __restrict__ Wh, const __nv_bfloat16* __restrict__ Wl, long wBS, int K,
    const __nv_bfloat16* __restrict__ X0h, const __nv_bfloat16* __restrict__ X0l,
    const __nv_bfloat16* __restrict__ X1h, const __nv_bfloat16* __restrict__ X1l,
    float* __restrict__ Yf, __nv_bfloat16* __restrict__ Yh, __nv_bfloat16* __restrict__ Yl,
    const float* __restrict__ bias, int epi, const float* __restrict__ E0, const float* __restrict__ E1)
{
    extern __shared__ __align__(16) char smem[];
    u32 sm = smem_u32(smem);
    int tid=threadIdx.x, lane=tid&31, wid=tid>>5;
    int n0 = blockIdx.x*128, b = blockIdx.y;
    int wm = (wid&1)*128, wn = (wid>>1)*32;
    int lr = lane&15, lc8 = (lane>>4)*8;
    const __nv_bfloat16* WhB = Wh + wBS*b;
    const __nv_bfloat16* WlB = Wl + wBS*b;
    int NC = K>>5;
    float acc[32][4];
    #pragma unroll
    for (int i=0;i<32;i++){ acc[i][0]=0;acc[i][1]=0;acc[i][2]=0;acc[i][3]=0; }
    for (int c=0; c<=NC; c++){
        if (c<NC){
            u32 st = sm + (u32)(c&1)*STG;
            int kb = c*32;
            #pragma unroll
            for (int j=0;j<4;j++){
                int o=tid+256*j, r=o>>2, cb=o&3;
                u32 d = st + (u32)(r*80+cb*16);
                cpa(d,          WhB + (size_t)r*K + kb + cb*8);
                cpa(d + 20480u, WlB + (size_t)r*K + kb + cb*8);
            }
            const __nv_bfloat16 *xh=X0h,*xl=X0l; int kk=kb;
            if (kk>=256){ xh=X1h; xl=X1l; kk-=256; }
            #pragma unroll
            for (int j=0;j<2;j++){
                int o=tid+256*j, r=o>>4, cb=o&15;
                size_t s = ((size_t)b*256 + kk + r)*HWs + n0 + cb*8;
                u32 d = st + 40960u + (u32)(r*272+cb*16);
                cpa(d,         xh + s);
                cpa(d + 8704u, xl + s);
            }
            cpcommit();
        }
        if (c==0) continue;
        if (c<NC) cpwait1(); else cpwait0();
        __syncthreads();
        u32 sA = sm + (u32)((c-1)&1)*STG;
        #pragma unroll
        for (int ks=0; ks<32; ks+=16){
            u32 bh[4][2], bl[4][2];
            #pragma unroll
            for (int pr=0; pr<2; pr++){
                u32 off = (u32)((ks+lr)*272 + (wn+pr*16+lc8)*2);
                ldsm4t(bh[pr*2][0],bh[pr*2][1],bh[pr*2+1][0],bh[pr*2+1][1], sA+40960u+off);
                ldsm4t(bl[pr*2][0],bl[pr*2][1],bl[pr*2+1][0],bl[pr*2+1][1], sA+49664u+off);
            }
            #pragma unroll
            for (int mt=0; mt<8; mt++){
                u32 ah[4], al[4];
                u32 off = (u32)((wm+mt*16+lr)*80 + (ks+lc8)*2);
                ldsm4(ah[0],ah[1],ah[2],ah[3], sA+off);
                ldsm4(al[0],al[1],al[2],al[3], sA+20480u+off);
                #pragma unroll
                for (int nt=0; nt<4; nt++){
                    float* cc = acc[mt*4+nt];
                    mmabf(cc, ah, bh[nt]); mmabf(cc, ah, bl[nt]); mmabf(cc, al, bh[nt]);
                }
            }
        }
        __syncthreads();
    }
    #pragma unroll
    for (int mt=0; mt<8; mt++){
        #pragma unroll
        for (int nt=0; nt<4; nt++){
            float* cc = acc[mt*4+nt];
            int n = n0 + wn + nt*8 + (lane&3)*2;
            #pragma unroll
            for (int hlf=0; hlf<2; hlf++){
                int m = wm + mt*16 + (lane>>2) + hlf*8;
                float v0 = cc[hlf*2] + bias[m], v1 = cc[hlf*2+1] + bias[m];
                long yb = ((long)b*CC + m)*HWs + n;
                if (epi==1){ v0=fmaxf(v0,0.f); v1=fmaxf(v1,0.f); }
                else if (epi==2){ v0+=E0[yb]; v1+=E0[yb+1]; }
                else if (epi==3){ v0=sigmoidf_(v0)*E0[yb]; v1=sigmoidf_(v1)*E0[yb+1]; }
                else if (epi==4){ float wl=E1[(long)m*513+512]; long eb=(long)b*HWs+n;
                    v0+=wl*E0[eb]; v1+=wl*E0[eb+1]; }
                if (Yf){ float2 st={v0,v1}; *(float2*)(Yf+yb)=st; }
                else   w2(Yh, Yl, yb, v0, v1);
            }
        }
    }
}

// ---- HMMA score + softmax: per (b,h), S[i,j]=sum_c Q[c,i]S[c,j], softmax over j ----
// stage: Qh 0, Ql 8704, Sh 17408, Sl 26112; stage=34816, dyn smem = 69632
template<int WRITE_M>
__global__ void __launch_bounds__(256,1) score_mma(
    const __nv_bfloat16* __restrict__ Qh, const __nv_bfloat16* __restrict__ Ql,
    const __nv_bfloat16* __restrict__ Sh, const __nv_bfloat16* __restrict__ Sl,
    __nv_bfloat16* __restrict__ Mh, __nv_bfloat16* __restrict__ Ml,
    float* __restrict__ mOut)
{
    extern __shared__ __align__(16) char smem[];
    u32 sm = smem_u32(smem);
    float* smE = (float*)smem;
    int tid=threadIdx.x, lane=tid&31, wid=tid>>5;
    int h = blockIdx.x, b = blockIdx.y;
    int wm=(wid&1)*64, wn=(wid>>1)*32;
    int lr=lane&15, lc8=(lane>>4)*8;
    float acc[16][4];
    #pragma unroll
    for (int i=0;i<16;i++){ acc[i][0]=0;acc[i][1]=0;acc[i][2]=0;acc[i][3]=0; }
    for (int c=0;c<=8;c++){
        if (c<8){
            u32 st = sm + (u32)(c&1)*34816u;
            int kb = c*32;
            #pragma unroll
            for (int j=0;j<2;j++){
                int o = tid + 256*j, r = o>>4, cb = o&15;
                size_t s = ((size_t)(b*256 + kb + r))*HWs + h*128 + cb*8;
                u32 d = st + (u32)(r*272 + cb*16);
                cpa(d, Qh+s); cpa(d+8704u, Ql+s);
                cpa(d+17408u, Sh+s); cpa(d+26112u, Sl+s);
            }
            cpcommit();
        }
        if (c==0) continue;
        if (c<8) cpwait1(); else cpwait0();
        __syncthreads();
        u32 sA = sm + (u32)((c-1)&1)*34816u;
        #pragma unroll
        for (int ks=0;ks<32;ks+=16){
            u32 bh[4][2], bl[4][2];
            #pragma unroll
            for (int pr=0;pr<2;pr++){
                u32 off = (u32)((ks+lr)*272 + (wn+pr*16+lc8)*2);
                ldsm4t(bh[pr*2][0],bh[pr*2][1],bh[pr*2+1][0],bh[pr*2+1][1], sA+17408u+off);
                ldsm4t(bl[pr*2][0],bl[pr*2][1],bl[pr*2+1][0],bl[pr*2+1][1], sA+26112u+off);
            }
            #pragma unroll
            for (int mt=0;mt<4;mt++){
                u32 r0,r1,r2,r3,q0,q1,q2,q3;
                u32 off = (u32)((ks+lr)*272 + (wm+mt*16+lc8)*2);
                ldsm4t(r0,r1,r2,r3, sA+off);
                ldsm4t(q0,q1,q2,q3, sA+8704u+off);
                u32 ah[4]={r0,r2,r1,r3}, al[4]={q0,q2,q1,q3};
                #pragma unroll
                for (int nt=0;nt<4;nt++){
                    float* cc = acc[mt*4+nt];
                    mmabf(cc, ah, bh[nt]); mmabf(cc, ah, bl[nt]); mmabf(cc, al, bh[nt]);
                }
            }
        }
        __syncthreads();
    }
    // stage scores in smE [128][132]
    #pragma unroll
    for (int mt=0;mt<4;mt++)
        #pragma unroll
        for (int nt=0;nt<4;nt++){
            float* cc = acc[mt*4+nt];
            int n = wn + nt*8 + (lane&3)*2;
            #pragma unroll
            for (int hlf=0;hlf<2;hlf++){
                int m = wm + mt*16 + (lane>>2) + hlf*8;
                smE[m*132+n] = cc[hlf*2]; smE[m*132+n+1] = cc[hlf*2+1];
            }
        }
    __syncthreads();
    int row = tid>>1, c0 = (tid&1)*64;
    float* rp = smE + row*132 + c0;
    float mx = -INFINITY;
    for (int j=0;j<64;j++) mx = fmaxf(mx, rp[j]);
    mx = fmaxf(mx, __shfl_xor_sync(0xffffffffu, mx, 1));
    float sum = 0.f;
    for (int j=0;j<64;j++){ float e = expf(rp[j]-mx); rp[j] = e; sum += e; }
    sum += __shfl_xor_sync(0xffffffffu, sum, 1);
    float inv = 1.f/sum;
    if (WRITE_M){
        long base = ((long)(b*128+h)*128 + row)*128 + c0;
        for (int j=0;j<64;j+=2) w2(Mh, Ml, base+j, rp[j]*inv, rp[j+1]*inv);
    } else {
        for (int j=0;j<64;j++) rp[j] *= inv;
        __syncthreads();
        if (tid < 128){
            float t = 0.f;
            for (int i=0;i<128;i++) t += smE[i*132+tid];
            mOut[(long)b*HWs + h*128 + tid] = (t>0.1f)?0.f:1.f;
        }
    }
}

// ---- HMMA attend: out[c,i] = sum_j M[i,j] v3[c,j], per (b,h), CTA=128c x 128i ----
// stage: Ah 0, Al 10240, Bh 20480, Bl 30720; stage=40960, dyn=81920
__global__ void __launch_bounds__(256,1) attend_mma(
    const __nv_bfloat16* __restrict__ Mh, const __nv_bfloat16* __restrict__ Ml,
    const __nv_bfloat16* __restrict__ Vh, const __nv_bfloat16* __restrict__ Vl,
    __nv_bfloat16* __restrict__ Oh, __nv_bfloat16* __restrict__ Ol)
{
    extern __shared__ __align__(16) char smem[];
    u32 sm = smem_u32(smem);
    int tid=threadIdx.x, lane=tid&31, wid=tid>>5;
    int c0 = blockIdx.x*128, bh = blockIdx.y, b = bh>>7, h = bh&127;
    int wm=(wid&1)*64, wn=(wid>>1)*32;
    int lr=lane&15, lc8=(lane>>4)*8;
    int tile=lane>>3, lrow=lane&7;
    float acc[16][4];
    #pragma unroll
    for (int i=0;i<16;i++){ acc[i][0]=0;acc[i][1]=0;acc[i][2]=0;acc[i][3]=0; }
    for (int c=0;c<=4;c++){
        if (c<4){
            u32 st = sm + (u32)(c&1)*40960u;
            int kb = c*32;
            #pragma unroll
            for (int j=0;j<2;j++){
                int o = tid + 256*j, r = o>>2, cb = o&3;
                u32 d = st + (u32)(r*80 + cb*16);
                size_t s = ((size_t)(b*256 + c0 + r))*HWs + h*128 + kb + cb*8;
                cpa(d, Vh+s); cpa(d+10240u, Vl+s);
                size_t s2 = (((size_t)(b*128+h)*128 + r))*128 + kb + cb*8;
                cpa(d+20480u, Mh+s2); cpa(d+30720u, Ml+s2);
            }
            cpcommit();
        }
        if (c==0) continue;
        if (c<4) cpwait1(); else cpwait0();
        __syncthreads();
        u32 sA = sm + (u32)((c-1)&1)*40960u;
        #pragma unroll
        for (int ks=0;ks<32;ks+=16){
            u32 bh_[4][2], bl_[4][2];
            #pragma unroll
            for (int pr=0;pr<2;pr++){
                u32 off = (u32)(((wn+pr*16+(tile>>1)*8+lrow)*40 + ks + (tile&1)*8)*2);
                u32 r0,r1,r2,r3;
                ldsm4(r0,r1,r2,r3, sA+20480u+off);
                bh_[pr*2][0]=r0; bh_[pr*2][1]=r1; bh_[pr*2+1][0]=r2; bh_[pr*2+1][1]=r3;
                ldsm4(r0,r1,r2,r3, sA+30720u+off);
                bl_[pr*2][0]=r0; bl_[pr*2][1]=r1; bl_[pr*2+1][0]=r2; bl_[pr*2+1][1]=r3;
            }
            #pragma unroll
            for (int mt=0;mt<4;mt++){
                u32 ah[4], al[4];
                u32 off = (u32)((wm+mt*16+lr)*80 + (ks+lc8)*2);
                ldsm4(ah[0],ah[1],ah[2],ah[3], sA+off);
                ldsm4(al[0],al[1],al[2],al[3], sA+10240u+off);
                #pragma unroll
                for (int nt=0;nt<4;nt++){
                    float* cc = acc[mt*4+nt];
                    mmabf(cc, ah, bh_[nt]); mmabf(cc, ah, bl_[nt]); mmabf(cc, al, bh_[nt]);
                }
            }
        }
        __syncthreads();
    }
    #pragma unroll
    for (int mt=0;mt<4;mt++)
        #pragma unroll
        for (int nt=0;nt<4;nt++){
            float* cc = acc[mt*4+nt];
            int n = wn + nt*8 + (lane&3)*2;
            #pragma unroll
            for (int hlf=0;hlf<2;hlf++){
                int m = wm + mt*16 + (lane>>2) + hlf*8;
                long idx = ((long)(b*256 + c0 + m))*HWs + h*128 + n;
                w2(Oh, Ol, idx, cc[hlf*2], cc[hlf*2+1]);
            }
        }
}

// ---- morphology ----
__global__ void morph_k(const float* __restrict__ src, float* __restrict__ dst,
                        int Wd, int Hd, int r, int erode, int total){
    int idx = blockIdx.x*256 + threadIdx.x;
    if (idx >= total) return;
    int plane=Wd*Hd, b=idx/plane, rem=idx-b*plane, h=rem/Wd, w=rem-h*Wd;
    const float* p = src + (long)b*plane;
    float res = erode ? 1.f : 0.f;
    int r2=r*r;
    for (int dy=-r;dy<=r;dy++) for (int dx=-r;dx<=r;dx++){
        if (dy*dy+dx*dx > r2) continue;
        int hh=h+dy, ww=w+dx;
        float v = (hh>=0&&hh<Hd&&ww>=0&&ww<Wd) ? p[hh*Wd+ww] : 0.f;
        if (erode){ if (v<0.5f) res=0.f; } else { if (v>0.5f) res=1.f; }
    }
    dst[(long)b*plane+rem]=res;
}
__global__ void pad_k(const float* __restrict__ src, float* __restrict__ dst, int total){
    int idx = blockIdx.x*256 + threadIdx.x;
    if (idx >= total) return;
    int b=idx/PHW, rem=idx-b*PHW, h=rem/PW, w=rem-h*PW;
    float v=0.f;
    if (h>=3 && h<3+HH && w>=3 && w<3+WW) v = src[(long)b*HWs + (h-3)*WW + (w-3)];
    dst[idx]=v;
}
__global__ void final_k(const float* __restrict__ src, float* __restrict__ dst){
    int idx = blockIdx.x*256 + threadIdx.x;
    int b=idx>>14, rem=idx&(HWs-1), h=rem>>7, w=rem&127;
    dst[idx] = 1.f - src[(long)b*PHW + (h+3)*PW + (w+3)];
}

extern "C" void kernel_launch(void* const* d_in, const int* in_sizes, int n_in,
                              void* d_out, int out_size) {
    const float* x_p=(const float*)d_in[0];  const float* x_c=(const float*)d_in[1];
    const float* pa_w1=(const float*)d_in[2];const float* pa_b1=(const float*)d_in[3];
    const float* pa_w2=(const float*)d_in[4];const float* pa_b2=(const float*)d_in[5];
    const float* pa_wc=(const float*)d_in[6];const float* pa_bc=(const float*)d_in[7];
    const float* ca_aw1=(const float*)d_in[8];const float* ca_ab1=(const float*)d_in[9];
    const float* ca_aw2=(const float*)d_in[10];const float* ca_ab2=(const float*)d_in[11];
    const float* ca_mw1=(const float*)d_in[12];const float* ca_mb1=(const float*)d_in[13];
    const float* ca_mw2=(const float*)d_in[14];const float* ca_mb2=(const float*)d_in[15];
    const float* b1_w=(const float*)d_in[16];const float* b1_b=(const float*)d_in[17];
    const float* b2_w=(const float*)d_in[18];const float* b2_b=(const float*)d_in[19];
    const float* b3_w=(const float*)d_in[20];const float* b3_b=(const float*)d_in[21];
    const float* fus_w=(const float*)d_in[22];const float* fus_b=(const float*)d_in[23];
    float* out=(float*)d_out;

    float *buf0,*buf1,*gate,*amean,*amax,*mA,*mB,*pA,*pB,*vfin;
    __nv_bfloat16 *ih,*il,*wh,*wl,*Mh,*Ml;
    cudaGetSymbolAddress((void**)&buf0,g_buf0); cudaGetSymbolAddress((void**)&buf1,g_buf1);
    cudaGetSymbolAddress((void**)&gate,g_gate);
    cudaGetSymbolAddress((void**)&amean,g_amean); cudaGetSymbolAddress((void**)&amax,g_amax);
    cudaGetSymbolAddress((void**)&mA,g_mA); cudaGetSymbolAddress((void**)&mB,g_mB);
    cudaGetSymbolAddress((void**)&pA,g_pA); cudaGetSymbolAddress((void**)&pB,g_pB);
    cudaGetSymbolAddress((void**)&vfin,g_vfinal);
    cudaGetSymbolAddress((void**)&ih,g_imgh); cudaGetSymbolAddress((void**)&il,g_imgl);
    cudaGetSymbolAddress((void**)&wh,g_wih);  cudaGetSymbolAddress((void**)&wl,g_wil);
    cudaGetSymbolAddress((void**)&Mh,g_Mh);   cudaGetSymbolAddress((void**)&Ml,g_Ml);
    cudaFuncSetAttribute(gemm_mma, cudaFuncAttributeMaxDynamicSharedMemorySize, GSM);
    cudaFuncSetAttribute(score_mma<1>, cudaFuncAttributeMaxDynamicSharedMemorySize, 69632);
    cudaFuncSetAttribute(score_mma<0>, cudaFuncAttributeMaxDynamicSharedMemorySize, 69632);
    cudaFuncSetAttribute(attend_mma, cudaFuncAttributeMaxDynamicSharedMemorySize, 81920);

    const long W1=0,W2=65536,WC=131072,B1=262144,B2=327680,B3=393216,FU=458752,B1G=589824,B2G=1114112;

    pool_k<<<NBCHW/256,256>>>(x_p, buf0, buf1);
    reduce_k<<<BB*CC,256>>>(x_c, amean, amax);
    cagate_k<<<BB,256>>>(amean,amax,ca_aw1,ca_ab1,ca_aw2,ca_ab2,ca_mw1,ca_mb1,ca_mw2,ca_mb2,gate);

    cvtw_k<<<256,256>>>(pa_w1,256,256,0, wh+W1, wl+W1);
    cvtw_k<<<256,256>>>(pa_w2,256,256,0, wh+W2, wl+W2);
    cvtw_k<<<512,256>>>(pa_wc,512,512,0, wh+WC, wl+WC);
    cvtw_k<<<256,256>>>(b1_w,256,256,0, wh+B1, wl+B1);
    cvtw_k<<<256,256>>>(b2_w,256,256,0, wh+B2, wl+B2);
    cvtw_k<<<256,256>>>(b3_w,256,256,0, wh+B3, wl+B3);
    cvtw_k<<<512,256>>>(fus_w,513,512,0, wh+FU, wl+FU);
    cvtw_k<<<2048,256>>>(b1_w,256,256,gate, wh+B1G, wl+B1G);
    cvtw_k<<<2048,256>>>(b2_w,256,256,gate, wh+B2G, wl+B2G);

    dim3 gg(128, BB);
    // PALayer avg path: y1 -> h -> z1 (img I4)
    cvt_k<<<NBCHW/1024,256>>>(buf0, ih+IK(3), il+IK(3));
    gemm_mma<<<gg,256,GSM>>>(wh+W1,wl+W1,0,256, ih+IK(3),il+IK(3),0,0, 0, ih+IK(9),il+IK(9), pa_b1,1, 0,0);
    gemm_mma<<<gg,256,GSM>>>(wh+W2,wl+W2,0,256, ih+IK(9),il+IK(9),0,0, 0, ih+IK(4),il+IK(4), pa_b2,2, buf0,0);
    // max path: y2 -> h -> z2 (img I5)
    cvt_k<<<NBCHW/1024,256>>>(buf1, ih+IK(3), il+IK(3));
    gemm_mma<<<gg,256,GSM>>>(wh+W1,wl+W1,0,256, ih+IK(3),il+IK(3),0,0, 0, ih+IK(9),il+IK(9), pa_b1,1, 0,0);
    gemm_mma<<<gg,256,GSM>>>(wh+W2,wl+W2,0,256, ih+IK(9),il+IK(9),0,0, 0, ih+IK(5),il+IK(5), pa_b2,2, buf1,0);
    // buffer_p (img I0)
    gemm_mma<<<gg,256,GSM>>>(wh+WC,wl+WC,0,512, ih+IK(4),il+IK(4), ih+IK(5),il+IK(5), 0, ih+IK(0),il+IK(0), pa_bc,3, x_p,0);
    // x_c img I1
    cvt_k<<<NBCHW/1024,256>>>(x_c, ih+IK(1), il+IK(1));
    // Q1->I4, S1->I5, Q2->I6, S2->I7, v3->I8 (all bf16 images)
    gemm_mma<<<gg,256,GSM>>>(wh+B1,wl+B1,0,256,       ih+IK(0),il+IK(0),0,0, 0, ih+IK(4),il+IK(4), b1_b,0, 0,0);
    gemm_mma<<<gg,256,GSM>>>(wh+B2G,wl+B2G,65536,256, ih+IK(1),il+IK(1),0,0, 0, ih+IK(5),il+IK(5), b2_b,0, 0,0);
    gemm_mma<<<gg,256,GSM>>>(wh+B1G,wl+B1G,65536,256, ih+IK(1),il+IK(1),0,0, 0, ih+IK(6),il+IK(6), b1_b,0, 0,0);
    gemm_mma<<<gg,256,GSM>>>(wh+B2,wl+B2,0,256,       ih+IK(0),il+IK(0),0,0, 0, ih+IK(7),il+IK(7), b2_b,0, 0,0);
    gemm_mma<<<gg,256,GSM>>>(wh+B3,wl+B3,0,256,       ih+IK(1),il+IK(1),0,0, 0, ih+IK(8),il+IK(8), b3_b,0, 0,0);
    cvt_k<<<NBCHW/1024,256>>>(x_p, ih+IK(2), il+IK(2));
    // attention (HMMA)
    dim3 gs(HH, BB);
    score_mma<1><<<gs,256,69632>>>(ih+IK(4),il+IK(4), ih+IK(5),il+IK(5), Mh, Ml, 0);
    score_mma<0><<<gs,256,69632>>>(ih+IK(6),il+IK(6), ih+IK(7),il+IK(7), 0, 0, mA);
    // morphology
    int n128 = BB*HWs;
    morph_k<<<n128/256,256>>>(mA,mB,128,128,2,1,n128);
    morph_k<<<n128/256,256>>>(mB,mA,128,128,2,0,n128);
    morph_k<<<n128/256,256>>>(mA,mB,128,128,1,0,n128);
    morph_k<<<n128/256,256>>>(mB,mA,128,128,1,1,n128);
    int np=BB*PHW, gp=(np+255)/256;
    pad_k<<<gp,256>>>(mA,pA,np);
    morph_k<<<gp,256>>>(pA,pB,PW,PW,3,0,np);
    morph_k<<<gp,256>>>(pB,pA,PW,PW,3,1,np);
    final_k<<<n128/256,256>>>(pA,vfin);
    // attend (HMMA) -> img I3; fusion
    dim3 ga(2, BB*HH);
    attend_mma<<<ga,256,81920>>>(Mh, Ml, ih+IK(8), il+IK(8), ih+IK(3), il+IK(3));
    gemm_mma<<<gg,256,GSM>>>(wh+FU,wl+FU,0,512, ih+IK(3),il+IK(3), ih+IK(2),il+IK(2), out,0,0, fus_b,4, vfin,fus_w);
}

// round 9
// speedup vs baseline: 2.2726x; 1.2000x over previous
#include <cuda_runtime.h>
#include <cuda_fp16.h>
#include <math.h>

#define BB 8
#define CC 256
#define HH 128
#define WW 128
#define HWs 16384
#define NBCHW (BB*CC*HWs)
#define PW 134
#define PHW (PW*PW)
typedef unsigned long long ull;
typedef unsigned int u32;

__device__ float g_buf0[NBCHW];
__device__ float g_buf1[NBCHW];
__device__ float g_gate[BB*CC];
__device__ float g_amean[BB*CC];
__device__ float g_amax[BB*CC];
__device__ float g_mA[BB*HWs];
__device__ float g_mB[BB*HWs];
__device__ float g_pA[BB*PHW];
__device__ float g_pB[BB*PHW];
__device__ float g_vfinal[BB*HWs];
__device__ __align__(16) __half g_imgh[335544320];
__device__ __align__(16) __half g_imgl[335544320];
__device__ __align__(16) __half g_Mh[16777216];
__device__ __align__(16) __half g_wih[1638400];
__device__ __align__(16) __half g_wil[1638400];
#define IK(k) ((long)(k)*33554432L)

__device__ __forceinline__ float sigmoidf_(float x){ return 1.0f/(1.0f+expf(-x)); }
__device__ __forceinline__ u32 smem_u32(const void* p){
    u32 a; asm("{ .reg .u64 t; cvta.to.shared.u64 t, %1; cvt.u32.u64 %0, t; }" : "=r"(a) : "l"(p)); return a; }
__device__ __forceinline__ u32 pack2(float a, float b){
    __half2 t = __floats2half2_rn(a, b); return *(u32*)&t; }
__device__ __forceinline__ void w2(__half* oh, __half* ol, long idx, float a, float b){
    u32 h = pack2(a,b); __half2 hv = *(__half2*)&h;
    ((u32*)oh)[idx>>1] = h;
    ((u32*)ol)[idx>>1] = pack2(a-__half2float(hv.x), b-__half2float(hv.y));
}
__device__ __forceinline__ void ldsm4(u32& r0,u32& r1,u32& r2,u32& r3,u32 a){
    asm volatile("ldmatrix.sync.aligned.m8n8.x4.shared.b16 {%0,%1,%2,%3}, [%4];"
        :"=r"(r0),"=r"(r1),"=r"(r2),"=r"(r3):"r"(a)); }
__device__ __forceinline__ void ldsm4t(u32& r0,u32& r1,u32& r2,u32& r3,u32 a){
    asm volatile("ldmatrix.sync.aligned.m8n8.x4.trans.shared.b16 {%0,%1,%2,%3}, [%4];"
        :"=r"(r0),"=r"(r1),"=r"(r2),"=r"(r3):"r"(a)); }
__device__ __forceinline__ void mmah(float* c, const u32* a, const u32* b){
    asm volatile("mma.sync.aligned.m16n8k16.row.col.f32.f16.f16.f32 "
        "{%0,%1,%2,%3},{%4,%5,%6,%7},{%8,%9},{%0,%1,%2,%3};"
        :"+f"(c[0]),"+f"(c[1]),"+f"(c[2]),"+f"(c[3])
        :"r"(a[0]),"r"(a[1]),"r"(a[2]),"r"(a[3]),"r"(b[0]),"r"(b[1])); }
__device__ __forceinline__ void cpa(u32 d, const void* s){
    asm volatile("cp.async.cg.shared.global [%0], [%1], 16;"::"r"(d),"l"(s)); }
__device__ __forceinline__ void cpcommit(){ asm volatile("cp.async.commit_group;":::"memory"); }
__device__ __forceinline__ void cpwait1(){ asm volatile("cp.async.wait_group 1;":::"memory"); }
__device__ __forceinline__ void cpwait0(){ asm volatile("cp.async.wait_group 0;":::"memory"); }

// ---- pool / reduce / gate ----
__global__ void pool_k(const float* __restrict__ xp, float* __restrict__ y1, float* __restrict__ y2){
    long idx = (long)blockIdx.x*256 + threadIdx.x;
    if (idx >= (long)NBCHW) return;
    int w = (int)(idx & 127), h = (int)((idx>>7)&127);
    long base = idx - (long)(h*WW+w);
    float s=0.f, mx=-INFINITY;
    #pragma unroll
    for (int dy=-1;dy<=1;dy++){ int hh=h+dy; if(hh<0||hh>=HH) continue;
        #pragma unroll
        for (int dx=-1;dx<=1;dx++){ int ww=w+dx; if(ww<0||ww>=WW) continue;
            float v = xp[base+hh*WW+ww]; s+=v; mx=fmaxf(mx,v); } }
    y1[idx]=s*(1.f/9.f); y2[idx]=mx;
}
__global__ void reduce_k(const float* __restrict__ x, float* __restrict__ mean, float* __restrict__ mxo){
    __shared__ float ss[256], sm[256];
    int bc=blockIdx.x, t=threadIdx.x;
    const float* p = x + (long)bc*HWs;
    float s=0.f, m=-INFINITY;
    for (int i=t;i<HWs;i+=256){ float v=p[i]; s+=v; m=fmaxf(m,v); }
    ss[t]=s; sm[t]=m; __syncthreads();
    for (int o=128;o>0;o>>=1){ if (t<o){ ss[t]+=ss[t+o]; sm[t]=fmaxf(sm[t],sm[t+o]); } __syncthreads(); }
    if (t==0){ mean[bc]=ss[0]*(1.f/(float)HWs); mxo[bc]=sm[0]; }
}
__global__ void cagate_k(const float* __restrict__ amean, const float* __restrict__ amax,
    const float* __restrict__ aw1, const float* __restrict__ ab1,
    const float* __restrict__ aw2, const float* __restrict__ ab2,
    const float* __restrict__ mw1, const float* __restrict__ mb1,
    const float* __restrict__ mw2, const float* __restrict__ mb2, float* __restrict__ gate){
    __shared__ float ha[16], hm[16];
    int b=blockIdx.x, t=threadIdx.x;
    if (t<16){ float s=ab1[t]; for (int i=0;i<CC;i++) s+=aw1[t*CC+i]*amean[b*CC+i]; ha[t]=fmaxf(s,0.f); }
    else if (t<32){ int u=t-16; float s=mb1[u]; for (int i=0;i<CC;i++) s+=mw1[u*CC+i]*amax[b*CC+i]; hm[u]=fmaxf(s,0.f); }
    __syncthreads();
    float g = ab2[t]+mb2[t];
    #pragma unroll
    for (int k=0;k<16;k++) g += aw2[t*16+k]*ha[k] + mw2[t*16+k]*hm[k];
    gate[b*CC+t] = sigmoidf_(g);
}
__global__ void cvt_k(const float* __restrict__ src, __half* __restrict__ oh, __half* __restrict__ ol){
    long i4 = ((long)blockIdx.x*256 + threadIdx.x)*4;
    float4 v = *(const float4*)(src + i4);
    w2(oh, ol, i4,   v.x, v.y);
    w2(oh, ol, i4+2, v.z, v.w);
}
__global__ void cvtw_k(const float* __restrict__ W, int RS, int K, const float* __restrict__ gate,
                       __half* __restrict__ oh, __half* __restrict__ ol){
    int idx = blockIdx.x*256 + threadIdx.x;
    int b = idx/(256*K); int rem = idx - b*256*K; int m = rem/K, k = rem - m*K;
    float v = W[(long)m*RS + k];
    if (gate) v *= gate[b*256 + k];
    __half h = __float2half_rn(v);
    oh[idx] = h; ol[idx] = __float2half_rn(v - __half2float(h));
}

// ---- HMMA GEMM (fp16 2-pass): Y = (Wh+Wl)·Bh, CTA = 256m x 128n ----
// stage: Ah 0 (20480), Al 20480, Bh 40960 (8704); stage=49664
#define STG 49664u
#define GSM (2*49664)
__global__ void __launch_bounds__(256,1) gemm_mma(
    const __half* __restrict__ Wh, const __half* __restrict__ Wl, long wBS, int K,
    const __half* __restrict__ X0h, const __half* __restrict__ X1h,
    float* __restrict__ Yf, __half* __restrict__ Yh, __half* __restrict__ Yl,
    const float* __restrict__ bias, int epi, const float* __restrict__ E0, const float* __restrict__ E1)
{
    extern __shared__ __align__(16) char smem[];
    u32 sm = smem_u32(smem);
    int tid=threadIdx.x, lane=tid&31, wid=tid>>5;
    int n0 = blockIdx.x*128, b = blockIdx.y;
    int wm = (wid&1)*128, wn = (wid>>1)*32;
    int lr = lane&15, lc8 = (lane>>4)*8;
    const __half* WhB = Wh + wBS*b;
    const __half* WlB = Wl + wBS*b;
    int NC = K>>5;
    float acc[32][4];
    #pragma unroll
    for (int i=0;i<32;i++){ acc[i][0]=0;acc[i][1]=0;acc[i][2]=0;acc[i][3]=0; }
    for (int c=0; c<=NC; c++){
        if (c<NC){
            u32 st = sm + (u32)(c&1)*STG;
            int kb = c*32;
            #pragma unroll
            for (int j=0;j<4;j++){
                int o=tid+256*j, r=o>>2, cb=o&3;
                u32 d = st + (u32)(r*80+cb*16);
                cpa(d,          WhB + (size_t)r*K + kb + cb*8);
                cpa(d + 20480u, WlB + (size_t)r*K + kb + cb*8);
            }
            const __half *xh=X0h; int kk=kb;
            if (kk>=256){ xh=X1h; kk-=256; }
            #pragma unroll
            for (int j=0;j<2;j++){
                int o=tid+256*j, r=o>>4, cb=o&15;
                size_t s = ((size_t)b*256 + kk + r)*HWs + n0 + cb*8;
                cpa(st + 40960u + (u32)(r*272+cb*16), xh + s);
            }
            cpcommit();
        }
        if (c==0) continue;
        if (c<NC) cpwait1(); else cpwait0();
        __syncthreads();
        u32 sA = sm + (u32)((c-1)&1)*STG;
        #pragma unroll
        for (int ks=0; ks<32; ks+=16){
            u32 bh[4][2];
            #pragma unroll
            for (int pr=0; pr<2; pr++){
                u32 off = (u32)((ks+lr)*272 + (wn+pr*16+lc8)*2);
                ldsm4t(bh[pr*2][0],bh[pr*2][1],bh[pr*2+1][0],bh[pr*2+1][1], sA+40960u+off);
            }
            #pragma unroll
            for (int mt=0; mt<8; mt++){
                u32 ah[4], al[4];
                u32 off = (u32)((wm+mt*16+lr)*80 + (ks+lc8)*2);
                ldsm4(ah[0],ah[1],ah[2],ah[3], sA+off);
                ldsm4(al[0],al[1],al[2],al[3], sA+20480u+off);
                #pragma unroll
                for (int nt=0; nt<4; nt++){
                    float* cc = acc[mt*4+nt];
                    mmah(cc, ah, bh[nt]); mmah(cc, al, bh[nt]);
                }
            }
        }
        __syncthreads();
    }
    #pragma unroll
    for (int mt=0; mt<8; mt++){
        #pragma unroll
        for (int nt=0; nt<4; nt++){
            float* cc = acc[mt*4+nt];
            int n = n0 + wn + nt*8 + (lane&3)*2;
            #pragma unroll
            for (int hlf=0; hlf<2; hlf++){
                int m = wm + mt*16 + (lane>>2) + hlf*8;
                float v0 = cc[hlf*2] + bias[m], v1 = cc[hlf*2+1] + bias[m];
                long yb = ((long)b*CC + m)*HWs + n;
                if (epi==1){ v0=fmaxf(v0,0.f); v1=fmaxf(v1,0.f); }
                else if (epi==2){ v0+=E0[yb]; v1+=E0[yb+1]; }
                else if (epi==3){ v0=sigmoidf_(v0)*E0[yb]; v1=sigmoidf_(v1)*E0[yb+1]; }
                else if (epi==4){ float wl=E1[(long)m*513+512]; long eb=(long)b*HWs+n;
                    v0+=wl*E0[eb]; v1+=wl*E0[eb+1]; }
                if (Yf){ float2 st={v0,v1}; *(float2*)(Yf+yb)=st; }
                else   w2(Yh, Yl, yb, v0, v1);
            }
        }
    }
}

// ---- HMMA score (fp16 2-pass): A=Q split, B=S hi; softmax over j ----
// stage: Qh 0, Ql 8704, Sh 17408; stage=26112 (x2=52224); epilogue needs 67584 -> dyn=67584
template<int WRITE_M>
__global__ void __launch_bounds__(256,1) score_mma(
    const __half* __restrict__ Qh, const __half* __restrict__ Ql,
    const __half* __restrict__ Sh,
    __half* __restrict__ Mh, float* __restrict__ mOut)
{
    extern __shared__ __align__(16) char smem[];
    u32 sm = smem_u32(smem);
    float* smE = (float*)smem;
    int tid=threadIdx.x, lane=tid&31, wid=tid>>5;
    int h = blockIdx.x, b = blockIdx.y;
    int wm=(wid&1)*64, wn=(wid>>1)*32;
    int lr=lane&15, lc8=(lane>>4)*8;
    float acc[16][4];
    #pragma unroll
    for (int i=0;i<16;i++){ acc[i][0]=0;acc[i][1]=0;acc[i][2]=0;acc[i][3]=0; }
    for (int c=0;c<=8;c++){
        if (c<8){
            u32 st = sm + (u32)(c&1)*26112u;
            int kb = c*32;
            #pragma unroll
            for (int j=0;j<2;j++){
                int o = tid + 256*j, r = o>>4, cb = o&15;
                size_t s = ((size_t)(b*256 + kb + r))*HWs + h*128 + cb*8;
                u32 d = st + (u32)(r*272 + cb*16);
                cpa(d, Qh+s); cpa(d+8704u, Ql+s); cpa(d+17408u, Sh+s);
            }
            cpcommit();
        }
        if (c==0) continue;
        if (c<8) cpwait1(); else cpwait0();
        __syncthreads();
        u32 sA = sm + (u32)((c-1)&1)*26112u;
        #pragma unroll
        for (int ks=0;ks<32;ks+=16){
            u32 bh[4][2];
            #pragma unroll
            for (int pr=0;pr<2;pr++){
                u32 off = (u32)((ks+lr)*272 + (wn+pr*16+lc8)*2);
                ldsm4t(bh[pr*2][0],bh[pr*2][1],bh[pr*2+1][0],bh[pr*2+1][1], sA+17408u+off);
            }
            #pragma unroll
            for (int mt=0;mt<4;mt++){
                u32 r0,r1,r2,r3,q0,q1,q2,q3;
                u32 off = (u32)((ks+lr)*272 + (wm+mt*16+lc8)*2);
                ldsm4t(r0,r1,r2,r3, sA+off);
                ldsm4t(q0,q1,q2,q3, sA+8704u+off);
                u32 ah[4]={r0,r2,r1,r3}, al[4]={q0,q2,q1,q3};
                #pragma unroll
                for (int nt=0;nt<4;nt++){
                    float* cc = acc[mt*4+nt];
                    mmah(cc, ah, bh[nt]); mmah(cc, al, bh[nt]);
                }
            }
        }
        __syncthreads();
    }
    #pragma unroll
    for (int mt=0;mt<4;mt++)
        #pragma unroll
        for (int nt=0;nt<4;nt++){
            float* cc = acc[mt*4+nt];
            int n = wn + nt*8 + (lane&3)*2;
            #pragma unroll
            for (int hlf=0;hlf<2;hlf++){
                int m = wm + mt*16 + (lane>>2) + hlf*8;
                smE[m*132+n] = cc[hlf*2]; smE[m*132+n+1] = cc[hlf*2+1];
            }
        }
    __syncthreads();
    int row = tid>>1, c0 = (tid&1)*64;
    float* rp = smE + row*132 + c0;
    float mx = -INFINITY;
    for (int j=0;j<64;j++) mx = fmaxf(mx, rp[j]);
    mx = fmaxf(mx, __shfl_xor_sync(0xffffffffu, mx, 1));
    float sum = 0.f;
    for (int j=0;j<64;j++){ float e = expf(rp[j]-mx); rp[j] = e; sum += e; }
    sum += __shfl_xor_sync(0xffffffffu, sum, 1);
    float inv = 1.f/sum;
    if (WRITE_M){
        long base = ((long)(b*128+h)*128 + row)*128 + c0;
        for (int j=0;j<64;j+=2)
            ((u32*)Mh)[(base+j)>>1] = pack2(rp[j]*inv, rp[j+1]*inv);
    } else {
        for (int j=0;j<64;j++) rp[j] *= inv;
        __syncthreads();
        if (tid < 128){
            float t = 0.f;
            for (int i=0;i<128;i++) t += smE[i*132+tid];
            mOut[(long)b*HWs + h*128 + tid] = (t>0.1f)?0.f:1.f;
        }
    }
}

// ---- HMMA attend (fp16 2-pass): A=v3 split, B=M hi ----
// stage: Vh 0, Vl 10240, Mh 20480; stage=30720, dyn=61440
__global__ void __launch_bounds__(256,1) attend_mma(
    const __half* __restrict__ Mh,
    const __half* __restrict__ Vh, const __half* __restrict__ Vl,
    __half* __restrict__ Oh, __half* __restrict__ Ol)
{
    extern __shared__ __align__(16) char smem[];
    u32 sm = smem_u32(smem);
    int tid=threadIdx.x, lane=tid&31, wid=tid>>5;
    int c0 = blockIdx.x*128, bh = blockIdx.y, b = bh>>7, h = bh&127;
    int wm=(wid&1)*64, wn=(wid>>1)*32;
    int lr=lane&15, lc8=(lane>>4)*8;
    int tile=lane>>3, lrow=lane&7;
    float acc[16][4];
    #pragma unroll
    for (int i=0;i<16;i++){ acc[i][0]=0;acc[i][1]=0;acc[i][2]=0;acc[i][3]=0; }
    for (int c=0;c<=4;c++){
        if (c<4){
            u32 st = sm + (u32)(c&1)*30720u;
            int kb = c*32;
            #pragma unroll
            for (int j=0;j<2;j++){
                int o = tid + 256*j, r = o>>2, cb = o&3;
                u32 d = st + (u32)(r*80 + cb*16);
                size_t s = ((size_t)(b*256 + c0 + r))*HWs + h*128 + kb + cb*8;
                cpa(d, Vh+s); cpa(d+10240u, Vl+s);
                size_t s2 = (((size_t)(b*128+h)*128 + r))*128 + kb + cb*8;
                cpa(d+20480u, Mh+s2);
            }
            cpcommit();
        }
        if (c==0) continue;
        if (c<4) cpwait1(); else cpwait0();
        __syncthreads();
        u32 sA = sm + (u32)((c-1)&1)*30720u;
        #pragma unroll
        for (int ks=0;ks<32;ks+=16){
            u32 bh_[4][2];
            #pragma unroll
            for (int pr=0;pr<2;pr++){
                u32 off = (u32)(((wn+pr*16+(tile>>1)*8+lrow)*40 + ks + (tile&1)*8)*2);
                u32 r0,r1,r2,r3;
                ldsm4(r0,r1,r2,r3, sA+20480u+off);
                bh_[pr*2][0]=r0; bh_[pr*2][1]=r1; bh_[pr*2+1][0]=r2; bh_[pr*2+1][1]=r3;
            }
            #pragma unroll
            for (int mt=0;mt<4;mt++){
                u32 ah[4], al[4];
                u32 off = (u32)((wm+mt*16+lr)*80 + (ks+lc8)*2);
                ldsm4(ah[0],ah[1],ah[2],ah[3], sA+off);
                ldsm4(al[0],al[1],al[2],al[3], sA+10240u+off);
                #pragma unroll
                for (int nt=0;nt<4;nt++){
                    float* cc = acc[mt*4+nt];
                    mmah(cc, ah, bh_[nt]); mmah(cc, al, bh_[nt]);
                }
            }
        }
        __syncthreads();
    }
    #pragma unroll
    for (int mt=0;mt<4;mt++)
        #pragma unroll
        for (int nt=0;nt<4;nt++){
            float* cc = acc[mt*4+nt];
            int n = wn + nt*8 + (lane&3)*2;
            #pragma unroll
            for (int hlf=0;hlf<2;hlf++){
                int m = wm + mt*16 + (lane>>2) + hlf*8;
                long idx = ((long)(b*256 + c0 + m))*HWs + h*128 + n;
                w2(Oh, Ol, idx, cc[hlf*2], cc[hlf*2+1]);
            }
        }
}

// ---- morphology ----
__global__ void morph_k(const float* __restrict__ src, float* __restrict__ dst,
                        int Wd, int Hd, int r, int erode, int total){
    int idx = blockIdx.x*256 + threadIdx.x;
    if (idx >= total) return;
    int plane=Wd*Hd, b=idx/plane, rem=idx-b*plane, h=rem/Wd, w=rem-h*Wd;
    const float* p = src + (long)b*plane;
    float res = erode ? 1.f : 0.f;
    int r2=r*r;
    for (int dy=-r;dy<=r;dy++) for (int dx=-r;dx<=r;dx++){
        if (dy*dy+dx*dx > r2) continue;
        int hh=h+dy, ww=w+dx;
        float v = (hh>=0&&hh<Hd&&ww>=0&&ww<Wd) ? p[hh*Wd+ww] : 0.f;
        if (erode){ if (v<0.5f) res=0.f; } else { if (v>0.5f) res=1.f; }
    }
    dst[(long)b*plane+rem]=res;
}
__global__ void pad_k(const float* __restrict__ src, float* __restrict__ dst, int total){
    int idx = blockIdx.x*256 + threadIdx.x;
    if (idx >= total) return;
    int b=idx/PHW, rem=idx-b*PHW, h=rem/PW, w=rem-h*PW;
    float v=0.f;
    if (h>=3 && h<3+HH && w>=3 && w<3+WW) v = src[(long)b*HWs + (h-3)*WW + (w-3)];
    dst[idx]=v;
}
__global__ void final_k(const float* __restrict__ src, float* __restrict__ dst){
    int idx = blockIdx.x*256 + threadIdx.x;
    int b=idx>>14, rem=idx&(HWs-1), h=rem>>7, w=rem&127;
    dst[idx] = 1.f - src[(long)b*PHW + (h+3)*PW + (w+3)];
}

extern "C" void kernel_launch(void* const* d_in, const int* in_sizes, int n_in,
                              void* d_out, int out_size) {
    const float* x_p=(const float*)d_in[0];  const float* x_c=(const float*)d_in[1];
    const float* pa_w1=(const float*)d_in[2];const float* pa_b1=(const float*)d_in[3];
    const float* pa_w2=(const float*)d_in[4];const float* pa_b2=(const float*)d_in[5];
    const float* pa_wc=(const float*)d_in[6];const float* pa_bc=(const float*)d_in[7];
    const float* ca_aw1=(const float*)d_in[8];const float* ca_ab1=(const float*)d_in[9];
    const float* ca_aw2=(const float*)d_in[10];const float* ca_ab2=(const float*)d_in[11];
    const float* ca_mw1=(const float*)d_in[12];const float* ca_mb1=(const float*)d_in[13];
    const float* ca_mw2=(const float*)d_in[14];const float* ca_mb2=(const float*)d_in[15];
    const float* b1_w=(const float*)d_in[16];const float* b1_b=(const float*)d_in[17];
    const float* b2_w=(const float*)d_in[18];const float* b2_b=(const float*)d_in[19];
    const float* b3_w=(const float*)d_in[20];const float* b3_b=(const float*)d_in[21];
    const float* fus_w=(const float*)d_in[22];const float* fus_b=(const float*)d_in[23];
    float* out=(float*)d_out;

    float *buf0,*buf1,*gate,*amean,*amax,*mA,*mB,*pA,*pB,*vfin;
    __half *ih,*il,*wh,*wl,*Mh;
    cudaGetSymbolAddress((void**)&buf0,g_buf0); cudaGetSymbolAddress((void**)&buf1,g_buf1);
    cudaGetSymbolAddress((void**)&gate,g_gate);
    cudaGetSymbolAddress((void**)&amean,g_amean); cudaGetSymbolAddress((void**)&amax,g_amax);
    cudaGetSymbolAddress((void**)&mA,g_mA); cudaGetSymbolAddress((void**)&mB,g_mB);
    cudaGetSymbolAddress((void**)&pA,g_pA); cudaGetSymbolAddress((void**)&pB,g_pB);
    cudaGetSymbolAddress((void**)&vfin,g_vfinal);
    cudaGetSymbolAddress((void**)&ih,g_imgh); cudaGetSymbolAddress((void**)&il,g_imgl);
    cudaGetSymbolAddress((void**)&wh,g_wih);  cudaGetSymbolAddress((void**)&wl,g_wil);
    cudaGetSymbolAddress((void**)&Mh,g_Mh);
    cudaFuncSetAttribute(gemm_mma, cudaFuncAttributeMaxDynamicSharedMemorySize, GSM);
    cudaFuncSetAttribute(score_mma<1>, cudaFuncAttributeMaxDynamicSharedMemorySize, 67584);
    cudaFuncSetAttribute(score_mma<0>, cudaFuncAttributeMaxDynamicSharedMemorySize, 67584);
    cudaFuncSetAttribute(attend_mma, cudaFuncAttributeMaxDynamicSharedMemorySize, 61440);

    const long W1=0,W2=65536,WC=131072,B1=262144,B2=327680,B3=393216,FU=458752,B1G=589824,B2G=1114112;

    pool_k<<<NBCHW/256,256>>>(x_p, buf0, buf1);
    reduce_k<<<BB*CC,256>>>(x_c, amean, amax);
    cagate_k<<<BB,256>>>(amean,amax,ca_aw1,ca_ab1,ca_aw2,ca_ab2,ca_mw1,ca_mb1,ca_mw2,ca_mb2,gate);

    cvtw_k<<<256,256>>>(pa_w1,256,256,0, wh+W1, wl+W1);
    cvtw_k<<<256,256>>>(pa_w2,256,256,0, wh+W2, wl+W2);
    cvtw_k<<<512,256>>>(pa_wc,512,512,0, wh+WC, wl+WC);
    cvtw_k<<<256,256>>>(b1_w,256,256,0, wh+B1, wl+B1);
    cvtw_k<<<256,256>>>(b2_w,256,256,0, wh+B2, wl+B2);
    cvtw_k<<<256,256>>>(b3_w,256,256,0, wh+B3, wl+B3);
    cvtw_k<<<512,256>>>(fus_w,513,512,0, wh+FU, wl+FU);
    cvtw_k<<<2048,256>>>(b1_w,256,256,gate, wh+B1G, wl+B1G);
    cvtw_k<<<2048,256>>>(b2_w,256,256,gate, wh+B2G, wl+B2G);

    dim3 gg(128, BB);
    // PALayer avg path: y1 -> h -> z1 (img I4)
    cvt_k<<<NBCHW/1024,256>>>(buf0, ih+IK(3), il+IK(3));
    gemm_mma<<<gg,256,GSM>>>(wh+W1,wl+W1,0,256, ih+IK(3),0, 0, ih+IK(9),il+IK(9), pa_b1,1, 0,0);
    gemm_mma<<<gg,256,GSM>>>(wh+W2,wl+W2,0,256, ih+IK(9),0, 0, ih+IK(4),il+IK(4), pa_b2,2, buf0,0);
    // max path: y2 -> h -> z2 (img I5)
    cvt_k<<<NBCHW/1024,256>>>(buf1, ih+IK(3), il+IK(3));
    gemm_mma<<<gg,256,GSM>>>(wh+W1,wl+W1,0,256, ih+IK(3),0, 0, ih+IK(9),il+IK(9), pa_b1,1, 0,0);
    gemm_mma<<<gg,256,GSM>>>(wh+W2,wl+W2,0,256, ih+IK(9),0, 0, ih+IK(5),il+IK(5), pa_b2,2, buf1,0);
    // buffer_p (img I0)
    gemm_mma<<<gg,256,GSM>>>(wh+WC,wl+WC,0,512, ih+IK(4),ih+IK(5), 0, ih+IK(0),il+IK(0), pa_bc,3, x_p,0);
    // x_c img I1
    cvt_k<<<NBCHW/1024,256>>>(x_c, ih+IK(1), il+IK(1));
    // Q1->I4, S1->I5, Q2->I6, S2->I7, v3->I8
    gemm_mma<<<gg,256,GSM>>>(wh+B1,wl+B1,0,256,       ih+IK(0),0, 0, ih+IK(4),il+IK(4), b1_b,0, 0,0);
    gemm_mma<<<gg,256,GSM>>>(wh+B2G,wl+B2G,65536,256, ih+IK(1),0, 0, ih+IK(5),il+IK(5), b2_b,0, 0,0);
    gemm_mma<<<gg,256,GSM>>>(wh+B1G,wl+B1G,65536,256, ih+IK(1),0, 0, ih+IK(6),il+IK(6), b1_b,0, 0,0);
    gemm_mma<<<gg,256,GSM>>>(wh+B2,wl+B2,0,256,       ih+IK(0),0, 0, ih+IK(7),il+IK(7), b2_b,0, 0,0);
    gemm_mma<<<gg,256,GSM>>>(wh+B3,wl+B3,0,256,       ih+IK(1),0, 0, ih+IK(8),il+IK(8), b3_b,0, 0,0);
    cvt_k<<<NBCHW/1024,256>>>(x_p, ih+IK(2), il+IK(2));
    // attention (HMMA fp16 2-pass)
    dim3 gs(HH, BB);
    score_mma<1><<<gs,256,67584>>>(ih+IK(4),il+IK(4), ih+IK(5), Mh, 0);
    score_mma<0><<<gs,256,67584>>>(ih+IK(6),il+IK(6), ih+IK(7), 0, mA);
    // morphology
    int n128 = BB*HWs;
    morph_k<<<n128/256,256>>>(mA,mB,128,128,2,1,n128);
    morph_k<<<n128/256,256>>>(mB,mA,128,128,2,0,n128);
    morph_k<<<n128/256,256>>>(mA,mB,128,128,1,0,n128);
    morph_k<<<n128/256,256>>>(mB,mA,128,128,1,1,n128);
    int np=BB*PHW, gp=(np+255)/256;
    pad_k<<<gp,256>>>(mA,pA,np);
    morph_k<<<gp,256>>>(pA,pB,PW,PW,3,0,np);
    morph_k<<<gp,256>>>(pB,pA,PW,PW,3,1,np);
    final_k<<<n128/256,256>>>(pA,vfin);
    // attend -> img I3; fusion
    dim3 ga(2, BB*HH);
    attend_mma<<<ga,256,61440>>>(Mh, ih+IK(8), il+IK(8), ih+IK(3), il+IK(3));
    gemm_mma<<<gg,256,GSM>>>(wh+FU,wl+FU,0,512, ih+IK(3),ih+IK(2), out,0,0, fus_b,4, vfin,fus_w);
}

// round 10
// speedup vs baseline: 2.5347x; 1.1153x over previous
#include <cuda_runtime.h>
#include <cuda_fp16.h>
#include <math.h>

#define BB 8
#define CC 256
#define HH 128
#define WW 128
#define HWs 16384
#define NBCHW (BB*CC*HWs)
#define PW 134
#define PHW (PW*PW)
typedef unsigned long long ull;
typedef unsigned int u32;

__device__ float g_buf0[NBCHW];
__device__ float g_buf1[NBCHW];
__device__ float g_gate[BB*CC];
__device__ float g_amean[BB*CC];
__device__ float g_amax[BB*CC];
__device__ float g_mA[BB*HWs];
__device__ float g_mB[BB*HWs];
__device__ float g_pA[BB*PHW];
__device__ float g_pB[BB*PHW];
__device__ float g_vfinal[BB*HWs];
__device__ __align__(16) __half g_imgh[335544320];
__device__ __align__(16) __half g_imgl[335544320];
__device__ __align__(16) __half g_Mh[16777216];
__device__ __align__(16) __half g_wih[1638400];
__device__ __align__(16) __half g_wil[1638400];
#define IK(k) ((long)(k)*33554432L)

__device__ __forceinline__ float sigmoidf_(float x){ return 1.0f/(1.0f+expf(-x)); }
__device__ __forceinline__ u32 smem_u32(const void* p){
    u32 a; asm("{ .reg .u64 t; cvta.to.shared.u64 t, %1; cvt.u32.u64 %0, t; }" : "=r"(a) : "l"(p)); return a; }
__device__ __forceinline__ u32 pack2(float a, float b){
    __half2 t = __floats2half2_rn(a, b); return *(u32*)&t; }
__device__ __forceinline__ void w2(__half* oh, __half* ol, long idx, float a, float b){
    u32 h = pack2(a,b); __half2 hv = *(__half2*)&h;
    ((u32*)oh)[idx>>1] = h;
    if (ol) ((u32*)ol)[idx>>1] = pack2(a-__half2float(hv.x), b-__half2float(hv.y));
}
__device__ __forceinline__ void ldsm4(u32& r0,u32& r1,u32& r2,u32& r3,u32 a){
    asm volatile("ldmatrix.sync.aligned.m8n8.x4.shared.b16 {%0,%1,%2,%3}, [%4];"
        :"=r"(r0),"=r"(r1),"=r"(r2),"=r"(r3):"r"(a)); }
__device__ __forceinline__ void ldsm4t(u32& r0,u32& r1,u32& r2,u32& r3,u32 a){
    asm volatile("ldmatrix.sync.aligned.m8n8.x4.trans.shared.b16 {%0,%1,%2,%3}, [%4];"
        :"=r"(r0),"=r"(r1),"=r"(r2),"=r"(r3):"r"(a)); }
__device__ __forceinline__ void mmah(float* c, const u32* a, const u32* b){
    asm volatile("mma.sync.aligned.m16n8k16.row.col.f32.f16.f16.f32 "
        "{%0,%1,%2,%3},{%4,%5,%6,%7},{%8,%9},{%0,%1,%2,%3};"
        :"+f"(c[0]),"+f"(c[1]),"+f"(c[2]),"+f"(c[3])
        :"r"(a[0]),"r"(a[1]),"r"(a[2]),"r"(a[3]),"r"(b[0]),"r"(b[1])); }
__device__ __forceinline__ void cpa(u32 d, const void* s){
    asm volatile("cp.async.cg.shared.global [%0], [%1], 16;"::"r"(d),"l"(s)); }
__device__ __forceinline__ void cpcommit(){ asm volatile("cp.async.commit_group;":::"memory"); }
__device__ __forceinline__ void cpwait1(){ asm volatile("cp.async.wait_group 1;":::"memory"); }
__device__ __forceinline__ void cpwait0(){ asm volatile("cp.async.wait_group 0;":::"memory"); }

// ---- pool: fp32 + fp16-hi images in one pass ----
__global__ void pool_k(const float* __restrict__ xp, float* __restrict__ y1, float* __restrict__ y2,
                       __half* __restrict__ y1h, __half* __restrict__ y2h){
    long idx = (long)blockIdx.x*256 + threadIdx.x;
    if (idx >= (long)NBCHW) return;
    int w = (int)(idx & 127), h = (int)((idx>>7)&127);
    long base = idx - (long)(h*WW+w);
    float s=0.f, mx=-INFINITY;
    #pragma unroll
    for (int dy=-1;dy<=1;dy++){ int hh=h+dy; if(hh<0||hh>=HH) continue;
        #pragma unroll
        for (int dx=-1;dx<=1;dx++){ int ww=w+dx; if(ww<0||ww>=WW) continue;
            float v = xp[base+hh*WW+ww]; s+=v; mx=fmaxf(mx,v); } }
    float a = s*(1.f/9.f);
    y1[idx]=a; y2[idx]=mx;
    y1h[idx]=__float2half_rn(a); y2h[idx]=__float2half_rn(mx);
}
__global__ void reduce_k(const float* __restrict__ x, float* __restrict__ mean, float* __restrict__ mxo){
    __shared__ float ss[256], sm[256];
    int bc=blockIdx.x, t=threadIdx.x;
    const float* p = x + (long)bc*HWs;
    float s=0.f, m=-INFINITY;
    for (int i=t;i<HWs;i+=256){ float v=p[i]; s+=v; m=fmaxf(m,v); }
    ss[t]=s; sm[t]=m; __syncthreads();
    for (int o=128;o>0;o>>=1){ if (t<o){ ss[t]+=ss[t+o]; sm[t]=fmaxf(sm[t],sm[t+o]); } __syncthreads(); }
    if (t==0){ mean[bc]=ss[0]*(1.f/(float)HWs); mxo[bc]=sm[0]; }
}
__global__ void cagate_k(const float* __restrict__ amean, const float* __restrict__ amax,
    const float* __restrict__ aw1, const float* __restrict__ ab1,
    const float* __restrict__ aw2, const float* __restrict__ ab2,
    const float* __restrict__ mw1, const float* __restrict__ mb1,
    const float* __restrict__ mw2, const float* __restrict__ mb2, float* __restrict__ gate){
    __shared__ float ha[16], hm[16];
    int b=blockIdx.x, t=threadIdx.x;
    if (t<16){ float s=ab1[t]; for (int i=0;i<CC;i++) s+=aw1[t*CC+i]*amean[b*CC+i]; ha[t]=fmaxf(s,0.f); }
    else if (t<32){ int u=t-16; float s=mb1[u]; for (int i=0;i<CC;i++) s+=mw1[u*CC+i]*amax[b*CC+i]; hm[u]=fmaxf(s,0.f); }
    __syncthreads();
    float g = ab2[t]+mb2[t];
    #pragma unroll
    for (int k=0;k<16;k++) g += aw2[t*16+k]*ha[k] + mw2[t*16+k]*hm[k];
    gate[b*CC+t] = sigmoidf_(g);
}
__global__ void cvt_k(const float* __restrict__ src, __half* __restrict__ oh){
    long i4 = ((long)blockIdx.x*256 + threadIdx.x)*4;
    float4 v = *(const float4*)(src + i4);
    ((u32*)oh)[i4>>1]     = pack2(v.x, v.y);
    ((u32*)oh)[(i4>>1)+1] = pack2(v.z, v.w);
}
__global__ void cvtw_k(const float* __restrict__ W, int RS, int K, const float* __restrict__ gate,
                       __half* __restrict__ oh, __half* __restrict__ ol){
    int idx = blockIdx.x*256 + threadIdx.x;
    int b = idx/(256*K); int rem = idx - b*256*K; int m = rem/K, k = rem - m*K;
    float v = W[(long)m*RS + k];
    if (gate) v *= gate[b*256 + k];
    __half h = __float2half_rn(v);
    oh[idx] = h;
    if (ol) ol[idx] = __float2half_rn(v - __half2float(h));
}

// ---- HMMA GEMM: Y = (Wh[+Wl])·Bh, CTA = 256m x 128n; Wl==0 -> 1-pass ----
// stage: Ah 0 (20480), Al 20480, Bh 40960 (8704); stage=49664
#define STG 49664u
#define GSM (2*49664)
__global__ void __launch_bounds__(256,1) gemm_mma(
    const __half* __restrict__ Wh, const __half* __restrict__ Wl, long wBS, int K,
    const __half* __restrict__ X0h, const __half* __restrict__ X1h,
    float* __restrict__ Yf, __half* __restrict__ Yh, __half* __restrict__ Yl,
    const float* __restrict__ bias, int epi, const float* __restrict__ E0, const float* __restrict__ E1)
{
    extern __shared__ __align__(16) char smem[];
    u32 sm = smem_u32(smem);
    int tid=threadIdx.x, lane=tid&31, wid=tid>>5;
    int n0 = blockIdx.x*128, b = blockIdx.y;
    int wm = (wid&1)*128, wn = (wid>>1)*32;
    int lr = lane&15, lc8 = (lane>>4)*8;
    const __half* WhB = Wh + wBS*b;
    const __half* WlB = Wl ? (Wl + wBS*b) : 0;
    int NC = K>>5;
    float acc[32][4];
    #pragma unroll
    for (int i=0;i<32;i++){ acc[i][0]=0;acc[i][1]=0;acc[i][2]=0;acc[i][3]=0; }
    for (int c=0; c<=NC; c++){
        if (c<NC){
            u32 st = sm + (u32)(c&1)*STG;
            int kb = c*32;
            #pragma unroll
            for (int j=0;j<4;j++){
                int o=tid+256*j, r=o>>2, cb=o&3;
                u32 d = st + (u32)(r*80+cb*16);
                cpa(d, WhB + (size_t)r*K + kb + cb*8);
                if (WlB) cpa(d + 20480u, WlB + (size_t)r*K + kb + cb*8);
            }
            const __half *xh=X0h; int kk=kb;
            if (kk>=256){ xh=X1h; kk-=256; }
            #pragma unroll
            for (int j=0;j<2;j++){
                int o=tid+256*j, r=o>>4, cb=o&15;
                size_t s = ((size_t)b*256 + kk + r)*HWs + n0 + cb*8;
                cpa(st + 40960u + (u32)(r*272+cb*16), xh + s);
            }
            cpcommit();
        }
        if (c==0) continue;
        if (c<NC) cpwait1(); else cpwait0();
        __syncthreads();
        u32 sA = sm + (u32)((c-1)&1)*STG;
        #pragma unroll
        for (int ks=0; ks<32; ks+=16){
            u32 bh[4][2];
            #pragma unroll
            for (int pr=0; pr<2; pr++){
                u32 off = (u32)((ks+lr)*272 + (wn+pr*16+lc8)*2);
                ldsm4t(bh[pr*2][0],bh[pr*2][1],bh[pr*2+1][0],bh[pr*2+1][1], sA+40960u+off);
            }
            #pragma unroll
            for (int mt=0; mt<8; mt++){
                u32 ah[4], al[4];
                u32 off = (u32)((wm+mt*16+lr)*80 + (ks+lc8)*2);
                ldsm4(ah[0],ah[1],ah[2],ah[3], sA+off);
                if (WlB) ldsm4(al[0],al[1],al[2],al[3], sA+20480u+off);
                #pragma unroll
                for (int nt=0; nt<4; nt++){
                    float* cc = acc[mt*4+nt];
                    mmah(cc, ah, bh[nt]);
                    if (WlB) mmah(cc, al, bh[nt]);
                }
            }
        }
        __syncthreads();
    }
    #pragma unroll
    for (int mt=0; mt<8; mt++){
        #pragma unroll
        for (int nt=0; nt<4; nt++){
            float* cc = acc[mt*4+nt];
            int n = n0 + wn + nt*8 + (lane&3)*2;
            #pragma unroll
            for (int hlf=0; hlf<2; hlf++){
                int m = wm + mt*16 + (lane>>2) + hlf*8;
                float v0 = cc[hlf*2] + bias[m], v1 = cc[hlf*2+1] + bias[m];
                long yb = ((long)b*CC + m)*HWs + n;
                if (epi==1){ v0=fmaxf(v0,0.f); v1=fmaxf(v1,0.f); }
                else if (epi==2){ v0+=E0[yb]; v1+=E0[yb+1]; }
                else if (epi==3){ v0=sigmoidf_(v0)*E0[yb]; v1=sigmoidf_(v1)*E0[yb+1]; }
                else if (epi==4){ float wl=E1[(long)m*513+512]; long eb=(long)b*HWs+n;
                    v0+=wl*E0[eb]; v1+=wl*E0[eb+1]; }
                if (Yf){ float2 st={v0,v1}; *(float2*)(Yf+yb)=st; }
                else   w2(Yh, Yl, yb, v0, v1);
            }
        }
    }
}

// ---- HMMA score (A=Q split 2-pass, B=S hi); softmax over j ----
// stage=26112 (x2=52224); epilogue 128*132*4=67584 -> dyn=67584
template<int WRITE_M>
__global__ void __launch_bounds__(256,1) score_mma(
    const __half* __restrict__ Qh, const __half* __restrict__ Ql,
    const __half* __restrict__ Sh,
    __half* __restrict__ Mh, float* __restrict__ mOut)
{
    extern __shared__ __align__(16) char smem[];
    u32 sm = smem_u32(smem);
    float* smE = (float*)smem;
    int tid=threadIdx.x, lane=tid&31, wid=tid>>5;
    int h = blockIdx.x, b = blockIdx.y;
    int wm=(wid&1)*64, wn=(wid>>1)*32;
    int lr=lane&15, lc8=(lane>>4)*8;
    float acc[16][4];
    #pragma unroll
    for (int i=0;i<16;i++){ acc[i][0]=0;acc[i][1]=0;acc[i][2]=0;acc[i][3]=0; }
    for (int c=0;c<=8;c++){
        if (c<8){
            u32 st = sm + (u32)(c&1)*26112u;
            int kb = c*32;
            #pragma unroll
            for (int j=0;j<2;j++){
                int o = tid + 256*j, r = o>>4, cb = o&15;
                size_t s = ((size_t)(b*256 + kb + r))*HWs + h*128 + cb*8;
                u32 d = st + (u32)(r*272 + cb*16);
                cpa(d, Qh+s); cpa(d+8704u, Ql+s); cpa(d+17408u, Sh+s);
            }
            cpcommit();
        }
        if (c==0) continue;
        if (c<8) cpwait1(); else cpwait0();
        __syncthreads();
        u32 sA = sm + (u32)((c-1)&1)*26112u;
        #pragma unroll
        for (int ks=0;ks<32;ks+=16){
            u32 bh[4][2];
            #pragma unroll
            for (int pr=0;pr<2;pr++){
                u32 off = (u32)((ks+lr)*272 + (wn+pr*16+lc8)*2);
                ldsm4t(bh[pr*2][0],bh[pr*2][1],bh[pr*2+1][0],bh[pr*2+1][1], sA+17408u+off);
            }
            #pragma unroll
            for (int mt=0;mt<4;mt++){
                u32 r0,r1,r2,r3,q0,q1,q2,q3;
                u32 off = (u32)((ks+lr)*272 + (wm+mt*16+lc8)*2);
                ldsm4t(r0,r1,r2,r3, sA+off);
                ldsm4t(q0,q1,q2,q3, sA+8704u+off);
                u32 ah[4]={r0,r2,r1,r3}, al[4]={q0,q2,q1,q3};
                #pragma unroll
                for (int nt=0;nt<4;nt++){
                    float* cc = acc[mt*4+nt];
                    mmah(cc, ah, bh[nt]); mmah(cc, al, bh[nt]);
                }
            }
        }
        __syncthreads();
    }
    #pragma unroll
    for (int mt=0;mt<4;mt++)
        #pragma unroll
        for (int nt=0;nt<4;nt++){
            float* cc = acc[mt*4+nt];
            int n = wn + nt*8 + (lane&3)*2;
            #pragma unroll
            for (int hlf=0;hlf<2;hlf++){
                int m = wm + mt*16 + (lane>>2) + hlf*8;
                smE[m*132+n] = cc[hlf*2]; smE[m*132+n+1] = cc[hlf*2+1];
            }
        }
    __syncthreads();
    int row = tid>>1, c0 = (tid&1)*64;
    float* rp = smE + row*132 + c0;
    float mx = -INFINITY;
    for (int j=0;j<64;j++) mx = fmaxf(mx, rp[j]);
    mx = fmaxf(mx, __shfl_xor_sync(0xffffffffu, mx, 1));
    float sum = 0.f;
    for (int j=0;j<64;j++){ float e = expf(rp[j]-mx); rp[j] = e; sum += e; }
    sum += __shfl_xor_sync(0xffffffffu, sum, 1);
    float inv = 1.f/sum;
    if (WRITE_M){
        long base = ((long)(b*128+h)*128 + row)*128 + c0;
        for (int j=0;j<64;j+=2)
            ((u32*)Mh)[(base+j)>>1] = pack2(rp[j]*inv, rp[j+1]*inv);
    } else {
        for (int j=0;j<64;j++) rp[j] *= inv;
        __syncthreads();
        if (tid < 128){
            float t = 0.f;
            for (int i=0;i<128;i++) t += smE[i*132+tid];
            mOut[(long)b*HWs + h*128 + tid] = (t>0.1f)?0.f:1.f;
        }
    }
}

// ---- HMMA attend (A=v3 split 2-pass, B=M hi); hi-only output ----
// stage: Vh 0, Vl 10240, Mh 20480; stage=30720, dyn=61440
__global__ void __launch_bounds__(256,1) attend_mma(
    const __half* __restrict__ Mh,
    const __half* __restrict__ Vh, const __half* __restrict__ Vl,
    __half* __restrict__ Oh)
{
    extern __shared__ __align__(16) char smem[];
    u32 sm = smem_u32(smem);
    int tid=threadIdx.x, lane=tid&31, wid=tid>>5;
    int c0 = blockIdx.x*128, bh = blockIdx.y, b = bh>>7, h = bh&127;
    int wm=(wid&1)*64, wn=(wid>>1)*32;
    int lr=lane&15, lc8=(lane>>4)*8;
    int tile=lane>>3, lrow=lane&7;
    float acc[16][4];
    #pragma unroll
    for (int i=0;i<16;i++){ acc[i][0]=0;acc[i][1]=0;acc[i][2]=0;acc[i][3]=0; }
    for (int c=0;c<=4;c++){
        if (c<4){
            u32 st = sm + (u32)(c&1)*30720u;
            int kb = c*32;
            #pragma unroll
            for (int j=0;j<2;j++){
                int o = tid + 256*j, r = o>>2, cb = o&3;
                u32 d = st + (u32)(r*80 + cb*16);
                size_t s = ((size_t)(b*256 + c0 + r))*HWs + h*128 + kb + cb*8;
                cpa(d, Vh+s); cpa(d+10240u, Vl+s);
                size_t s2 = (((size_t)(b*128+h)*128 + r))*128 + kb + cb*8;
                cpa(d+20480u, Mh+s2);
            }
            cpcommit();
        }
        if (c==0) continue;
        if (c<4) cpwait1(); else cpwait0();
        __syncthreads();
        u32 sA = sm + (u32)((c-1)&1)*30720u;
        #pragma unroll
        for (int ks=0;ks<32;ks+=16){
            u32 bh_[4][2];
            #pragma unroll
            for (int pr=0;pr<2;pr++){
                u32 off = (u32)(((wn+pr*16+(tile>>1)*8+lrow)*40 + ks + (tile&1)*8)*2);
                u32 r0,r1,r2,r3;
                ldsm4(r0,r1,r2,r3, sA+20480u+off);
                bh_[pr*2][0]=r0; bh_[pr*2][1]=r1; bh_[pr*2+1][0]=r2; bh_[pr*2+1][1]=r3;
            }
            #pragma unroll
            for (int mt=0;mt<4;mt++){
                u32 ah[4], al[4];
                u32 off = (u32)((wm+mt*16+lr)*80 + (ks+lc8)*2);
                ldsm4(ah[0],ah[1],ah[2],ah[3], sA+off);
                ldsm4(al[0],al[1],al[2],al[3], sA+10240u+off);
                #pragma unroll
                for (int nt=0;nt<4;nt++){
                    float* cc = acc[mt*4+nt];
                    mmah(cc, ah, bh_[nt]); mmah(cc, al, bh_[nt]);
                }
            }
        }
        __syncthreads();
    }
    #pragma unroll
    for (int mt=0;mt<4;mt++)
        #pragma unroll
        for (int nt=0;nt<4;nt++){
            float* cc = acc[mt*4+nt];
            int n = wn + nt*8 + (lane&3)*2;
            #pragma unroll
            for (int hlf=0;hlf<2;hlf++){
                int m = wm + mt*16 + (lane>>2) + hlf*8;
                long idx = ((long)(b*256 + c0 + m))*HWs + h*128 + n;
                ((u32*)Oh)[idx>>1] = pack2(cc[hlf*2], cc[hlf*2+1]);
            }
        }
}

// ---- morphology ----
__global__ void morph_k(const float* __restrict__ src, float* __restrict__ dst,
                        int Wd, int Hd, int r, int erode, int total){
    int idx = blockIdx.x*256 + threadIdx.x;
    if (idx >= total) return;
    int plane=Wd*Hd, b=idx/plane, rem=idx-b*plane, h=rem/Wd, w=rem-h*Wd;
    const float* p = src + (long)b*plane;
    float res = erode ? 1.f : 0.f;
    int r2=r*r;
    for (int dy=-r;dy<=r;dy++) for (int dx=-r;dx<=r;dx++){
        if (dy*dy+dx*dx > r2) continue;
        int hh=h+dy, ww=w+dx;
        float v = (hh>=0&&hh<Hd&&ww>=0&&ww<Wd) ? p[hh*Wd+ww] : 0.f;
        if (erode){ if (v<0.5f) res=0.f; } else { if (v>0.5f) res=1.f; }
    }
    dst[(long)b*plane+rem]=res;
}
__global__ void pad_k(const float* __restrict__ src, float* __restrict__ dst, int total){
    int idx = blockIdx.x*256 + threadIdx.x;
    if (idx >= total) return;
    int b=idx/PHW, rem=idx-b*PHW, h=rem/PW, w=rem-h*PW;
    float v=0.f;
    if (h>=3 && h<3+HH && w>=3 && w<3+WW) v = src[(long)b*HWs + (h-3)*WW + (w-3)];
    dst[idx]=v;
}
__global__ void final_k(const float* __restrict__ src, float* __restrict__ dst){
    int idx = blockIdx.x*256 + threadIdx.x;
    int b=idx>>14, rem=idx&(HWs-1), h=rem>>7, w=rem&127;
    dst[idx] = 1.f - src[(long)b*PHW + (h+3)*PW + (w+3)];
}

extern "C" void kernel_launch(void* const* d_in, const int* in_sizes, int n_in,
                              void* d_out, int out_size) {
    const float* x_p=(const float*)d_in[0];  const float* x_c=(const float*)d_in[1];
    const float* pa_w1=(const float*)d_in[2];const float* pa_b1=(const float*)d_in[3];
    const float* pa_w2=(const float*)d_in[4];const float* pa_b2=(const float*)d_in[5];
    const float* pa_wc=(const float*)d_in[6];const float* pa_bc=(const float*)d_in[7];
    const float* ca_aw1=(const float*)d_in[8];const float* ca_ab1=(const float*)d_in[9];
    const float* ca_aw2=(const float*)d_in[10];const float* ca_ab2=(const float*)d_in[11];
    const float* ca_mw1=(const float*)d_in[12];const float* ca_mb1=(const float*)d_in[13];
    const float* ca_mw2=(const float*)d_in[14];const float* ca_mb2=(const float*)d_in[15];
    const float* b1_w=(const float*)d_in[16];const float* b1_b=(const float*)d_in[17];
    const float* b2_w=(const float*)d_in[18];const float* b2_b=(const float*)d_in[19];
    const float* b3_w=(const float*)d_in[20];const float* b3_b=(const float*)d_in[21];
    const float* fus_w=(const float*)d_in[22];const float* fus_b=(const float*)d_in[23];
    float* out=(float*)d_out;

    float *buf0,*buf1,*gate,*amean,*amax,*mA,*mB,*pA,*pB,*vfin;
    __half *ih,*il,*wh,*wl,*Mh;
    cudaGetSymbolAddress((void**)&buf0,g_buf0); cudaGetSymbolAddress((void**)&buf1,g_buf1);
    cudaGetSymbolAddress((void**)&gate,g_gate);
    cudaGetSymbolAddress((void**)&amean,g_amean); cudaGetSymbolAddress((void**)&amax,g_amax);
    cudaGetSymbolAddress((void**)&mA,g_mA); cudaGetSymbolAddress((void**)&mB,g_mB);
    cudaGetSymbolAddress((void**)&pA,g_pA); cudaGetSymbolAddress((void**)&pB,g_pB);
    cudaGetSymbolAddress((void**)&vfin,g_vfinal);
    cudaGetSymbolAddress((void**)&ih,g_imgh); cudaGetSymbolAddress((void**)&il,g_imgl);
    cudaGetSymbolAddress((void**)&wh,g_wih);  cudaGetSymbolAddress((void**)&wl,g_wil);
    cudaGetSymbolAddress((void**)&Mh,g_Mh);
    cudaFuncSetAttribute(gemm_mma, cudaFuncAttributeMaxDynamicSharedMemorySize, GSM);
    cudaFuncSetAttribute(score_mma<1>, cudaFuncAttributeMaxDynamicSharedMemorySize, 67584);
    cudaFuncSetAttribute(score_mma<0>, cudaFuncAttributeMaxDynamicSharedMemorySize, 67584);
    cudaFuncSetAttribute(attend_mma, cudaFuncAttributeMaxDynamicSharedMemorySize, 61440);

    const long W1=0,W2=65536,WC=131072,B1=262144,B2=327680,B3=393216,FU=458752,B1G=589824,B2G=1114112;

    // pool emits fp32 + fp16-hi images (I3 = y1h, I9 = y2h)
    pool_k<<<NBCHW/256,256>>>(x_p, buf0, buf1, ih+IK(3), ih+IK(9));
    reduce_k<<<BB*CC,256>>>(x_c, amean, amax);
    cagate_k<<<BB,256>>>(amean,amax,ca_aw1,ca_ab1,ca_aw2,ca_ab2,ca_mw1,ca_mb1,ca_mw2,ca_mb2,gate);

    // 2-pass weights (hi+lo); 1-pass weights (hi only)
    cvtw_k<<<256,256>>>(pa_w1,256,256,0, wh+W1, wl+W1);
    cvtw_k<<<256,256>>>(pa_w2,256,256,0, wh+W2, wl+W2);
    cvtw_k<<<512,256>>>(pa_wc,512,512,0, wh+WC, wl+WC);
    cvtw_k<<<256,256>>>(b1_w,256,256,0, wh+B1, 0);
    cvtw_k<<<256,256>>>(b2_w,256,256,0, wh+B2, 0);
    cvtw_k<<<256,256>>>(b3_w,256,256,0, wh+B3, 0);
    cvtw_k<<<512,256>>>(fus_w,513,512,0, wh+FU, 0);
    cvtw_k<<<2048,256>>>(b1_w,256,256,gate, wh+B1G, 0);
    cvtw_k<<<2048,256>>>(b2_w,256,256,gate, wh+B2G, 0);

    dim3 gg(128, BB);
    // PALayer avg: h1 -> I5 (hi), z1 -> I4 (hi)
    gemm_mma<<<gg,256,GSM>>>(wh+W1,wl+W1,0,256, ih+IK(3),0, 0, ih+IK(5),0, pa_b1,1, 0,0);
    gemm_mma<<<gg,256,GSM>>>(wh+W2,wl+W2,0,256, ih+IK(5),0, 0, ih+IK(4),0, pa_b2,2, buf0,0);
    // max: h2 -> I5, z2 -> I6
    gemm_mma<<<gg,256,GSM>>>(wh+W1,wl+W1,0,256, ih+IK(9),0, 0, ih+IK(5),0, pa_b1,1, 0,0);
    gemm_mma<<<gg,256,GSM>>>(wh+W2,wl+W2,0,256, ih+IK(5),0, 0, ih+IK(6),0, pa_b2,2, buf1,0);
    // buffer_p -> I0 (hi)
    gemm_mma<<<gg,256,GSM>>>(wh+WC,wl+WC,0,512, ih+IK(4),ih+IK(6), 0, ih+IK(0),0, pa_bc,3, x_p,0);
    // x_c -> I1 hi, x_p -> I2 hi
    cvt_k<<<NBCHW/1024,256>>>(x_c, ih+IK(1));
    cvt_k<<<NBCHW/1024,256>>>(x_p, ih+IK(2));
    // Q1 -> I3 hi+lo; S1 -> I5 hi; Q2 -> I9 hi+lo; S2 -> I7 hi; v3 -> I8 hi+lo (1-pass weights)
    gemm_mma<<<gg,256,GSM>>>(wh+B1,0,0,256,       ih+IK(0),0, 0, ih+IK(3),il+IK(3), b1_b,0, 0,0);
    gemm_mma<<<gg,256,GSM>>>(wh+B2G,0,65536,256,  ih+IK(1),0, 0, ih+IK(5),0,        b2_b,0, 0,0);
    gemm_mma<<<gg,256,GSM>>>(wh+B1G,0,65536,256,  ih+IK(1),0, 0, ih+IK(9),il+IK(9), b1_b,0, 0,0);
    gemm_mma<<<gg,256,GSM>>>(wh+B2,0,0,256,       ih+IK(0),0, 0, ih+IK(7),0,        b2_b,0, 0,0);
    gemm_mma<<<gg,256,GSM>>>(wh+B3,0,0,256,       ih+IK(1),0, 0, ih+IK(8),il+IK(8), b3_b,0, 0,0);
    // attention
    dim3 gs(HH, BB);
    score_mma<1><<<gs,256,67584>>>(ih+IK(3),il+IK(3), ih+IK(5), Mh, 0);
    score_mma<0><<<gs,256,67584>>>(ih+IK(9),il+IK(9), ih+IK(7), 0, mA);
    // morphology
    int n128 = BB*HWs;
    morph_k<<<n128/256,256>>>(mA,mB,128,128,2,1,n128);
    morph_k<<<n128/256,256>>>(mB,mA,128,128,2,0,n128);
    morph_k<<<n128/256,256>>>(mA,mB,128,128,1,0,n128);
    morph_k<<<n128/256,256>>>(mB,mA,128,128,1,1,n128);
    int np=BB*PHW, gp=(np+255)/256;
    pad_k<<<gp,256>>>(mA,pA,np);
    morph_k<<<gp,256>>>(pA,pB,PW,PW,3,0,np);
    morph_k<<<gp,256>>>(pB,pA,PW,PW,3,1,np);
    final_k<<<n128/256,256>>>(pA,vfin);
    // attend -> I5 hi; fusion (1-pass weights)
    dim3 ga(2, BB*HH);
    attend_mma<<<ga,256,61440>>>(Mh, ih+IK(8), il+IK(8), ih+IK(5));
    gemm_mma<<<gg,256,GSM>>>(wh+FU,0,0,512, ih+IK(5),ih+IK(2), out,0,0, fus_b,4, vfin,fus_w);
}